// round 2
// baseline (speedup 1.0000x reference)
#include <cuda_runtime.h>
#include <cstdint>

// ---------------- problem constants ----------------
#define BB   16
#define NN   1025
#define CC   384
#define HH   6
#define HD   64
#define HID  1536
#define TOK  1024
#define MTOT (BB*NN)      // 16400
#define MTOK (BB*TOK)     // 16384

// ---------------- scratch (device globals, no alloc) ----------------
__device__ float g_h   [MTOT*CC];
__device__ float g_qkv [MTOT*3*CC];
__device__ float g_o   [MTOT*CC];
__device__ float g_x1  [MTOT*CC];
__device__ float g_h2  [MTOT*CC];
__device__ float g_y   [MTOK*HID];
__device__ float g_y2  [MTOK*HID];
__device__ float g_y3  [MTOK*CC];
__device__ float g_part[BB*16*CC];
__device__ float g_w   [BB*CC];

__device__ __forceinline__ float gelu_f(float x){
    return 0.5f * x * (1.0f + erff(x * 0.70710678118654752f));
}

// ---------------- LayerNorm over last dim (C=384) ----------------
__global__ void ln_kernel(const float* __restrict__ x, const float* __restrict__ g,
                          const float* __restrict__ bta, float* __restrict__ out)
{
    __shared__ float red[4];
    __shared__ float bc[2];
    int row = blockIdx.x;
    const float* xr = x + (size_t)row * CC;
    int t = threadIdx.x;                      // 128 threads
    float v0 = xr[t], v1 = xr[t+128], v2 = xr[t+256];
    float s = v0 + v1 + v2;
    #pragma unroll
    for (int o=16;o;o>>=1) s += __shfl_xor_sync(0xffffffffu, s, o);
    if ((t&31)==0) red[t>>5] = s;
    __syncthreads();
    if (t==0) bc[0] = (red[0]+red[1]+red[2]+red[3]) * (1.0f/CC);
    __syncthreads();
    float mu = bc[0];
    float d0=v0-mu, d1=v1-mu, d2=v2-mu;
    float q = d0*d0 + d1*d1 + d2*d2;
    #pragma unroll
    for (int o=16;o;o>>=1) q += __shfl_xor_sync(0xffffffffu, q, o);
    if ((t&31)==0) red[t>>5] = q;
    __syncthreads();
    if (t==0) bc[1] = rsqrtf((red[0]+red[1]+red[2]+red[3]) * (1.0f/CC) + 1e-5f);
    __syncthreads();
    float rs = bc[1];
    float* orow = out + (size_t)row * CC;
    orow[t]     = d0*rs*g[t]     + bta[t];
    orow[t+128] = d1*rs*g[t+128] + bta[t+128];
    orow[t+256] = d2*rs*g[t+256] + bta[t+256];
}

// ---------------- tiled SGEMM: C[M,N] = A[M,K] @ W[N,K]^T + epilogue ----------------
// EPI: 0 none | 1 residual+bias | 2 (v+bias)*scale+shift then GELU | 3 (v+bias)*scale+shift
template<int EPI, bool SKIP>
__global__ void __launch_bounds__(256) gemm_kernel(
    const float* __restrict__ A, const float* __restrict__ W, float* __restrict__ C,
    int M, int N, int K,
    const float* __restrict__ bias, const float* __restrict__ scale,
    const float* __restrict__ shift, const float* __restrict__ residual)
{
    __shared__ float As[16*68];
    __shared__ float Ws[16*68];
    const int tid = threadIdx.x;
    const int tx4 = (tid & 15) * 4;
    const int ty4 = (tid >> 4) * 4;
    const int n0 = blockIdx.x * 64, m0 = blockIdx.y * 64;
    const int lc = tid & 15, lr = tid >> 4;
    float acc[4][4] = {};
    for (int k0 = 0; k0 < K; k0 += 16){
        #pragma unroll
        for (int i=0;i<4;i++){
            int m = m0 + lr + i*16;
            float v = 0.f;
            if (m < M){
                int gr = SKIP ? ((m >> 10)*1025 + (m & 1023) + 1) : m;
                v = A[(size_t)gr*K + k0 + lc];
            }
            As[lc*68 + lr + i*16] = v;
        }
        #pragma unroll
        for (int i=0;i<4;i++){
            int n = n0 + lr + i*16;
            Ws[lc*68 + lr + i*16] = W[(size_t)n*K + k0 + lc];
        }
        __syncthreads();
        #pragma unroll
        for (int kk=0;kk<16;kk++){
            float4 a = *(const float4*)(As + kk*68 + ty4);
            float4 w = *(const float4*)(Ws + kk*68 + tx4);
            acc[0][0]+=a.x*w.x; acc[0][1]+=a.x*w.y; acc[0][2]+=a.x*w.z; acc[0][3]+=a.x*w.w;
            acc[1][0]+=a.y*w.x; acc[1][1]+=a.y*w.y; acc[1][2]+=a.y*w.z; acc[1][3]+=a.y*w.w;
            acc[2][0]+=a.z*w.x; acc[2][1]+=a.z*w.y; acc[2][2]+=a.z*w.z; acc[2][3]+=a.z*w.w;
            acc[3][0]+=a.w*w.x; acc[3][1]+=a.w*w.y; acc[3][2]+=a.w*w.z; acc[3][3]+=a.w*w.w;
        }
        __syncthreads();
    }
    #pragma unroll
    for (int i=0;i<4;i++){
        int m = m0 + ty4 + i;
        if (m >= M) continue;
        #pragma unroll
        for (int j=0;j<4;j++){
            int n = n0 + tx4 + j;
            size_t idx = (size_t)m*N + n;
            float v = acc[i][j];
            if (EPI == 0)      C[idx] = v;
            else if (EPI == 1) C[idx] = residual[idx] + v + bias[n];
            else if (EPI == 2) { v = (v + bias[n])*scale[n] + shift[n]; C[idx] = gelu_f(v); }
            else               C[idx] = (v + bias[n])*scale[n] + shift[n];
        }
    }
}

// ---------------- fused flash attention ----------------
// grid = B*H*17 blocks, 256 threads. 64-query tile, loops 17 key tiles of 64.
// smem: QsT[64][68] (d-major), KVs[ ] (K as [d][k], then V as [k][d]), PsT[64k][68q], stats.
#define APAD 68
#define ATTN_SMEM_FLOATS (3*64*APAD + 192)

__global__ void __launch_bounds__(256) attn_kernel(const float* __restrict__ qkv,
                                                   float* __restrict__ o)
{
    extern __shared__ float sm[];
    float* QsT = sm;                    // [d][q]  64*68
    float* KVs = sm + 64*APAD;          // K: [d][k], later V: [k][d]
    float* PsT = sm + 2*64*APAD;        // [k][q]
    float* m_s = sm + 3*64*APAD;        // 64
    float* l_s = m_s + 64;              // 64
    float* al_s = l_s + 64;             // 64

    const int tid = threadIdx.x;
    const int tile = blockIdx.x % 17;
    const int bh   = blockIdx.x / 17;
    const int h = bh % HH, b = bh / HH;
    const int q0 = tile * 64;

    const float* qp = qkv + (size_t)b*NN*(3*CC) + h*HD;
    const float* kp = qp + CC;
    const float* vp = qp + 2*CC;

    const int d  = tid & 63;
    const int r0 = tid >> 6;            // 0..3
    const int tx4 = (tid & 15) * 4;
    const int ty4 = (tid >> 4) * 4;

    #pragma unroll
    for (int i=0;i<16;i++){
        int r = r0*16 + i;
        int q = q0 + r;
        QsT[d*APAD + r] = (q < NN) ? qp[(size_t)q*(3*CC) + d] * 0.125f : 0.f;
    }
    if (tid < 64){ m_s[tid] = -1e30f; l_s[tid] = 0.f; }
    float acc[4][4] = {};
    __syncthreads();

    for (int kt = 0; kt < 17; kt++){
        int nv = min(64, NN - kt*64);
        // load K tile: KVs[d][k]
        #pragma unroll
        for (int i=0;i<16;i++){
            int r = r0*16 + i;
            int kk = kt*64 + r;
            KVs[d*APAD + r] = (kk < NN) ? kp[(size_t)kk*(3*CC) + d] : 0.f;
        }
        __syncthreads();
        // scores S[q][k] -> PsT[k][q]
        float s[4][4] = {};
        #pragma unroll
        for (int dd=0; dd<64; dd++){
            float4 a  = *(const float4*)(QsT + dd*APAD + ty4);
            float4 bb = *(const float4*)(KVs + dd*APAD + tx4);
            s[0][0]+=a.x*bb.x; s[0][1]+=a.x*bb.y; s[0][2]+=a.x*bb.z; s[0][3]+=a.x*bb.w;
            s[1][0]+=a.y*bb.x; s[1][1]+=a.y*bb.y; s[1][2]+=a.y*bb.z; s[1][3]+=a.y*bb.w;
            s[2][0]+=a.z*bb.x; s[2][1]+=a.z*bb.y; s[2][2]+=a.z*bb.z; s[2][3]+=a.z*bb.w;
            s[3][0]+=a.w*bb.x; s[3][1]+=a.w*bb.y; s[3][2]+=a.w*bb.z; s[3][3]+=a.w*bb.w;
        }
        #pragma unroll
        for (int j=0;j<4;j++)
            #pragma unroll
            for (int i=0;i<4;i++)
                PsT[(tx4+j)*APAD + ty4 + i] = s[i][j];
        __syncthreads();
        // load V tile (reuse KVs as [k][d]) while threads<64 run softmax
        #pragma unroll
        for (int i=0;i<16;i++){
            int r = r0*16 + i;
            int kk = kt*64 + r;
            KVs[r*APAD + d] = (kk < NN) ? vp[(size_t)kk*(3*CC) + d] : 0.f;
        }
        if (tid < 64){
            float mold = m_s[tid], mx = mold;
            for (int k=0;k<nv;k++) mx = fmaxf(mx, PsT[k*APAD + tid]);
            float alpha = __expf(mold - mx);
            float ls = 0.f;
            for (int k=0;k<nv;k++){
                float p = __expf(PsT[k*APAD + tid] - mx);
                PsT[k*APAD + tid] = p;
                ls += p;
            }
            for (int k=nv;k<64;k++) PsT[k*APAD + tid] = 0.f;
            l_s[tid]  = l_s[tid]*alpha + ls;
            m_s[tid]  = mx;
            al_s[tid] = alpha;
        }
        __syncthreads();
        // rescale accumulators and do O += P @ V
        float al[4];
        #pragma unroll
        for (int i=0;i<4;i++) al[i] = al_s[ty4 + i];
        #pragma unroll
        for (int i=0;i<4;i++)
            #pragma unroll
            for (int j=0;j<4;j++)
                acc[i][j] *= al[i];
        #pragma unroll
        for (int k=0;k<64;k++){
            float4 a  = *(const float4*)(PsT + k*APAD + ty4);
            float4 bb = *(const float4*)(KVs + k*APAD + tx4);
            acc[0][0]+=a.x*bb.x; acc[0][1]+=a.x*bb.y; acc[0][2]+=a.x*bb.z; acc[0][3]+=a.x*bb.w;
            acc[1][0]+=a.y*bb.x; acc[1][1]+=a.y*bb.y; acc[1][2]+=a.y*bb.z; acc[1][3]+=a.y*bb.w;
            acc[2][0]+=a.z*bb.x; acc[2][1]+=a.z*bb.y; acc[2][2]+=a.z*bb.z; acc[2][3]+=a.z*bb.w;
            acc[3][0]+=a.w*bb.x; acc[3][1]+=a.w*bb.y; acc[3][2]+=a.w*bb.z; acc[3][3]+=a.w*bb.w;
        }
        __syncthreads();
    }
    #pragma unroll
    for (int i=0;i<4;i++){
        int q = q0 + ty4 + i;
        if (q >= NN) continue;
        float linv = 1.0f / l_s[ty4 + i];
        float4 r;
        r.x = acc[i][0]*linv; r.y = acc[i][1]*linv;
        r.z = acc[i][2]*linv; r.w = acc[i][3]*linv;
        *(float4*)(o + ((size_t)(b*NN + q))*CC + h*HD + tx4) = r;
    }
}

// ---------------- depthwise 3x3 + BN + residual GELU ----------------
__global__ void dwconv_kernel(const float* __restrict__ y, const float* __restrict__ w2,
                              const float* __restrict__ b2, const float* __restrict__ s2,
                              const float* __restrict__ h2b, float* __restrict__ out)
{
    int pix = blockIdx.x;                 // 0..16383
    int b = pix >> 10, p = pix & 1023;
    int sy = p >> 5, sx = p & 31;
    const float* yb = y + (size_t)(b << 10) * HID;
    for (int c = threadIdx.x; c < HID; c += blockDim.x){
        float acc = 0.f;
        #pragma unroll
        for (int dy=0; dy<3; dy++){
            int iy = sy + dy - 1;
            if ((unsigned)iy >= 32u) continue;
            #pragma unroll
            for (int dx=0; dx<3; dx++){
                int ix = sx + dx - 1;
                if ((unsigned)ix >= 32u) continue;
                acc += yb[(size_t)((iy<<5)+ix)*HID + c] * w2[c*9 + dy*3 + dx];
            }
        }
        float v = (acc + b2[c]) * s2[c] + h2b[c];
        out[(size_t)pix*HID + c] = y[(size_t)pix*HID + c] + gelu_f(v);
    }
}

// ---------------- spatial mean partials ----------------
__global__ void mean_part_kernel(const float* __restrict__ y3, float* __restrict__ part)
{
    int b = blockIdx.x, ch = blockIdx.y, c = threadIdx.x;   // 384 threads
    float s = 0.f;
    int base = (b << 10) + ch*64;
    for (int t=0;t<64;t++) s += y3[(size_t)(base + t)*CC + c];
    part[(b*16 + ch)*CC + c] = s;
}

// ---------------- SE gate ----------------
__global__ void se_kernel(const float* __restrict__ part, const float* __restrict__ cw,
                          const float* __restrict__ cb, const float* __restrict__ ew,
                          const float* __restrict__ eb, float* __restrict__ wout)
{
    __shared__ float m[CC];
    __shared__ float cv[96];
    int b = blockIdx.x, t = threadIdx.x;    // 384 threads
    float s = 0.f;
    for (int i=0;i<16;i++) s += part[(b*16 + i)*CC + t];
    m[t] = s * (1.0f/1024.0f);
    __syncthreads();
    if (t < 96){
        float a = cb[t];
        for (int k=0;k<CC;k++) a += m[k]*cw[t*CC + k];
        cv[t] = gelu_f(a);
    }
    __syncthreads();
    float a = eb[t];
    for (int k=0;k<96;k++) a += cv[k]*ew[t*96 + k];
    wout[b*CC + t] = a;
}

// ---------------- final assemble: out = x1 + concat(cls*w, y3) ----------------
__global__ void final_kernel(const float* __restrict__ x1, const float* __restrict__ h2,
                             const float* __restrict__ y3, const float* __restrict__ w,
                             float* __restrict__ out)
{
    size_t i = (size_t)blockIdx.x*256 + threadIdx.x;
    if (i >= (size_t)MTOT*CC) return;
    int c = (int)(i % CC);
    int row = (int)(i / CC);
    int b = row / NN, n = row % NN;
    float add;
    if (n == 0) add = h2[i] * w[b*CC + c];
    else        add = y3[(size_t)((b<<10) + (n-1))*CC + c];
    out[i] = x1[i] + add;
}

// ---------------- launcher ----------------
extern "C" void kernel_launch(void* const* d_in, const int* in_sizes, int n_in,
                              void* d_out, int out_size)
{
    const float* x       = (const float*)d_in[0];
    const float* ln1_g   = (const float*)d_in[1];
    const float* ln1_b   = (const float*)d_in[2];
    const float* qkv_w   = (const float*)d_in[3];
    const float* proj_w  = (const float*)d_in[4];
    const float* proj_b  = (const float*)d_in[5];
    const float* ln2_g   = (const float*)d_in[6];
    const float* ln2_b   = (const float*)d_in[7];
    const float* conv1_w = (const float*)d_in[8];
    const float* conv1_b = (const float*)d_in[9];
    const float* conv2_w = (const float*)d_in[10];
    const float* conv2_b = (const float*)d_in[11];
    const float* conv3_w = (const float*)d_in[12];
    const float* conv3_b = (const float*)d_in[13];
    const float* bn1_s   = (const float*)d_in[14];
    const float* bn1_b   = (const float*)d_in[15];
    const float* bn2_s   = (const float*)d_in[16];
    const float* bn2_b   = (const float*)d_in[17];
    const float* bn3_s   = (const float*)d_in[18];
    const float* bn3_b   = (const float*)d_in[19];
    const float* comp_w  = (const float*)d_in[20];
    const float* comp_b  = (const float*)d_in[21];
    const float* exc_w   = (const float*)d_in[22];
    const float* exc_b   = (const float*)d_in[23];
    float* out = (float*)d_out;

    static bool init = false;
    static float *p_h, *p_qkv, *p_o, *p_x1, *p_h2, *p_y, *p_y2, *p_y3, *p_part, *p_w;
    if (!init){
        cudaGetSymbolAddress((void**)&p_h,    g_h);
        cudaGetSymbolAddress((void**)&p_qkv,  g_qkv);
        cudaGetSymbolAddress((void**)&p_o,    g_o);
        cudaGetSymbolAddress((void**)&p_x1,   g_x1);
        cudaGetSymbolAddress((void**)&p_h2,   g_h2);
        cudaGetSymbolAddress((void**)&p_y,    g_y);
        cudaGetSymbolAddress((void**)&p_y2,   g_y2);
        cudaGetSymbolAddress((void**)&p_y3,   g_y3);
        cudaGetSymbolAddress((void**)&p_part, g_part);
        cudaGetSymbolAddress((void**)&p_w,    g_w);
        cudaFuncSetAttribute(attn_kernel, cudaFuncAttributeMaxDynamicSharedMemorySize,
                             ATTN_SMEM_FLOATS*4);
        init = true;
    }

    // 1. LN1
    ln_kernel<<<MTOT, 128>>>(x, ln1_g, ln1_b, p_h);
    // 2. QKV = h @ qkv_w^T
    gemm_kernel<0,false><<<dim3(18,257), 256>>>(p_h, qkv_w, p_qkv, MTOT, 3*CC, CC,
                                                nullptr, nullptr, nullptr, nullptr);
    // 3. attention -> o
    attn_kernel<<<BB*HH*17, 256, ATTN_SMEM_FLOATS*4>>>(p_qkv, p_o);
    // 4. x1 = x + o @ proj_w^T + proj_b
    gemm_kernel<1,false><<<dim3(6,257), 256>>>(p_o, proj_w, p_x1, MTOT, CC, CC,
                                               proj_b, nullptr, nullptr, x);
    // 5. LN2
    ln_kernel<<<MTOT, 128>>>(p_x1, ln2_g, ln2_b, p_h2);
    // 6. conv1 (1x1) + BN1 + GELU on tokens only (skip cls row)
    gemm_kernel<2,true><<<dim3(24,256), 256>>>(p_h2, conv1_w, p_y, MTOK, HID, CC,
                                               conv1_b, bn1_s, bn1_b, nullptr);
    // 7. depthwise 3x3 + BN2, y2 = y + gelu(.)
    dwconv_kernel<<<MTOK, 256>>>(p_y, conv2_w, conv2_b, bn2_s, bn2_b, p_y2);
    // 8. conv3 (1x1) + BN3
    gemm_kernel<3,false><<<dim3(6,256), 256>>>(p_y2, conv3_w, p_y3, MTOK, CC, HID,
                                               conv3_b, bn3_s, bn3_b, nullptr);
    // 9. spatial mean partials
    mean_part_kernel<<<dim3(16,16), CC>>>(p_y3, p_part);
    // 10. SE gate
    se_kernel<<<BB, CC>>>(p_part, comp_w, comp_b, exc_w, exc_b, p_w);
    // 11. assemble
    final_kernel<<<(MTOT*CC + 255)/256, 256>>>(p_x1, p_h2, p_y3, p_w, out);
}

// round 3
// speedup vs baseline: 1.7171x; 1.7171x over previous
#include <cuda_runtime.h>
#include <cstdint>

// ---------------- problem constants ----------------
#define BB   16
#define NN   1025
#define CC   384
#define HH   6
#define HD   64
#define HID  1536
#define TOK  1024
#define MTOT (BB*NN)      // 16400
#define MTOK (BB*TOK)     // 16384

// ---------------- scratch (device globals, no alloc) ----------------
__device__ float g_h   [MTOT*CC];
__device__ float g_qkv [MTOT*3*CC];
__device__ float g_o   [MTOT*CC];
__device__ float g_x1  [MTOT*CC];
__device__ float g_h2  [MTOT*CC];
__device__ float g_y   [MTOK*HID];
__device__ float g_y2  [MTOK*HID];
__device__ float g_y3  [MTOK*CC];
__device__ float g_part[BB*16*CC];
__device__ float g_w   [BB*CC];

__device__ __forceinline__ float gelu_f(float x){
    return 0.5f * x * (1.0f + erff(x * 0.70710678118654752f));
}

__device__ __forceinline__ uint32_t cvt_tf32(float f){
    uint32_t u;
    asm("cvt.rna.tf32.f32 %0, %1;" : "=r"(u) : "f"(f));
    return u;
}

__device__ __forceinline__ void mma_tf32(float* c, const uint32_t* a, const uint32_t* b){
    asm volatile("mma.sync.aligned.m16n8k8.row.col.f32.tf32.tf32.f32 "
        "{%0,%1,%2,%3}, {%4,%5,%6,%7}, {%8,%9}, {%0,%1,%2,%3};"
        : "+f"(c[0]), "+f"(c[1]), "+f"(c[2]), "+f"(c[3])
        : "r"(a[0]), "r"(a[1]), "r"(a[2]), "r"(a[3]), "r"(b[0]), "r"(b[1]));
}

// ---------------- LayerNorm over last dim (C=384) ----------------
__global__ void ln_kernel(const float* __restrict__ x, const float* __restrict__ g,
                          const float* __restrict__ bta, float* __restrict__ out)
{
    __shared__ float red[4];
    __shared__ float bc[2];
    int row = blockIdx.x;
    const float* xr = x + (size_t)row * CC;
    int t = threadIdx.x;                      // 128 threads
    float v0 = xr[t], v1 = xr[t+128], v2 = xr[t+256];
    float s = v0 + v1 + v2;
    #pragma unroll
    for (int o=16;o;o>>=1) s += __shfl_xor_sync(0xffffffffu, s, o);
    if ((t&31)==0) red[t>>5] = s;
    __syncthreads();
    if (t==0) bc[0] = (red[0]+red[1]+red[2]+red[3]) * (1.0f/CC);
    __syncthreads();
    float mu = bc[0];
    float d0=v0-mu, d1=v1-mu, d2=v2-mu;
    float q = d0*d0 + d1*d1 + d2*d2;
    #pragma unroll
    for (int o=16;o;o>>=1) q += __shfl_xor_sync(0xffffffffu, q, o);
    if ((t&31)==0) red[t>>5] = q;
    __syncthreads();
    if (t==0) bc[1] = rsqrtf((red[0]+red[1]+red[2]+red[3]) * (1.0f/CC) + 1e-5f);
    __syncthreads();
    float rs = bc[1];
    float* orow = out + (size_t)row * CC;
    orow[t]     = d0*rs*g[t]     + bta[t];
    orow[t+128] = d1*rs*g[t+128] + bta[t+128];
    orow[t+256] = d2*rs*g[t+256] + bta[t+256];
}

// ---------------- TF32 tensor-core GEMM: C[M,N] = A[M,K] @ W[N,K]^T + epilogue --------
// Block tile 128x64, 4 warps (each 64x32 = 4x4 m16n8k8 frags), k-block 32.
// smem row stride 36 words: conflict-free STS.128 staging and LDS.32 frag loads.
// EPI: 0 none | 1 residual+bias | 2 (v+bias)*scale+shift then GELU | 3 same no GELU
#define SPAD 36
template<int EPI, bool SKIP>
__global__ void __launch_bounds__(128) gemm_tc(
    const float* __restrict__ A, const float* __restrict__ W, float* __restrict__ C,
    int M, int N, int K,
    const float* __restrict__ bias, const float* __restrict__ scale,
    const float* __restrict__ shift, const float* __restrict__ residual)
{
    __shared__ uint32_t As[128*SPAD];
    __shared__ uint32_t Bs[64*SPAD];
    const int tid  = threadIdx.x;
    const int lane = tid & 31;
    const int warp = tid >> 5;
    const int wm = (warp & 1) * 64;
    const int wn = (warp >> 1) * 32;
    const int m0 = blockIdx.y * 128, n0 = blockIdx.x * 64;
    const int f = tid & 7;          // float4 slot within 32-wide k
    const int r = tid >> 3;         // row group 0..15
    const int g4 = lane >> 2;       // 0..7
    const int q4 = lane & 3;        // 0..3

    float c[4][4][4];
    #pragma unroll
    for (int i=0;i<4;i++)
        #pragma unroll
        for (int j=0;j<4;j++)
            #pragma unroll
            for (int e=0;e<4;e++) c[i][j][e] = 0.f;

    for (int k0 = 0; k0 < K; k0 += 32){
        // ---- stage A (128 x 32) ----
        #pragma unroll
        for (int i = 0; i < 8; i++){
            int row = r + 16*i;
            int m = m0 + row;
            float4 v = make_float4(0.f,0.f,0.f,0.f);
            if (m < M){
                int gr = SKIP ? ((m >> 10)*1025 + (m & 1023) + 1) : m;
                v = *(const float4*)(A + (size_t)gr*K + k0 + 4*f);
            }
            uint4 u;
            u.x = cvt_tf32(v.x); u.y = cvt_tf32(v.y);
            u.z = cvt_tf32(v.z); u.w = cvt_tf32(v.w);
            *(uint4*)(As + row*SPAD + 4*f) = u;
        }
        // ---- stage B (64 x 32) ----
        #pragma unroll
        for (int i = 0; i < 4; i++){
            int row = r + 16*i;
            float4 v = *(const float4*)(W + (size_t)(n0+row)*K + k0 + 4*f);
            uint4 u;
            u.x = cvt_tf32(v.x); u.y = cvt_tf32(v.y);
            u.z = cvt_tf32(v.z); u.w = cvt_tf32(v.w);
            *(uint4*)(Bs + row*SPAD + 4*f) = u;
        }
        __syncthreads();
        // ---- mma over 4 k-steps of 8 ----
        #pragma unroll
        for (int k8 = 0; k8 < 4; k8++){
            const int kb = k8*8 + q4;
            uint32_t a[4][4], b[4][2];
            #pragma unroll
            for (int i=0;i<4;i++){
                int ar = wm + 16*i + g4;
                a[i][0] = As[ar*SPAD + kb];
                a[i][1] = As[(ar+8)*SPAD + kb];
                a[i][2] = As[ar*SPAD + kb + 4];
                a[i][3] = As[(ar+8)*SPAD + kb + 4];
            }
            #pragma unroll
            for (int j=0;j<4;j++){
                int br = wn + 8*j + g4;
                b[j][0] = Bs[br*SPAD + kb];
                b[j][1] = Bs[br*SPAD + kb + 4];
            }
            #pragma unroll
            for (int i=0;i<4;i++)
                #pragma unroll
                for (int j=0;j<4;j++)
                    mma_tf32(c[i][j], a[i], b[j]);
        }
        __syncthreads();
    }
    // ---- epilogue ----
    #pragma unroll
    for (int i=0;i<4;i++){
        int mrow0 = m0 + wm + 16*i + g4;
        #pragma unroll
        for (int hh=0; hh<2; hh++){
            int m = mrow0 + 8*hh;
            if (m >= M) continue;
            #pragma unroll
            for (int j=0;j<4;j++){
                int n = n0 + wn + 8*j + 2*q4;
                #pragma unroll
                for (int e=0; e<2; e++){
                    int nc = n + e;
                    float v = c[i][j][hh*2 + e];
                    size_t idx = (size_t)m*N + nc;
                    if (EPI == 0)      C[idx] = v;
                    else if (EPI == 1) C[idx] = residual[idx] + v + bias[nc];
                    else if (EPI == 2){ v = (v + bias[nc])*scale[nc] + shift[nc]; C[idx] = gelu_f(v); }
                    else               C[idx] = (v + bias[nc])*scale[nc] + shift[nc];
                }
            }
        }
    }
}

// ---------------- fused flash attention (scalar, unchanged this round) ----------------
#define APAD 68
#define ATTN_SMEM_FLOATS (3*64*APAD + 192)

__global__ void __launch_bounds__(256) attn_kernel(const float* __restrict__ qkv,
                                                   float* __restrict__ o)
{
    extern __shared__ float sm[];
    float* QsT = sm;                    // [d][q]  64*68
    float* KVs = sm + 64*APAD;          // K: [d][k], later V: [k][d]
    float* PsT = sm + 2*64*APAD;        // [k][q]
    float* m_s = sm + 3*64*APAD;        // 64
    float* l_s = m_s + 64;              // 64
    float* al_s = l_s + 64;             // 64

    const int tid = threadIdx.x;
    const int tile = blockIdx.x % 17;
    const int bh   = blockIdx.x / 17;
    const int h = bh % HH, b = bh / HH;
    const int q0 = tile * 64;

    const float* qp = qkv + (size_t)b*NN*(3*CC) + h*HD;
    const float* kp = qp + CC;
    const float* vp = qp + 2*CC;

    const int d  = tid & 63;
    const int r0 = tid >> 6;            // 0..3
    const int tx4 = (tid & 15) * 4;
    const int ty4 = (tid >> 4) * 4;

    #pragma unroll
    for (int i=0;i<16;i++){
        int r = r0*16 + i;
        int q = q0 + r;
        QsT[d*APAD + r] = (q < NN) ? qp[(size_t)q*(3*CC) + d] * 0.125f : 0.f;
    }
    if (tid < 64){ m_s[tid] = -1e30f; l_s[tid] = 0.f; }
    float acc[4][4] = {};
    __syncthreads();

    for (int kt = 0; kt < 17; kt++){
        int nv = min(64, NN - kt*64);
        #pragma unroll
        for (int i=0;i<16;i++){
            int r = r0*16 + i;
            int kk = kt*64 + r;
            KVs[d*APAD + r] = (kk < NN) ? kp[(size_t)kk*(3*CC) + d] : 0.f;
        }
        __syncthreads();
        float s[4][4] = {};
        #pragma unroll
        for (int dd=0; dd<64; dd++){
            float4 a  = *(const float4*)(QsT + dd*APAD + ty4);
            float4 bb = *(const float4*)(KVs + dd*APAD + tx4);
            s[0][0]+=a.x*bb.x; s[0][1]+=a.x*bb.y; s[0][2]+=a.x*bb.z; s[0][3]+=a.x*bb.w;
            s[1][0]+=a.y*bb.x; s[1][1]+=a.y*bb.y; s[1][2]+=a.y*bb.z; s[1][3]+=a.y*bb.w;
            s[2][0]+=a.z*bb.x; s[2][1]+=a.z*bb.y; s[2][2]+=a.z*bb.z; s[2][3]+=a.z*bb.w;
            s[3][0]+=a.w*bb.x; s[3][1]+=a.w*bb.y; s[3][2]+=a.w*bb.z; s[3][3]+=a.w*bb.w;
        }
        #pragma unroll
        for (int j=0;j<4;j++)
            #pragma unroll
            for (int i=0;i<4;i++)
                PsT[(tx4+j)*APAD + ty4 + i] = s[i][j];
        __syncthreads();
        #pragma unroll
        for (int i=0;i<16;i++){
            int r = r0*16 + i;
            int kk = kt*64 + r;
            KVs[r*APAD + d] = (kk < NN) ? vp[(size_t)kk*(3*CC) + d] : 0.f;
        }
        if (tid < 64){
            float mold = m_s[tid], mx = mold;
            for (int k=0;k<nv;k++) mx = fmaxf(mx, PsT[k*APAD + tid]);
            float alpha = __expf(mold - mx);
            float ls = 0.f;
            for (int k=0;k<nv;k++){
                float p = __expf(PsT[k*APAD + tid] - mx);
                PsT[k*APAD + tid] = p;
                ls += p;
            }
            for (int k=nv;k<64;k++) PsT[k*APAD + tid] = 0.f;
            l_s[tid]  = l_s[tid]*alpha + ls;
            m_s[tid]  = mx;
            al_s[tid] = alpha;
        }
        __syncthreads();
        float al[4];
        #pragma unroll
        for (int i=0;i<4;i++) al[i] = al_s[ty4 + i];
        #pragma unroll
        for (int i=0;i<4;i++)
            #pragma unroll
            for (int j=0;j<4;j++)
                acc[i][j] *= al[i];
        #pragma unroll
        for (int k=0;k<64;k++){
            float4 a  = *(const float4*)(PsT + k*APAD + ty4);
            float4 bb = *(const float4*)(KVs + k*APAD + tx4);
            acc[0][0]+=a.x*bb.x; acc[0][1]+=a.x*bb.y; acc[0][2]+=a.x*bb.z; acc[0][3]+=a.x*bb.w;
            acc[1][0]+=a.y*bb.x; acc[1][1]+=a.y*bb.y; acc[1][2]+=a.y*bb.z; acc[1][3]+=a.y*bb.w;
            acc[2][0]+=a.z*bb.x; acc[2][1]+=a.z*bb.y; acc[2][2]+=a.z*bb.z; acc[2][3]+=a.z*bb.w;
            acc[3][0]+=a.w*bb.x; acc[3][1]+=a.w*bb.y; acc[3][2]+=a.w*bb.z; acc[3][3]+=a.w*bb.w;
        }
        __syncthreads();
    }
    #pragma unroll
    for (int i=0;i<4;i++){
        int q = q0 + ty4 + i;
        if (q >= NN) continue;
        float linv = 1.0f / l_s[ty4 + i];
        float4 rr;
        rr.x = acc[i][0]*linv; rr.y = acc[i][1]*linv;
        rr.z = acc[i][2]*linv; rr.w = acc[i][3]*linv;
        *(float4*)(o + ((size_t)(b*NN + q))*CC + h*HD + tx4) = rr;
    }
}

// ---------------- depthwise 3x3 + BN + residual GELU ----------------
__global__ void dwconv_kernel(const float* __restrict__ y, const float* __restrict__ w2,
                              const float* __restrict__ b2, const float* __restrict__ s2,
                              const float* __restrict__ h2b, float* __restrict__ out)
{
    int pix = blockIdx.x;                 // 0..16383
    int b = pix >> 10, p = pix & 1023;
    int sy = p >> 5, sx = p & 31;
    const float* yb = y + (size_t)(b << 10) * HID;
    for (int c = threadIdx.x; c < HID; c += blockDim.x){
        float acc = 0.f;
        #pragma unroll
        for (int dy=0; dy<3; dy++){
            int iy = sy + dy - 1;
            if ((unsigned)iy >= 32u) continue;
            #pragma unroll
            for (int dx=0; dx<3; dx++){
                int ix = sx + dx - 1;
                if ((unsigned)ix >= 32u) continue;
                acc += yb[(size_t)((iy<<5)+ix)*HID + c] * w2[c*9 + dy*3 + dx];
            }
        }
        float v = (acc + b2[c]) * s2[c] + h2b[c];
        out[(size_t)pix*HID + c] = y[(size_t)pix*HID + c] + gelu_f(v);
    }
}

// ---------------- spatial mean partials ----------------
__global__ void mean_part_kernel(const float* __restrict__ y3, float* __restrict__ part)
{
    int b = blockIdx.x, ch = blockIdx.y, c = threadIdx.x;   // 384 threads
    float s = 0.f;
    int base = (b << 10) + ch*64;
    for (int t=0;t<64;t++) s += y3[(size_t)(base + t)*CC + c];
    part[(b*16 + ch)*CC + c] = s;
}

// ---------------- SE gate ----------------
__global__ void se_kernel(const float* __restrict__ part, const float* __restrict__ cw,
                          const float* __restrict__ cb, const float* __restrict__ ew,
                          const float* __restrict__ eb, float* __restrict__ wout)
{
    __shared__ float m[CC];
    __shared__ float cv[96];
    int b = blockIdx.x, t = threadIdx.x;    // 384 threads
    float s = 0.f;
    for (int i=0;i<16;i++) s += part[(b*16 + i)*CC + t];
    m[t] = s * (1.0f/1024.0f);
    __syncthreads();
    if (t < 96){
        float a = cb[t];
        for (int k=0;k<CC;k++) a += m[k]*cw[t*CC + k];
        cv[t] = gelu_f(a);
    }
    __syncthreads();
    float a = eb[t];
    for (int k=0;k<96;k++) a += cv[k]*ew[t*96 + k];
    wout[b*CC + t] = a;
}

// ---------------- final assemble: out = x1 + concat(cls*w, y3) ----------------
__global__ void final_kernel(const float* __restrict__ x1, const float* __restrict__ h2,
                             const float* __restrict__ y3, const float* __restrict__ w,
                             float* __restrict__ out)
{
    size_t i = (size_t)blockIdx.x*256 + threadIdx.x;
    if (i >= (size_t)MTOT*CC) return;
    int c = (int)(i % CC);
    int row = (int)(i / CC);
    int b = row / NN, n = row % NN;
    float add;
    if (n == 0) add = h2[i] * w[b*CC + c];
    else        add = y3[(size_t)((b<<10) + (n-1))*CC + c];
    out[i] = x1[i] + add;
}

// ---------------- launcher ----------------
extern "C" void kernel_launch(void* const* d_in, const int* in_sizes, int n_in,
                              void* d_out, int out_size)
{
    const float* x       = (const float*)d_in[0];
    const float* ln1_g   = (const float*)d_in[1];
    const float* ln1_b   = (const float*)d_in[2];
    const float* qkv_w   = (const float*)d_in[3];
    const float* proj_w  = (const float*)d_in[4];
    const float* proj_b  = (const float*)d_in[5];
    const float* ln2_g   = (const float*)d_in[6];
    const float* ln2_b   = (const float*)d_in[7];
    const float* conv1_w = (const float*)d_in[8];
    const float* conv1_b = (const float*)d_in[9];
    const float* conv2_w = (const float*)d_in[10];
    const float* conv2_b = (const float*)d_in[11];
    const float* conv3_w = (const float*)d_in[12];
    const float* conv3_b = (const float*)d_in[13];
    const float* bn1_s   = (const float*)d_in[14];
    const float* bn1_b   = (const float*)d_in[15];
    const float* bn2_s   = (const float*)d_in[16];
    const float* bn2_b   = (const float*)d_in[17];
    const float* bn3_s   = (const float*)d_in[18];
    const float* bn3_b   = (const float*)d_in[19];
    const float* comp_w  = (const float*)d_in[20];
    const float* comp_b  = (const float*)d_in[21];
    const float* exc_w   = (const float*)d_in[22];
    const float* exc_b   = (const float*)d_in[23];
    float* out = (float*)d_out;

    static bool init = false;
    static float *p_h, *p_qkv, *p_o, *p_x1, *p_h2, *p_y, *p_y2, *p_y3, *p_part, *p_w;
    if (!init){
        cudaGetSymbolAddress((void**)&p_h,    g_h);
        cudaGetSymbolAddress((void**)&p_qkv,  g_qkv);
        cudaGetSymbolAddress((void**)&p_o,    g_o);
        cudaGetSymbolAddress((void**)&p_x1,   g_x1);
        cudaGetSymbolAddress((void**)&p_h2,   g_h2);
        cudaGetSymbolAddress((void**)&p_y,    g_y);
        cudaGetSymbolAddress((void**)&p_y2,   g_y2);
        cudaGetSymbolAddress((void**)&p_y3,   g_y3);
        cudaGetSymbolAddress((void**)&p_part, g_part);
        cudaGetSymbolAddress((void**)&p_w,    g_w);
        cudaFuncSetAttribute(attn_kernel, cudaFuncAttributeMaxDynamicSharedMemorySize,
                             ATTN_SMEM_FLOATS*4);
        init = true;
    }

    // 1. LN1
    ln_kernel<<<MTOT, 128>>>(x, ln1_g, ln1_b, p_h);
    // 2. QKV = h @ qkv_w^T (tf32 tensor cores)
    gemm_tc<0,false><<<dim3(18,129), 128>>>(p_h, qkv_w, p_qkv, MTOT, 3*CC, CC,
                                            nullptr, nullptr, nullptr, nullptr);
    // 3. attention -> o
    attn_kernel<<<BB*HH*17, 256, ATTN_SMEM_FLOATS*4>>>(p_qkv, p_o);
    // 4. x1 = x + o @ proj_w^T + proj_b
    gemm_tc<1,false><<<dim3(6,129), 128>>>(p_o, proj_w, p_x1, MTOT, CC, CC,
                                           proj_b, nullptr, nullptr, x);
    // 5. LN2
    ln_kernel<<<MTOT, 128>>>(p_x1, ln2_g, ln2_b, p_h2);
    // 6. conv1 (1x1) + BN1 + GELU on tokens only (skip cls row)
    gemm_tc<2,true><<<dim3(24,128), 128>>>(p_h2, conv1_w, p_y, MTOK, HID, CC,
                                           conv1_b, bn1_s, bn1_b, nullptr);
    // 7. depthwise 3x3 + BN2, y2 = y + gelu(.)
    dwconv_kernel<<<MTOK, 256>>>(p_y, conv2_w, conv2_b, bn2_s, bn2_b, p_y2);
    // 8. conv3 (1x1) + BN3
    gemm_tc<3,false><<<dim3(6,128), 128>>>(p_y2, conv3_w, p_y3, MTOK, CC, HID,
                                           conv3_b, bn3_s, bn3_b, nullptr);
    // 9. spatial mean partials
    mean_part_kernel<<<dim3(16,16), CC>>>(p_y3, p_part);
    // 10. SE gate
    se_kernel<<<BB, CC>>>(p_part, comp_w, comp_b, exc_w, exc_b, p_w);
    // 11. assemble
    final_kernel<<<(MTOT*CC + 255)/256, 256>>>(p_x1, p_h2, p_y3, p_w, out);
}

// round 4
// speedup vs baseline: 2.4869x; 1.4483x over previous
#include <cuda_runtime.h>
#include <cstdint>

// ---------------- problem constants ----------------
#define BB   16
#define NN   1025
#define CC   384
#define HH   6
#define HD   64
#define HID  1536
#define MTOT (BB*NN)      // 16400
#define MTOK (BB*1024)    // 16384

// ---------------- scratch (device globals, no alloc) ----------------
__device__ float g_h   [MTOT*CC];
__device__ float g_qkv [MTOT*3*CC];
__device__ float g_o   [MTOT*CC];
__device__ float g_x1  [MTOT*CC];
__device__ float g_h2  [MTOT*CC];
__device__ float g_y   [MTOK*HID];
__device__ float g_y2  [MTOK*HID];
__device__ float g_y3  [MTOK*CC];
__device__ float g_part[BB*16*CC];
__device__ float g_w   [BB*CC];

__device__ __forceinline__ float gelu_f(float x){
    return 0.5f * x * (1.0f + erff(x * 0.70710678118654752f));
}

__device__ __forceinline__ void mma_tf32(float* c, const uint32_t* a, const uint32_t* b){
    asm volatile("mma.sync.aligned.m16n8k8.row.col.f32.tf32.tf32.f32 "
        "{%0,%1,%2,%3}, {%4,%5,%6,%7}, {%8,%9}, {%0,%1,%2,%3};"
        : "+f"(c[0]), "+f"(c[1]), "+f"(c[2]), "+f"(c[3])
        : "r"(a[0]), "r"(a[1]), "r"(a[2]), "r"(a[3]), "r"(b[0]), "r"(b[1]));
}

__device__ __forceinline__ uint32_t smem_u32(const void* p){
    return (uint32_t)__cvta_generic_to_shared(p);
}

// 16B async copy; pred==false -> zero-fill (src still must be a valid address)
__device__ __forceinline__ void cp16(uint32_t dst, const void* src, bool pred){
    int sz = pred ? 16 : 0;
    asm volatile("cp.async.ca.shared.global [%0], [%1], 16, %2;"
                 :: "r"(dst), "l"(src), "r"(sz));
}
__device__ __forceinline__ void cp_commit(){ asm volatile("cp.async.commit_group;"); }
__device__ __forceinline__ void cp_wait0(){ asm volatile("cp.async.wait_group 0;"); }

// ---------------- LayerNorm over last dim (C=384) ----------------
__global__ void ln_kernel(const float* __restrict__ x, const float* __restrict__ g,
                          const float* __restrict__ bta, float* __restrict__ out)
{
    __shared__ float red[4];
    __shared__ float bc[2];
    int row = blockIdx.x;
    const float* xr = x + (size_t)row * CC;
    int t = threadIdx.x;                      // 128 threads
    float v0 = xr[t], v1 = xr[t+128], v2 = xr[t+256];
    float s = v0 + v1 + v2;
    #pragma unroll
    for (int o=16;o;o>>=1) s += __shfl_xor_sync(0xffffffffu, s, o);
    if ((t&31)==0) red[t>>5] = s;
    __syncthreads();
    if (t==0) bc[0] = (red[0]+red[1]+red[2]+red[3]) * (1.0f/CC);
    __syncthreads();
    float mu = bc[0];
    float d0=v0-mu, d1=v1-mu, d2=v2-mu;
    float q = d0*d0 + d1*d1 + d2*d2;
    #pragma unroll
    for (int o=16;o;o>>=1) q += __shfl_xor_sync(0xffffffffu, q, o);
    if ((t&31)==0) red[t>>5] = q;
    __syncthreads();
    if (t==0) bc[1] = rsqrtf((red[0]+red[1]+red[2]+red[3]) * (1.0f/CC) + 1e-5f);
    __syncthreads();
    float rs = bc[1];
    float* orow = out + (size_t)row * CC;
    orow[t]     = d0*rs*g[t]     + bta[t];
    orow[t+128] = d1*rs*g[t+128] + bta[t+128];
    orow[t+256] = d2*rs*g[t+256] + bta[t+256];
}

// ---------------- TF32 tensor-core GEMM, cp.async double-buffered ----------------
// C[M,N] = A[M,K] @ W[N,K]^T + epilogue. Block tile 128x64, 4 warps, k-block 32.
// EPI: 0 none | 1 residual+bias | 2 (v+bias)*scale+shift then GELU | 3 same no GELU
#define SPAD 36
#define GEMM_SMEM ((2*128 + 2*64)*SPAD*4)
template<int EPI, bool SKIP>
__global__ void __launch_bounds__(128) gemm_tc(
    const float* __restrict__ A, const float* __restrict__ W, float* __restrict__ C,
    int M, int N, int K,
    const float* __restrict__ bias, const float* __restrict__ scale,
    const float* __restrict__ shift, const float* __restrict__ residual)
{
    extern __shared__ float smg[];
    float* Asb[2] = { smg,               smg + 128*SPAD };
    float* Bsb[2] = { smg + 2*128*SPAD,  smg + 2*128*SPAD + 64*SPAD };

    const int tid  = threadIdx.x;
    const int lane = tid & 31;
    const int warp = tid >> 5;
    const int wm = (warp & 1) * 64;
    const int wn = (warp >> 1) * 32;
    const int m0 = blockIdx.y * 128, n0 = blockIdx.x * 64;
    const int f = tid & 7;          // float4 slot within 32-wide k
    const int r = tid >> 3;         // row group 0..15
    const int g4 = lane >> 2;       // 0..7
    const int q4 = lane & 3;        // 0..3

    float c[4][4][4];
    #pragma unroll
    for (int i=0;i<4;i++)
        #pragma unroll
        for (int j=0;j<4;j++)
            #pragma unroll
            for (int e=0;e<4;e++) c[i][j][e] = 0.f;

    const int nk = K / 32;

    // stage k-block kb into buffer buf
    auto stage = [&](int kb, int buf){
        int k0 = kb * 32;
        #pragma unroll
        for (int i = 0; i < 8; i++){
            int row = r + 16*i;
            int m = m0 + row;
            bool p = (m < M);
            int gr = 0;
            if (p) gr = SKIP ? ((m >> 10)*1025 + (m & 1023) + 1) : m;
            cp16(smem_u32(Asb[buf] + row*SPAD + 4*f), A + (size_t)gr*K + k0 + 4*f, p);
        }
        #pragma unroll
        for (int i = 0; i < 4; i++){
            int row = r + 16*i;
            cp16(smem_u32(Bsb[buf] + row*SPAD + 4*f), W + (size_t)(n0+row)*K + k0 + 4*f, true);
        }
    };

    stage(0, 0);
    cp_commit();

    for (int kb = 0; kb < nk; kb++){
        cp_wait0();
        __syncthreads();
        if (kb + 1 < nk){ stage(kb+1, (kb+1)&1); cp_commit(); }
        const uint32_t* Au = (const uint32_t*)Asb[kb&1];
        const uint32_t* Bu = (const uint32_t*)Bsb[kb&1];
        #pragma unroll
        for (int k8 = 0; k8 < 4; k8++){
            const int kbp = k8*8 + q4;
            uint32_t a[4][4], b[4][2];
            #pragma unroll
            for (int i=0;i<4;i++){
                int ar = wm + 16*i + g4;
                a[i][0] = Au[ar*SPAD + kbp];
                a[i][1] = Au[(ar+8)*SPAD + kbp];
                a[i][2] = Au[ar*SPAD + kbp + 4];
                a[i][3] = Au[(ar+8)*SPAD + kbp + 4];
            }
            #pragma unroll
            for (int j=0;j<4;j++){
                int br = wn + 8*j + g4;
                b[j][0] = Bu[br*SPAD + kbp];
                b[j][1] = Bu[br*SPAD + kbp + 4];
            }
            #pragma unroll
            for (int i=0;i<4;i++)
                #pragma unroll
                for (int j=0;j<4;j++)
                    mma_tf32(c[i][j], a[i], b[j]);
        }
    }
    // ---- epilogue ----
    #pragma unroll
    for (int i=0;i<4;i++){
        int mrow0 = m0 + wm + 16*i + g4;
        #pragma unroll
        for (int hh=0; hh<2; hh++){
            int m = mrow0 + 8*hh;
            if (m >= M) continue;
            #pragma unroll
            for (int j=0;j<4;j++){
                int n = n0 + wn + 8*j + 2*q4;
                #pragma unroll
                for (int e=0; e<2; e++){
                    int nc = n + e;
                    float v = c[i][j][hh*2 + e];
                    size_t idx = (size_t)m*N + nc;
                    if (EPI == 0)      C[idx] = v;
                    else if (EPI == 1) C[idx] = residual[idx] + v + bias[nc];
                    else if (EPI == 2){ v = (v + bias[nc])*scale[nc] + shift[nc]; C[idx] = gelu_f(v); }
                    else               C[idx] = (v + bias[nc])*scale[nc] + shift[nc];
                }
            }
        }
    }
}

// ---------------- tensor-core flash attention ----------------
// 128 threads (4 warps), each warp owns 16 q rows. 64-q tile x 17 k-tiles of 64.
// S=Q·K^T and P·V via m16n8k8 tf32 mma; online softmax in registers.
#define AST 68
#define ATTN_SMEM (3*64*AST*4)
__global__ void __launch_bounds__(128) attn_tc(const float* __restrict__ qkv,
                                               float* __restrict__ o)
{
    extern __shared__ float sm[];
    float* Qs = sm;                 // [64][AST]
    float* Ks = sm + 64*AST;        // [64][AST], reused as P staging
    float* Vs = sm + 2*64*AST;      // [64][AST]

    const int tid  = threadIdx.x;
    const int lane = tid & 31;
    const int warp = tid >> 5;
    const int g4 = lane >> 2, q4 = lane & 3;
    const int tile = blockIdx.x % 17;
    const int bh   = blockIdx.x / 17;
    const int h = bh % HH, b = bh / HH;
    const int q0 = tile * 64;
    const int qrow = warp * 16;

    const float* qp = qkv + (size_t)b*NN*(3*CC) + h*HD;
    const float* kp = qp + CC;
    const float* vp = qp + 2*CC;

    const int f  = tid & 15;        // float4 slot (16 per 64-wide row)
    const int rr = tid >> 4;        // 0..7

    // stage Q (once)
    #pragma unroll
    for (int i=0;i<8;i++){
        int row = rr + 8*i;
        int q = q0 + row;
        bool p = (q < NN);
        const float* src = qp + (size_t)(p ? q : 0)*(3*CC) + 4*f;
        cp16(smem_u32(Qs + row*AST + 4*f), src, p);
    }
    cp_commit();

    float oa[8][4];
    #pragma unroll
    for (int j=0;j<8;j++){ oa[j][0]=0.f; oa[j][1]=0.f; oa[j][2]=0.f; oa[j][3]=0.f; }
    float m0r = -1e30f, m1r = -1e30f, l0r = 0.f, l1r = 0.f;

    for (int kt = 0; kt < 17; kt++){
        // stage K and V tiles
        #pragma unroll
        for (int i=0;i<8;i++){
            int row = rr + 8*i;
            int kk = kt*64 + row;
            bool p = (kk < NN);
            size_t off = (size_t)(p ? kk : 0)*(3*CC) + 4*f;
            cp16(smem_u32(Ks + row*AST + 4*f), kp + off, p);
            cp16(smem_u32(Vs + row*AST + 4*f), vp + off, p);
        }
        cp_commit();
        cp_wait0();
        __syncthreads();

        const uint32_t* Qu = (const uint32_t*)Qs;
        const uint32_t* Ku = (const uint32_t*)Ks;
        const uint32_t* Vu = (const uint32_t*)Vs;

        // ---- S = Q K^T ----
        float sc[8][4];
        #pragma unroll
        for (int j=0;j<8;j++){ sc[j][0]=0.f; sc[j][1]=0.f; sc[j][2]=0.f; sc[j][3]=0.f; }
        #pragma unroll
        for (int ks=0; ks<8; ks++){
            uint32_t a[4];
            a[0] = Qu[(qrow+g4)*AST   + ks*8+q4];
            a[1] = Qu[(qrow+g4+8)*AST + ks*8+q4];
            a[2] = Qu[(qrow+g4)*AST   + ks*8+q4+4];
            a[3] = Qu[(qrow+g4+8)*AST + ks*8+q4+4];
            #pragma unroll
            for (int j=0;j<8;j++){
                uint32_t bfr[2];
                bfr[0] = Ku[(8*j+g4)*AST + ks*8+q4];
                bfr[1] = Ku[(8*j+g4)*AST + ks*8+q4+4];
                mma_tf32(sc[j], a, bfr);
            }
        }
        // scale 1/sqrt(64) and mask invalid keys (only last tile)
        #pragma unroll
        for (int j=0;j<8;j++){
            sc[j][0]*=0.125f; sc[j][1]*=0.125f; sc[j][2]*=0.125f; sc[j][3]*=0.125f;
        }
        if (kt == 16){
            #pragma unroll
            for (int j=0;j<8;j++){
                int c0 = kt*64 + 8*j + 2*q4;
                if (c0   >= NN){ sc[j][0] = -1e30f; sc[j][2] = -1e30f; }
                if (c0+1 >= NN){ sc[j][1] = -1e30f; sc[j][3] = -1e30f; }
            }
        }
        // ---- online softmax in registers ----
        float mx0 = -1e30f, mx1 = -1e30f;
        #pragma unroll
        for (int j=0;j<8;j++){
            mx0 = fmaxf(mx0, fmaxf(sc[j][0], sc[j][1]));
            mx1 = fmaxf(mx1, fmaxf(sc[j][2], sc[j][3]));
        }
        mx0 = fmaxf(mx0, __shfl_xor_sync(0xffffffffu, mx0, 1));
        mx0 = fmaxf(mx0, __shfl_xor_sync(0xffffffffu, mx0, 2));
        mx1 = fmaxf(mx1, __shfl_xor_sync(0xffffffffu, mx1, 1));
        mx1 = fmaxf(mx1, __shfl_xor_sync(0xffffffffu, mx1, 2));
        float mn0 = fmaxf(m0r, mx0), mn1 = fmaxf(m1r, mx1);
        float al0 = __expf(m0r - mn0), al1 = __expf(m1r - mn1);
        float s0 = 0.f, s1 = 0.f;
        #pragma unroll
        for (int j=0;j<8;j++){
            float p00 = __expf(sc[j][0]-mn0), p01 = __expf(sc[j][1]-mn0);
            float p10 = __expf(sc[j][2]-mn1), p11 = __expf(sc[j][3]-mn1);
            sc[j][0]=p00; sc[j][1]=p01; sc[j][2]=p10; sc[j][3]=p11;
            s0 += p00 + p01; s1 += p10 + p11;
        }
        s0 += __shfl_xor_sync(0xffffffffu, s0, 1);
        s0 += __shfl_xor_sync(0xffffffffu, s0, 2);
        s1 += __shfl_xor_sync(0xffffffffu, s1, 1);
        s1 += __shfl_xor_sync(0xffffffffu, s1, 2);
        l0r = l0r*al0 + s0; l1r = l1r*al1 + s1;
        m0r = mn0; m1r = mn1;
        #pragma unroll
        for (int j=0;j<8;j++){
            oa[j][0]*=al0; oa[j][1]*=al0; oa[j][2]*=al1; oa[j][3]*=al1;
        }
        __syncthreads();               // all warps done reading Ks
        // ---- stage P into Ks region (per-warp slice) ----
        float* Ps = Ks + warp*16*AST;
        #pragma unroll
        for (int j=0;j<8;j++){
            Ps[g4*AST     + 8*j + 2*q4]     = sc[j][0];
            Ps[g4*AST     + 8*j + 2*q4 + 1] = sc[j][1];
            Ps[(g4+8)*AST + 8*j + 2*q4]     = sc[j][2];
            Ps[(g4+8)*AST + 8*j + 2*q4 + 1] = sc[j][3];
        }
        __syncwarp();
        const uint32_t* Pu = (const uint32_t*)Ps;
        // ---- O += P V ----
        #pragma unroll
        for (int ks=0; ks<8; ks++){
            uint32_t a[4];
            a[0] = Pu[g4*AST     + ks*8+q4];
            a[1] = Pu[(g4+8)*AST + ks*8+q4];
            a[2] = Pu[g4*AST     + ks*8+q4+4];
            a[3] = Pu[(g4+8)*AST + ks*8+q4+4];
            #pragma unroll
            for (int j=0;j<8;j++){
                uint32_t bfr[2];
                bfr[0] = Vu[(ks*8+q4)*AST   + 8*j+g4];
                bfr[1] = Vu[(ks*8+q4+4)*AST + 8*j+g4];
                mma_tf32(oa[j], a, bfr);
            }
        }
        __syncthreads();               // PV reads done before next tile overwrites
    }
    // ---- write O ----
    float inv0 = 1.0f / l0r, inv1 = 1.0f / l1r;
    int qg0 = q0 + qrow + g4, qg1 = qg0 + 8;
    #pragma unroll
    for (int j=0;j<8;j++){
        int d = h*HD + 8*j + 2*q4;
        if (qg0 < NN){
            float2 v; v.x = oa[j][0]*inv0; v.y = oa[j][1]*inv0;
            *(float2*)(o + (size_t)(b*NN + qg0)*CC + d) = v;
        }
        if (qg1 < NN){
            float2 v; v.x = oa[j][2]*inv1; v.y = oa[j][3]*inv1;
            *(float2*)(o + (size_t)(b*NN + qg1)*CC + d) = v;
        }
    }
}

// ---------------- depthwise 3x3 + BN + residual GELU ----------------
__global__ void dwconv_kernel(const float* __restrict__ y, const float* __restrict__ w2,
                              const float* __restrict__ b2, const float* __restrict__ s2,
                              const float* __restrict__ h2b, float* __restrict__ out)
{
    int pix = blockIdx.x;                 // 0..16383
    int b = pix >> 10, p = pix & 1023;
    int sy = p >> 5, sx = p & 31;
    const float* yb = y + (size_t)(b << 10) * HID;
    for (int c = threadIdx.x; c < HID; c += blockDim.x){
        float acc = 0.f;
        #pragma unroll
        for (int dy=0; dy<3; dy++){
            int iy = sy + dy - 1;
            if ((unsigned)iy >= 32u) continue;
            #pragma unroll
            for (int dx=0; dx<3; dx++){
                int ix = sx + dx - 1;
                if ((unsigned)ix >= 32u) continue;
                acc += yb[(size_t)((iy<<5)+ix)*HID + c] * w2[c*9 + dy*3 + dx];
            }
        }
        float v = (acc + b2[c]) * s2[c] + h2b[c];
        out[(size_t)pix*HID + c] = y[(size_t)pix*HID + c] + gelu_f(v);
    }
}

// ---------------- spatial mean partials ----------------
__global__ void mean_part_kernel(const float* __restrict__ y3, float* __restrict__ part)
{
    int b = blockIdx.x, ch = blockIdx.y, c = threadIdx.x;   // 384 threads
    float s = 0.f;
    int base = (b << 10) + ch*64;
    for (int t=0;t<64;t++) s += y3[(size_t)(base + t)*CC + c];
    part[(b*16 + ch)*CC + c] = s;
}

// ---------------- SE gate ----------------
__global__ void se_kernel(const float* __restrict__ part, const float* __restrict__ cw,
                          const float* __restrict__ cb, const float* __restrict__ ew,
                          const float* __restrict__ eb, float* __restrict__ wout)
{
    __shared__ float m[CC];
    __shared__ float cv[96];
    int b = blockIdx.x, t = threadIdx.x;    // 384 threads
    float s = 0.f;
    for (int i=0;i<16;i++) s += part[(b*16 + i)*CC + t];
    m[t] = s * (1.0f/1024.0f);
    __syncthreads();
    if (t < 96){
        float a = cb[t];
        for (int k=0;k<CC;k++) a += m[k]*cw[t*CC + k];
        cv[t] = gelu_f(a);
    }
    __syncthreads();
    float a = eb[t];
    for (int k=0;k<96;k++) a += cv[k]*ew[t*96 + k];
    wout[b*CC + t] = a;
}

// ---------------- final assemble: out = x1 + concat(cls*w, y3) ----------------
__global__ void final_kernel(const float* __restrict__ x1, const float* __restrict__ h2,
                             const float* __restrict__ y3, const float* __restrict__ w,
                             float* __restrict__ out)
{
    size_t i = (size_t)blockIdx.x*256 + threadIdx.x;
    if (i >= (size_t)MTOT*CC) return;
    int c = (int)(i % CC);
    int row = (int)(i / CC);
    int b = row / NN, n = row % NN;
    float add;
    if (n == 0) add = h2[i] * w[b*CC + c];
    else        add = y3[(size_t)((b<<10) + (n-1))*CC + c];
    out[i] = x1[i] + add;
}

// ---------------- launcher ----------------
extern "C" void kernel_launch(void* const* d_in, const int* in_sizes, int n_in,
                              void* d_out, int out_size)
{
    const float* x       = (const float*)d_in[0];
    const float* ln1_g   = (const float*)d_in[1];
    const float* ln1_b   = (const float*)d_in[2];
    const float* qkv_w   = (const float*)d_in[3];
    const float* proj_w  = (const float*)d_in[4];
    const float* proj_b  = (const float*)d_in[5];
    const float* ln2_g   = (const float*)d_in[6];
    const float* ln2_b   = (const float*)d_in[7];
    const float* conv1_w = (const float*)d_in[8];
    const float* conv1_b = (const float*)d_in[9];
    const float* conv2_w = (const float*)d_in[10];
    const float* conv2_b = (const float*)d_in[11];
    const float* conv3_w = (const float*)d_in[12];
    const float* conv3_b = (const float*)d_in[13];
    const float* bn1_s   = (const float*)d_in[14];
    const float* bn1_b   = (const float*)d_in[15];
    const float* bn2_s   = (const float*)d_in[16];
    const float* bn2_b   = (const float*)d_in[17];
    const float* bn3_s   = (const float*)d_in[18];
    const float* bn3_b   = (const float*)d_in[19];
    const float* comp_w  = (const float*)d_in[20];
    const float* comp_b  = (const float*)d_in[21];
    const float* exc_w   = (const float*)d_in[22];
    const float* exc_b   = (const float*)d_in[23];
    float* out = (float*)d_out;

    static bool init = false;
    static float *p_h, *p_qkv, *p_o, *p_x1, *p_h2, *p_y, *p_y2, *p_y3, *p_part, *p_w;
    if (!init){
        cudaGetSymbolAddress((void**)&p_h,    g_h);
        cudaGetSymbolAddress((void**)&p_qkv,  g_qkv);
        cudaGetSymbolAddress((void**)&p_o,    g_o);
        cudaGetSymbolAddress((void**)&p_x1,   g_x1);
        cudaGetSymbolAddress((void**)&p_h2,   g_h2);
        cudaGetSymbolAddress((void**)&p_y,    g_y);
        cudaGetSymbolAddress((void**)&p_y2,   g_y2);
        cudaGetSymbolAddress((void**)&p_y3,   g_y3);
        cudaGetSymbolAddress((void**)&p_part, g_part);
        cudaGetSymbolAddress((void**)&p_w,    g_w);
        cudaFuncSetAttribute(gemm_tc<0,false>, cudaFuncAttributeMaxDynamicSharedMemorySize, GEMM_SMEM);
        cudaFuncSetAttribute(gemm_tc<1,false>, cudaFuncAttributeMaxDynamicSharedMemorySize, GEMM_SMEM);
        cudaFuncSetAttribute(gemm_tc<2,true>,  cudaFuncAttributeMaxDynamicSharedMemorySize, GEMM_SMEM);
        cudaFuncSetAttribute(gemm_tc<3,false>, cudaFuncAttributeMaxDynamicSharedMemorySize, GEMM_SMEM);
        cudaFuncSetAttribute(attn_tc, cudaFuncAttributeMaxDynamicSharedMemorySize, ATTN_SMEM);
        init = true;
    }

    // 1. LN1
    ln_kernel<<<MTOT, 128>>>(x, ln1_g, ln1_b, p_h);
    // 2. QKV = h @ qkv_w^T
    gemm_tc<0,false><<<dim3(18,129), 128, GEMM_SMEM>>>(p_h, qkv_w, p_qkv, MTOT, 3*CC, CC,
                                                       nullptr, nullptr, nullptr, nullptr);
    // 3. attention -> o (tensor cores)
    attn_tc<<<BB*HH*17, 128, ATTN_SMEM>>>(p_qkv, p_o);
    // 4. x1 = x + o @ proj_w^T + proj_b
    gemm_tc<1,false><<<dim3(6,129), 128, GEMM_SMEM>>>(p_o, proj_w, p_x1, MTOT, CC, CC,
                                                      proj_b, nullptr, nullptr, x);
    // 5. LN2
    ln_kernel<<<MTOT, 128>>>(p_x1, ln2_g, ln2_b, p_h2);
    // 6. conv1 (1x1) + BN1 + GELU on tokens only (skip cls row)
    gemm_tc<2,true><<<dim3(24,128), 128, GEMM_SMEM>>>(p_h2, conv1_w, p_y, MTOK, HID, CC,
                                                      conv1_b, bn1_s, bn1_b, nullptr);
    // 7. depthwise 3x3 + BN2, y2 = y + gelu(.)
    dwconv_kernel<<<MTOK, 256>>>(p_y, conv2_w, conv2_b, bn2_s, bn2_b, p_y2);
    // 8. conv3 (1x1) + BN3
    gemm_tc<3,false><<<dim3(6,128), 128, GEMM_SMEM>>>(p_y2, conv3_w, p_y3, MTOK, CC, HID,
                                                      conv3_b, bn3_s, bn3_b, nullptr);
    // 9. spatial mean partials
    mean_part_kernel<<<dim3(16,16), CC>>>(p_y3, p_part);
    // 10. SE gate
    se_kernel<<<BB, CC>>>(p_part, comp_w, comp_b, exc_w, exc_b, p_w);
    // 11. assemble
    final_kernel<<<(MTOT*CC + 255)/256, 256>>>(p_x1, p_h2, p_y3, p_w, out);
}

// round 6
// speedup vs baseline: 2.6354x; 1.0597x over previous
#include <cuda_runtime.h>
#include <cstdint>

// ---------------- problem constants ----------------
#define BB   16
#define NN   1025
#define CC   384
#define HH   6
#define HD   64
#define HID  1536
#define MTOT (BB*NN)      // 16400
#define MTOK (BB*1024)    // 16384

// ---------------- scratch (device globals, no alloc) ----------------
__device__ float g_h   [MTOT*CC];
__device__ float g_qkv [MTOT*3*CC];
__device__ float g_o   [MTOT*CC];
__device__ float g_x1  [MTOT*CC];
__device__ float g_h2  [MTOT*CC];
__device__ float g_y   [MTOK*HID];
__device__ float g_y2  [MTOK*HID];
__device__ float g_y3  [MTOK*CC];
__device__ float g_part[BB*16*CC];
__device__ float g_w   [BB*CC];

__device__ __forceinline__ float gelu_f(float x){
    return 0.5f * x * (1.0f + erff(x * 0.70710678118654752f));
}

__device__ __forceinline__ void mma_tf32(float* c, const uint32_t* a, const uint32_t* b){
    asm volatile("mma.sync.aligned.m16n8k8.row.col.f32.tf32.tf32.f32 "
        "{%0,%1,%2,%3}, {%4,%5,%6,%7}, {%8,%9}, {%0,%1,%2,%3};"
        : "+f"(c[0]), "+f"(c[1]), "+f"(c[2]), "+f"(c[3])
        : "r"(a[0]), "r"(a[1]), "r"(a[2]), "r"(a[3]), "r"(b[0]), "r"(b[1]));
}

__device__ __forceinline__ uint32_t smem_u32(const void* p){
    return (uint32_t)__cvta_generic_to_shared(p);
}

// 16B async copy; pred==false -> zero-fill
__device__ __forceinline__ void cp16(uint32_t dst, const void* src, bool pred){
    int sz = pred ? 16 : 0;
    asm volatile("cp.async.ca.shared.global [%0], [%1], 16, %2;"
                 :: "r"(dst), "l"(src), "r"(sz));
}
__device__ __forceinline__ void cp_commit(){ asm volatile("cp.async.commit_group;"); }
__device__ __forceinline__ void cp_wait0(){ asm volatile("cp.async.wait_group 0;"); }
__device__ __forceinline__ void cp_wait1(){ asm volatile("cp.async.wait_group 1;"); }

// ---------------- LayerNorm over last dim (C=384) ----------------
__global__ void ln_kernel(const float* __restrict__ x, const float* __restrict__ g,
                          const float* __restrict__ bta, float* __restrict__ out)
{
    __shared__ float red[4];
    __shared__ float bc[2];
    int row = blockIdx.x;
    const float* xr = x + (size_t)row * CC;
    int t = threadIdx.x;                      // 128 threads
    float v0 = xr[t], v1 = xr[t+128], v2 = xr[t+256];
    float s = v0 + v1 + v2;
    #pragma unroll
    for (int o=16;o;o>>=1) s += __shfl_xor_sync(0xffffffffu, s, o);
    if ((t&31)==0) red[t>>5] = s;
    __syncthreads();
    if (t==0) bc[0] = (red[0]+red[1]+red[2]+red[3]) * (1.0f/CC);
    __syncthreads();
    float mu = bc[0];
    float d0=v0-mu, d1=v1-mu, d2=v2-mu;
    float q = d0*d0 + d1*d1 + d2*d2;
    #pragma unroll
    for (int o=16;o;o>>=1) q += __shfl_xor_sync(0xffffffffu, q, o);
    if ((t&31)==0) red[t>>5] = q;
    __syncthreads();
    if (t==0) bc[1] = rsqrtf((red[0]+red[1]+red[2]+red[3]) * (1.0f/CC) + 1e-5f);
    __syncthreads();
    float rs = bc[1];
    float* orow = out + (size_t)row * CC;
    orow[t]     = d0*rs*g[t]     + bta[t];
    orow[t+128] = d1*rs*g[t+128] + bta[t+128];
    orow[t+256] = d2*rs*g[t+256] + bta[t+256];
}

// ---------------- TF32 mma.sync GEMM v2 ----------------
// C[M,N] = A[M,K] @ W[N,K]^T + epilogue.
// 128 threads / 4 warps. CTA tile 128x128, warp tile 64x64, k-block 32.
// Triple-buffered cp.async pipeline, ONE syncthreads per k-block.
// EPI: 0 none | 1 residual+bias | 2 (v+bias)*scale+shift then GELU | 3 same no GELU
#define SPAD 36
#define BUFW (2*128*SPAD)            // words per pipeline buffer (A then B)
#define GEMM_SMEM (3*BUFW*4)         // bytes

template<int EPI, bool SKIP>
__global__ void __launch_bounds__(128) gemm_tc(
    const float* __restrict__ A, const float* __restrict__ W, float* __restrict__ C,
    int M, int N, int K,
    const float* __restrict__ bias, const float* __restrict__ scale,
    const float* __restrict__ shift, const float* __restrict__ residual)
{
    extern __shared__ float smg[];
    const int tid  = threadIdx.x;
    const int lane = tid & 31;
    const int warp = tid >> 5;
    const int wm = (warp & 1) * 64;
    const int wn = (warp >> 1) * 64;
    const int m0 = blockIdx.y * 128, n0 = blockIdx.x * 128;
    const int f = tid & 7;          // float4 slot within 32-wide k
    const int r = tid >> 3;         // row group 0..15
    const int g4 = lane >> 2;       // 0..7
    const int q4 = lane & 3;        // 0..3
    const int nk = K / 32;

    float c[4][8][4];
    #pragma unroll
    for (int i=0;i<4;i++)
        #pragma unroll
        for (int j=0;j<8;j++)
            #pragma unroll
            for (int e=0;e<4;e++) c[i][j][e] = 0.f;

    auto stage = [&](int kb, int bf){
        float* As = smg + bf*BUFW;
        float* Bs = As + 128*SPAD;
        int k0 = kb * 32;
        #pragma unroll
        for (int i = 0; i < 8; i++){
            int row = r + 16*i;
            int m = m0 + row;
            bool p = (m < M);
            int gr = 0;
            if (p) gr = SKIP ? ((m >> 10)*1025 + (m & 1023) + 1) : m;
            cp16(smem_u32(As + row*SPAD + 4*f), A + (size_t)gr*K + k0 + 4*f, p);
        }
        #pragma unroll
        for (int i = 0; i < 8; i++){
            int row = r + 16*i;
            cp16(smem_u32(Bs + row*SPAD + 4*f), W + (size_t)(n0+row)*K + k0 + 4*f, true);
        }
    };

    stage(0, 0); cp_commit();
    stage(1, 1); cp_commit();

    for (int kb = 0; kb < nk; kb++){
        if (kb + 1 < nk) cp_wait1(); else cp_wait0();
        __syncthreads();
        if (kb + 2 < nk){ stage(kb+2, (kb+2)%3); cp_commit(); }
        const uint32_t* Au = (const uint32_t*)(smg + (kb%3)*BUFW);
        const uint32_t* Bu = Au + 128*SPAD;
        #pragma unroll
        for (int k8 = 0; k8 < 4; k8++){
            const int kbp = k8*8 + q4;
            uint32_t a[4][4], b[8][2];
            #pragma unroll
            for (int i=0;i<4;i++){
                int ar = wm + 16*i + g4;
                a[i][0] = Au[ar*SPAD + kbp];
                a[i][1] = Au[(ar+8)*SPAD + kbp];
                a[i][2] = Au[ar*SPAD + kbp + 4];
                a[i][3] = Au[(ar+8)*SPAD + kbp + 4];
            }
            #pragma unroll
            for (int j=0;j<8;j++){
                int br = wn + 8*j + g4;
                b[j][0] = Bu[br*SPAD + kbp];
                b[j][1] = Bu[br*SPAD + kbp + 4];
            }
            #pragma unroll
            for (int i=0;i<4;i++)
                #pragma unroll
                for (int j=0;j<8;j++)
                    mma_tf32(c[i][j], a[i], b[j]);
        }
    }
    // ---- epilogue ----
    #pragma unroll
    for (int i=0;i<4;i++){
        int mrow0 = m0 + wm + 16*i + g4;
        #pragma unroll
        for (int hh=0; hh<2; hh++){
            int m = mrow0 + 8*hh;
            if (m >= M) continue;
            #pragma unroll
            for (int j=0;j<8;j++){
                int n = n0 + wn + 8*j + 2*q4;
                float2 v;
                v.x = c[i][j][hh*2 + 0];
                v.y = c[i][j][hh*2 + 1];
                size_t idx = (size_t)m*N + n;
                if (EPI == 0){
                    *(float2*)(C + idx) = v;
                } else if (EPI == 1){
                    float2 rv = *(const float2*)(residual + idx);
                    v.x += bias[n]   + rv.x;
                    v.y += bias[n+1] + rv.y;
                    *(float2*)(C + idx) = v;
                } else if (EPI == 2){
                    v.x = gelu_f((v.x + bias[n])  *scale[n]   + shift[n]);
                    v.y = gelu_f((v.y + bias[n+1])*scale[n+1] + shift[n+1]);
                    *(float2*)(C + idx) = v;
                } else {
                    v.x = (v.x + bias[n])  *scale[n]   + shift[n];
                    v.y = (v.y + bias[n+1])*scale[n+1] + shift[n+1];
                    *(float2*)(C + idx) = v;
                }
            }
        }
    }
}

// ---------------- tensor-core flash attention (mma.sync) ----------------
#define AST 68
#define ATTN_SMEM (3*64*AST*4)
__global__ void __launch_bounds__(128) attn_tc(const float* __restrict__ qkv,
                                               float* __restrict__ o)
{
    extern __shared__ float sm[];
    float* Qs = sm;                 // [64][AST]
    float* Ks = sm + 64*AST;        // [64][AST], reused as P staging
    float* Vs = sm + 2*64*AST;      // [64][AST]

    const int tid  = threadIdx.x;
    const int lane = tid & 31;
    const int warp = tid >> 5;
    const int g4 = lane >> 2, q4 = lane & 3;
    const int tile = blockIdx.x % 17;
    const int bh   = blockIdx.x / 17;
    const int h = bh % HH, b = bh / HH;
    const int q0 = tile * 64;
    const int qrow = warp * 16;

    const float* qp = qkv + (size_t)b*NN*(3*CC) + h*HD;
    const float* kp = qp + CC;
    const float* vp = qp + 2*CC;

    const int f  = tid & 15;
    const int rr = tid >> 4;

    #pragma unroll
    for (int i=0;i<8;i++){
        int row = rr + 8*i;
        int q = q0 + row;
        bool p = (q < NN);
        const float* src = qp + (size_t)(p ? q : 0)*(3*CC) + 4*f;
        cp16(smem_u32(Qs + row*AST + 4*f), src, p);
    }
    cp_commit();

    float oa[8][4];
    #pragma unroll
    for (int j=0;j<8;j++){ oa[j][0]=0.f; oa[j][1]=0.f; oa[j][2]=0.f; oa[j][3]=0.f; }
    float m0r = -1e30f, m1r = -1e30f, l0r = 0.f, l1r = 0.f;

    for (int kt = 0; kt < 17; kt++){
        #pragma unroll
        for (int i=0;i<8;i++){
            int row = rr + 8*i;
            int kk = kt*64 + row;
            bool p = (kk < NN);
            size_t off = (size_t)(p ? kk : 0)*(3*CC) + 4*f;
            cp16(smem_u32(Ks + row*AST + 4*f), kp + off, p);
            cp16(smem_u32(Vs + row*AST + 4*f), vp + off, p);
        }
        cp_commit();
        cp_wait0();
        __syncthreads();

        const uint32_t* Qu = (const uint32_t*)Qs;
        const uint32_t* Ku = (const uint32_t*)Ks;
        const uint32_t* Vu = (const uint32_t*)Vs;

        float sc[8][4];
        #pragma unroll
        for (int j=0;j<8;j++){ sc[j][0]=0.f; sc[j][1]=0.f; sc[j][2]=0.f; sc[j][3]=0.f; }
        #pragma unroll
        for (int ks=0; ks<8; ks++){
            uint32_t a[4];
            a[0] = Qu[(qrow+g4)*AST   + ks*8+q4];
            a[1] = Qu[(qrow+g4+8)*AST + ks*8+q4];
            a[2] = Qu[(qrow+g4)*AST   + ks*8+q4+4];
            a[3] = Qu[(qrow+g4+8)*AST + ks*8+q4+4];
            #pragma unroll
            for (int j=0;j<8;j++){
                uint32_t bfr[2];
                bfr[0] = Ku[(8*j+g4)*AST + ks*8+q4];
                bfr[1] = Ku[(8*j+g4)*AST + ks*8+q4+4];
                mma_tf32(sc[j], a, bfr);
            }
        }
        #pragma unroll
        for (int j=0;j<8;j++){
            sc[j][0]*=0.125f; sc[j][1]*=0.125f; sc[j][2]*=0.125f; sc[j][3]*=0.125f;
        }
        if (kt == 16){
            #pragma unroll
            for (int j=0;j<8;j++){
                int c0 = kt*64 + 8*j + 2*q4;
                if (c0   >= NN){ sc[j][0] = -1e30f; sc[j][2] = -1e30f; }
                if (c0+1 >= NN){ sc[j][1] = -1e30f; sc[j][3] = -1e30f; }
            }
        }
        float mx0 = -1e30f, mx1 = -1e30f;
        #pragma unroll
        for (int j=0;j<8;j++){
            mx0 = fmaxf(mx0, fmaxf(sc[j][0], sc[j][1]));
            mx1 = fmaxf(mx1, fmaxf(sc[j][2], sc[j][3]));
        }
        mx0 = fmaxf(mx0, __shfl_xor_sync(0xffffffffu, mx0, 1));
        mx0 = fmaxf(mx0, __shfl_xor_sync(0xffffffffu, mx0, 2));
        mx1 = fmaxf(mx1, __shfl_xor_sync(0xffffffffu, mx1, 1));
        mx1 = fmaxf(mx1, __shfl_xor_sync(0xffffffffu, mx1, 2));
        float mn0 = fmaxf(m0r, mx0), mn1 = fmaxf(m1r, mx1);
        float al0 = __expf(m0r - mn0), al1 = __expf(m1r - mn1);
        float s0 = 0.f, s1 = 0.f;
        #pragma unroll
        for (int j=0;j<8;j++){
            float p00 = __expf(sc[j][0]-mn0), p01 = __expf(sc[j][1]-mn0);
            float p10 = __expf(sc[j][2]-mn1), p11 = __expf(sc[j][3]-mn1);
            sc[j][0]=p00; sc[j][1]=p01; sc[j][2]=p10; sc[j][3]=p11;
            s0 += p00 + p01; s1 += p10 + p11;
        }
        s0 += __shfl_xor_sync(0xffffffffu, s0, 1);
        s0 += __shfl_xor_sync(0xffffffffu, s0, 2);
        s1 += __shfl_xor_sync(0xffffffffu, s1, 1);
        s1 += __shfl_xor_sync(0xffffffffu, s1, 2);
        l0r = l0r*al0 + s0; l1r = l1r*al1 + s1;
        m0r = mn0; m1r = mn1;
        #pragma unroll
        for (int j=0;j<8;j++){
            oa[j][0]*=al0; oa[j][1]*=al0; oa[j][2]*=al1; oa[j][3]*=al1;
        }
        __syncthreads();
        float* Ps = Ks + warp*16*AST;
        #pragma unroll
        for (int j=0;j<8;j++){
            Ps[g4*AST     + 8*j + 2*q4]     = sc[j][0];
            Ps[g4*AST     + 8*j + 2*q4 + 1] = sc[j][1];
            Ps[(g4+8)*AST + 8*j + 2*q4]     = sc[j][2];
            Ps[(g4+8)*AST + 8*j + 2*q4 + 1] = sc[j][3];
        }
        __syncwarp();
        const uint32_t* Pu = (const uint32_t*)Ps;
        #pragma unroll
        for (int ks=0; ks<8; ks++){
            uint32_t a[4];
            a[0] = Pu[g4*AST     + ks*8+q4];
            a[1] = Pu[(g4+8)*AST + ks*8+q4];
            a[2] = Pu[g4*AST     + ks*8+q4+4];
            a[3] = Pu[(g4+8)*AST + ks*8+q4+4];
            #pragma unroll
            for (int j=0;j<8;j++){
                uint32_t bfr[2];
                bfr[0] = Vu[(ks*8+q4)*AST   + 8*j+g4];
                bfr[1] = Vu[(ks*8+q4+4)*AST + 8*j+g4];
                mma_tf32(oa[j], a, bfr);
            }
        }
        __syncthreads();
    }
    float inv0 = 1.0f / l0r, inv1 = 1.0f / l1r;
    int qg0 = q0 + qrow + g4, qg1 = qg0 + 8;
    #pragma unroll
    for (int j=0;j<8;j++){
        int d = h*HD + 8*j + 2*q4;
        if (qg0 < NN){
            float2 v; v.x = oa[j][0]*inv0; v.y = oa[j][1]*inv0;
            *(float2*)(o + (size_t)(b*NN + qg0)*CC + d) = v;
        }
        if (qg1 < NN){
            float2 v; v.x = oa[j][2]*inv1; v.y = oa[j][3]*inv1;
            *(float2*)(o + (size_t)(b*NN + qg1)*CC + d) = v;
        }
    }
}

// ---------------- depthwise 3x3 + BN + residual GELU ----------------
__global__ void dwconv_kernel(const float* __restrict__ y, const float* __restrict__ w2,
                              const float* __restrict__ b2, const float* __restrict__ s2,
                              const float* __restrict__ h2b, float* __restrict__ out)
{
    int pix = blockIdx.x;                 // 0..16383
    int b = pix >> 10, p = pix & 1023;
    int sy = p >> 5, sx = p & 31;
    const float* yb = y + (size_t)(b << 10) * HID;
    for (int c = threadIdx.x; c < HID; c += blockDim.x){
        float acc = 0.f;
        #pragma unroll
        for (int dy=0; dy<3; dy++){
            int iy = sy + dy - 1;
            if ((unsigned)iy >= 32u) continue;
            #pragma unroll
            for (int dx=0; dx<3; dx++){
                int ix = sx + dx - 1;
                if ((unsigned)ix >= 32u) continue;
                acc += yb[(size_t)((iy<<5)+ix)*HID + c] * w2[c*9 + dy*3 + dx];
            }
        }
        float v = (acc + b2[c]) * s2[c] + h2b[c];
        out[(size_t)pix*HID + c] = y[(size_t)pix*HID + c] + gelu_f(v);
    }
}

// ---------------- spatial mean partials ----------------
__global__ void mean_part_kernel(const float* __restrict__ y3, float* __restrict__ part)
{
    int b = blockIdx.x, ch = blockIdx.y, c = threadIdx.x;   // 384 threads
    float s = 0.f;
    int base = (b << 10) + ch*64;
    for (int t=0;t<64;t++) s += y3[(size_t)(base + t)*CC + c];
    part[(b*16 + ch)*CC + c] = s;
}

// ---------------- SE gate ----------------
__global__ void se_kernel(const float* __restrict__ part, const float* __restrict__ cw,
                          const float* __restrict__ cb, const float* __restrict__ ew,
                          const float* __restrict__ eb, float* __restrict__ wout)
{
    __shared__ float m[CC];
    __shared__ float cv[96];
    int b = blockIdx.x, t = threadIdx.x;    // 384 threads
    float s = 0.f;
    for (int i=0;i<16;i++) s += part[(b*16 + i)*CC + t];
    m[t] = s * (1.0f/1024.0f);
    __syncthreads();
    if (t < 96){
        float a = cb[t];
        for (int k=0;k<CC;k++) a += m[k]*cw[t*CC + k];
        cv[t] = gelu_f(a);
    }
    __syncthreads();
    float a = eb[t];
    for (int k=0;k<96;k++) a += cv[k]*ew[t*96 + k];
    wout[b*CC + t] = a;
}

// ---------------- final assemble: out = x1 + concat(cls*w, y3) ----------------
__global__ void final_kernel(const float* __restrict__ x1, const float* __restrict__ h2,
                             const float* __restrict__ y3, const float* __restrict__ w,
                             float* __restrict__ out)
{
    size_t i = (size_t)blockIdx.x*256 + threadIdx.x;
    if (i >= (size_t)MTOT*CC) return;
    int c = (int)(i % CC);
    int row = (int)(i / CC);
    int b = row / NN, n = row % NN;
    float add;
    if (n == 0) add = h2[i] * w[b*CC + c];
    else        add = y3[(size_t)((b<<10) + (n-1))*CC + c];
    out[i] = x1[i] + add;
}

// ---------------- launcher ----------------
extern "C" void kernel_launch(void* const* d_in, const int* in_sizes, int n_in,
                              void* d_out, int out_size)
{
    const float* x       = (const float*)d_in[0];
    const float* ln1_g   = (const float*)d_in[1];
    const float* ln1_b   = (const float*)d_in[2];
    const float* qkv_w   = (const float*)d_in[3];
    const float* proj_w  = (const float*)d_in[4];
    const float* proj_b  = (const float*)d_in[5];
    const float* ln2_g   = (const float*)d_in[6];
    const float* ln2_b   = (const float*)d_in[7];
    const float* conv1_w = (const float*)d_in[8];
    const float* conv1_b = (const float*)d_in[9];
    const float* conv2_w = (const float*)d_in[10];
    const float* conv2_b = (const float*)d_in[11];
    const float* conv3_w = (const float*)d_in[12];
    const float* conv3_b = (const float*)d_in[13];
    const float* bn1_s   = (const float*)d_in[14];
    const float* bn1_b   = (const float*)d_in[15];
    const float* bn2_s   = (const float*)d_in[16];
    const float* bn2_b   = (const float*)d_in[17];
    const float* bn3_s   = (const float*)d_in[18];
    const float* bn3_b   = (const float*)d_in[19];
    const float* comp_w  = (const float*)d_in[20];
    const float* comp_b  = (const float*)d_in[21];
    const float* exc_w   = (const float*)d_in[22];
    const float* exc_b   = (const float*)d_in[23];
    float* out = (float*)d_out;

    static bool init = false;
    static float *p_h, *p_qkv, *p_o, *p_x1, *p_h2, *p_y, *p_y2, *p_y3, *p_part, *p_w;
    if (!init){
        cudaGetSymbolAddress((void**)&p_h,    g_h);
        cudaGetSymbolAddress((void**)&p_qkv,  g_qkv);
        cudaGetSymbolAddress((void**)&p_o,    g_o);
        cudaGetSymbolAddress((void**)&p_x1,   g_x1);
        cudaGetSymbolAddress((void**)&p_h2,   g_h2);
        cudaGetSymbolAddress((void**)&p_y,    g_y);
        cudaGetSymbolAddress((void**)&p_y2,   g_y2);
        cudaGetSymbolAddress((void**)&p_y3,   g_y3);
        cudaGetSymbolAddress((void**)&p_part, g_part);
        cudaGetSymbolAddress((void**)&p_w,    g_w);
        cudaFuncSetAttribute(gemm_tc<0,false>, cudaFuncAttributeMaxDynamicSharedMemorySize, GEMM_SMEM);
        cudaFuncSetAttribute(gemm_tc<1,false>, cudaFuncAttributeMaxDynamicSharedMemorySize, GEMM_SMEM);
        cudaFuncSetAttribute(gemm_tc<2,true>,  cudaFuncAttributeMaxDynamicSharedMemorySize, GEMM_SMEM);
        cudaFuncSetAttribute(gemm_tc<3,false>, cudaFuncAttributeMaxDynamicSharedMemorySize, GEMM_SMEM);
        cudaFuncSetAttribute(attn_tc, cudaFuncAttributeMaxDynamicSharedMemorySize, ATTN_SMEM);
        init = true;
    }

    // 1. LN1
    ln_kernel<<<MTOT, 128>>>(x, ln1_g, ln1_b, p_h);
    // 2. QKV = h @ qkv_w^T
    gemm_tc<0,false><<<dim3(9,129), 128, GEMM_SMEM>>>(p_h, qkv_w, p_qkv, MTOT, 3*CC, CC,
                                                      nullptr, nullptr, nullptr, nullptr);
    // 3. attention -> o
    attn_tc<<<BB*HH*17, 128, ATTN_SMEM>>>(p_qkv, p_o);
    // 4. x1 = x + o @ proj_w^T + proj_b
    gemm_tc<1,false><<<dim3(3,129), 128, GEMM_SMEM>>>(p_o, proj_w, p_x1, MTOT, CC, CC,
                                                      proj_b, nullptr, nullptr, x);
    // 5. LN2
    ln_kernel<<<MTOT, 128>>>(p_x1, ln2_g, ln2_b, p_h2);
    // 6. conv1 (1x1) + BN1 + GELU on tokens only (skip cls row)
    gemm_tc<2,true><<<dim3(12,128), 128, GEMM_SMEM>>>(p_h2, conv1_w, p_y, MTOK, HID, CC,
                                                      conv1_b, bn1_s, bn1_b, nullptr);
    // 7. depthwise 3x3 + BN2, y2 = y + gelu(.)
    dwconv_kernel<<<MTOK, 256>>>(p_y, conv2_w, conv2_b, bn2_s, bn2_b, p_y2);
    // 8. conv3 (1x1) + BN3
    gemm_tc<3,false><<<dim3(3,128), 128, GEMM_SMEM>>>(p_y2, conv3_w, p_y3, MTOK, CC, HID,
                                                      conv3_b, bn3_s, bn3_b, nullptr);
    // 9. spatial mean partials
    mean_part_kernel<<<dim3(16,16), CC>>>(p_y3, p_part);
    // 10. SE gate
    se_kernel<<<BB, CC>>>(p_part, comp_w, comp_b, exc_w, exc_b, p_w);
    // 11. assemble
    final_kernel<<<(MTOT*CC + 255)/256, 256>>>(p_x1, p_h2, p_y3, p_w, out);
}

// round 7
// speedup vs baseline: 2.7155x; 1.0304x over previous
#include <cuda_runtime.h>
#include <cstdint>

// ---------------- problem constants ----------------
#define BB   16
#define NN   1025
#define CC   384
#define HH   6
#define HD   64
#define HID  1536
#define MTOT (BB*NN)      // 16400
#define MTOK (BB*1024)    // 16384

// ---------------- scratch (device globals, no alloc) ----------------
__device__ float g_h   [MTOT*CC];
__device__ float g_qkv [MTOT*3*CC];
__device__ float g_o   [MTOT*CC];
__device__ float g_x1  [MTOT*CC];
__device__ float g_h2  [MTOT*CC];
__device__ float g_y   [MTOK*HID];
__device__ float g_y2  [MTOK*HID];
__device__ float g_y3  [MTOK*CC];
__device__ float g_part[BB*16*CC];
__device__ float g_w   [BB*CC];

__device__ __forceinline__ float gelu_f(float x){
    return 0.5f * x * (1.0f + erff(x * 0.70710678118654752f));
}

__device__ __forceinline__ void mma_tf32(float* c, const uint32_t* a, const uint32_t* b){
    asm volatile("mma.sync.aligned.m16n8k8.row.col.f32.tf32.tf32.f32 "
        "{%0,%1,%2,%3}, {%4,%5,%6,%7}, {%8,%9}, {%0,%1,%2,%3};"
        : "+f"(c[0]), "+f"(c[1]), "+f"(c[2]), "+f"(c[3])
        : "r"(a[0]), "r"(a[1]), "r"(a[2]), "r"(a[3]), "r"(b[0]), "r"(b[1]));
}

__device__ __forceinline__ uint32_t smem_u32(const void* p){
    return (uint32_t)__cvta_generic_to_shared(p);
}

// 16B async copy; pred==false -> zero-fill
__device__ __forceinline__ void cp16(uint32_t dst, const void* src, bool pred){
    int sz = pred ? 16 : 0;
    asm volatile("cp.async.ca.shared.global [%0], [%1], 16, %2;"
                 :: "r"(dst), "l"(src), "r"(sz));
}
__device__ __forceinline__ void cp_commit(){ asm volatile("cp.async.commit_group;"); }
__device__ __forceinline__ void cp_wait0(){ asm volatile("cp.async.wait_group 0;"); }
__device__ __forceinline__ void cp_wait1(){ asm volatile("cp.async.wait_group 1;"); }

// ---------------- LayerNorm over last dim (C=384) ----------------
__global__ void ln_kernel(const float* __restrict__ x, const float* __restrict__ g,
                          const float* __restrict__ bta, float* __restrict__ out)
{
    __shared__ float red[4];
    __shared__ float bc[2];
    int row = blockIdx.x;
    const float* xr = x + (size_t)row * CC;
    int t = threadIdx.x;                      // 128 threads
    float v0 = xr[t], v1 = xr[t+128], v2 = xr[t+256];
    float s = v0 + v1 + v2;
    #pragma unroll
    for (int o=16;o;o>>=1) s += __shfl_xor_sync(0xffffffffu, s, o);
    if ((t&31)==0) red[t>>5] = s;
    __syncthreads();
    if (t==0) bc[0] = (red[0]+red[1]+red[2]+red[3]) * (1.0f/CC);
    __syncthreads();
    float mu = bc[0];
    float d0=v0-mu, d1=v1-mu, d2=v2-mu;
    float q = d0*d0 + d1*d1 + d2*d2;
    #pragma unroll
    for (int o=16;o;o>>=1) q += __shfl_xor_sync(0xffffffffu, q, o);
    if ((t&31)==0) red[t>>5] = q;
    __syncthreads();
    if (t==0) bc[1] = rsqrtf((red[0]+red[1]+red[2]+red[3]) * (1.0f/CC) + 1e-5f);
    __syncthreads();
    float rs = bc[1];
    float* orow = out + (size_t)row * CC;
    orow[t]     = d0*rs*g[t]     + bta[t];
    orow[t+128] = d1*rs*g[t+128] + bta[t+128];
    orow[t+256] = d2*rs*g[t+256] + bta[t+256];
}

// ---------------- TF32 mma.sync GEMM v3 ----------------
// C[M,N] = A[M,K] @ W[N,K]^T + epilogue.
// 256 threads / 8 warps. CTA tile 128x128, warp tile 64x32, k-block 32.
// Triple-buffered cp.async pipeline, one syncthreads per k-block, 2 CTAs/SM.
// EPI: 0 none | 1 residual+bias | 2 (v+bias)*scale+shift then GELU | 3 same no GELU
#define SPAD 36
#define BUFW (2*128*SPAD)            // words per pipeline buffer (A then B)
#define GEMM_SMEM (3*BUFW*4)         // bytes (108 KB)

template<int EPI, bool SKIP>
__global__ void __launch_bounds__(256, 2) gemm_tc(
    const float* __restrict__ A, const float* __restrict__ W, float* __restrict__ C,
    int M, int N, int K,
    const float* __restrict__ bias, const float* __restrict__ scale,
    const float* __restrict__ shift, const float* __restrict__ residual)
{
    extern __shared__ float smg[];
    const int tid  = threadIdx.x;
    const int lane = tid & 31;
    const int warp = tid >> 5;
    const int wm = (warp & 1) * 64;      // 2 m-tiles
    const int wn = (warp >> 1) * 32;     // 4 n-tiles
    const int m0 = blockIdx.y * 128, n0 = blockIdx.x * 128;
    const int f = tid & 7;               // float4 slot within 32-wide k
    const int r = tid >> 3;              // row group 0..31
    const int g4 = lane >> 2;            // 0..7
    const int q4 = lane & 3;             // 0..3
    const int nk = K / 32;

    float c[4][4][4];
    #pragma unroll
    for (int i=0;i<4;i++)
        #pragma unroll
        for (int j=0;j<4;j++)
            #pragma unroll
            for (int e=0;e<4;e++) c[i][j][e] = 0.f;

    auto stage = [&](int kb, int bf){
        float* As = smg + bf*BUFW;
        float* Bs = As + 128*SPAD;
        int k0 = kb * 32;
        #pragma unroll
        for (int i = 0; i < 4; i++){
            int row = r + 32*i;
            int m = m0 + row;
            bool p = (m < M);
            int gr = 0;
            if (p) gr = SKIP ? ((m >> 10)*1025 + (m & 1023) + 1) : m;
            cp16(smem_u32(As + row*SPAD + 4*f), A + (size_t)gr*K + k0 + 4*f, p);
        }
        #pragma unroll
        for (int i = 0; i < 4; i++){
            int row = r + 32*i;
            cp16(smem_u32(Bs + row*SPAD + 4*f), W + (size_t)(n0+row)*K + k0 + 4*f, true);
        }
    };

    stage(0, 0); cp_commit();
    stage(1, 1); cp_commit();

    for (int kb = 0; kb < nk; kb++){
        if (kb + 1 < nk) cp_wait1(); else cp_wait0();
        __syncthreads();
        if (kb + 2 < nk){ stage(kb+2, (kb+2)%3); cp_commit(); }
        const uint32_t* Au = (const uint32_t*)(smg + (kb%3)*BUFW);
        const uint32_t* Bu = Au + 128*SPAD;
        #pragma unroll
        for (int k8 = 0; k8 < 4; k8++){
            const int kbp = k8*8 + q4;
            uint32_t a[4][4], b[4][2];
            #pragma unroll
            for (int i=0;i<4;i++){
                int ar = wm + 16*i + g4;
                a[i][0] = Au[ar*SPAD + kbp];
                a[i][1] = Au[(ar+8)*SPAD + kbp];
                a[i][2] = Au[ar*SPAD + kbp + 4];
                a[i][3] = Au[(ar+8)*SPAD + kbp + 4];
            }
            #pragma unroll
            for (int j=0;j<4;j++){
                int br = wn + 8*j + g4;
                b[j][0] = Bu[br*SPAD + kbp];
                b[j][1] = Bu[br*SPAD + kbp + 4];
            }
            #pragma unroll
            for (int i=0;i<4;i++)
                #pragma unroll
                for (int j=0;j<4;j++)
                    mma_tf32(c[i][j], a[i], b[j]);
        }
    }
    // ---- epilogue ----
    #pragma unroll
    for (int i=0;i<4;i++){
        int mrow0 = m0 + wm + 16*i + g4;
        #pragma unroll
        for (int hh=0; hh<2; hh++){
            int m = mrow0 + 8*hh;
            if (m >= M) continue;
            #pragma unroll
            for (int j=0;j<4;j++){
                int n = n0 + wn + 8*j + 2*q4;
                float2 v;
                v.x = c[i][j][hh*2 + 0];
                v.y = c[i][j][hh*2 + 1];
                size_t idx = (size_t)m*N + n;
                if (EPI == 0){
                    *(float2*)(C + idx) = v;
                } else if (EPI == 1){
                    float2 rv = *(const float2*)(residual + idx);
                    v.x += bias[n]   + rv.x;
                    v.y += bias[n+1] + rv.y;
                    *(float2*)(C + idx) = v;
                } else if (EPI == 2){
                    v.x = gelu_f((v.x + bias[n])  *scale[n]   + shift[n]);
                    v.y = gelu_f((v.y + bias[n+1])*scale[n+1] + shift[n+1]);
                    *(float2*)(C + idx) = v;
                } else {
                    v.x = (v.x + bias[n])  *scale[n]   + shift[n];
                    v.y = (v.y + bias[n+1])*scale[n+1] + shift[n+1];
                    *(float2*)(C + idx) = v;
                }
            }
        }
    }
}

// ---------------- tensor-core flash attention (mma.sync) ----------------
#define AST 68
#define ATTN_SMEM (3*64*AST*4)
__global__ void __launch_bounds__(128) attn_tc(const float* __restrict__ qkv,
                                               float* __restrict__ o)
{
    extern __shared__ float sm[];
    float* Qs = sm;                 // [64][AST]
    float* Ks = sm + 64*AST;        // [64][AST], reused as P staging
    float* Vs = sm + 2*64*AST;      // [64][AST]

    const int tid  = threadIdx.x;
    const int lane = tid & 31;
    const int warp = tid >> 5;
    const int g4 = lane >> 2, q4 = lane & 3;
    const int tile = blockIdx.x % 17;
    const int bh   = blockIdx.x / 17;
    const int h = bh % HH, b = bh / HH;
    const int q0 = tile * 64;
    const int qrow = warp * 16;

    const float* qp = qkv + (size_t)b*NN*(3*CC) + h*HD;
    const float* kp = qp + CC;
    const float* vp = qp + 2*CC;

    const int f  = tid & 15;
    const int rr = tid >> 4;

    #pragma unroll
    for (int i=0;i<8;i++){
        int row = rr + 8*i;
        int q = q0 + row;
        bool p = (q < NN);
        const float* src = qp + (size_t)(p ? q : 0)*(3*CC) + 4*f;
        cp16(smem_u32(Qs + row*AST + 4*f), src, p);
    }
    cp_commit();

    float oa[8][4];
    #pragma unroll
    for (int j=0;j<8;j++){ oa[j][0]=0.f; oa[j][1]=0.f; oa[j][2]=0.f; oa[j][3]=0.f; }
    float m0r = -1e30f, m1r = -1e30f, l0r = 0.f, l1r = 0.f;

    for (int kt = 0; kt < 17; kt++){
        #pragma unroll
        for (int i=0;i<8;i++){
            int row = rr + 8*i;
            int kk = kt*64 + row;
            bool p = (kk < NN);
            size_t off = (size_t)(p ? kk : 0)*(3*CC) + 4*f;
            cp16(smem_u32(Ks + row*AST + 4*f), kp + off, p);
            cp16(smem_u32(Vs + row*AST + 4*f), vp + off, p);
        }
        cp_commit();
        cp_wait0();
        __syncthreads();

        const uint32_t* Qu = (const uint32_t*)Qs;
        const uint32_t* Ku = (const uint32_t*)Ks;
        const uint32_t* Vu = (const uint32_t*)Vs;

        float sc[8][4];
        #pragma unroll
        for (int j=0;j<8;j++){ sc[j][0]=0.f; sc[j][1]=0.f; sc[j][2]=0.f; sc[j][3]=0.f; }
        #pragma unroll
        for (int ks=0; ks<8; ks++){
            uint32_t a[4];
            a[0] = Qu[(qrow+g4)*AST   + ks*8+q4];
            a[1] = Qu[(qrow+g4+8)*AST + ks*8+q4];
            a[2] = Qu[(qrow+g4)*AST   + ks*8+q4+4];
            a[3] = Qu[(qrow+g4+8)*AST + ks*8+q4+4];
            #pragma unroll
            for (int j=0;j<8;j++){
                uint32_t bfr[2];
                bfr[0] = Ku[(8*j+g4)*AST + ks*8+q4];
                bfr[1] = Ku[(8*j+g4)*AST + ks*8+q4+4];
                mma_tf32(sc[j], a, bfr);
            }
        }
        #pragma unroll
        for (int j=0;j<8;j++){
            sc[j][0]*=0.125f; sc[j][1]*=0.125f; sc[j][2]*=0.125f; sc[j][3]*=0.125f;
        }
        if (kt == 16){
            #pragma unroll
            for (int j=0;j<8;j++){
                int c0 = kt*64 + 8*j + 2*q4;
                if (c0   >= NN){ sc[j][0] = -1e30f; sc[j][2] = -1e30f; }
                if (c0+1 >= NN){ sc[j][1] = -1e30f; sc[j][3] = -1e30f; }
            }
        }
        float mx0 = -1e30f, mx1 = -1e30f;
        #pragma unroll
        for (int j=0;j<8;j++){
            mx0 = fmaxf(mx0, fmaxf(sc[j][0], sc[j][1]));
            mx1 = fmaxf(mx1, fmaxf(sc[j][2], sc[j][3]));
        }
        mx0 = fmaxf(mx0, __shfl_xor_sync(0xffffffffu, mx0, 1));
        mx0 = fmaxf(mx0, __shfl_xor_sync(0xffffffffu, mx0, 2));
        mx1 = fmaxf(mx1, __shfl_xor_sync(0xffffffffu, mx1, 1));
        mx1 = fmaxf(mx1, __shfl_xor_sync(0xffffffffu, mx1, 2));
        float mn0 = fmaxf(m0r, mx0), mn1 = fmaxf(m1r, mx1);
        float al0 = __expf(m0r - mn0), al1 = __expf(m1r - mn1);
        float s0 = 0.f, s1 = 0.f;
        #pragma unroll
        for (int j=0;j<8;j++){
            float p00 = __expf(sc[j][0]-mn0), p01 = __expf(sc[j][1]-mn0);
            float p10 = __expf(sc[j][2]-mn1), p11 = __expf(sc[j][3]-mn1);
            sc[j][0]=p00; sc[j][1]=p01; sc[j][2]=p10; sc[j][3]=p11;
            s0 += p00 + p01; s1 += p10 + p11;
        }
        s0 += __shfl_xor_sync(0xffffffffu, s0, 1);
        s0 += __shfl_xor_sync(0xffffffffu, s0, 2);
        s1 += __shfl_xor_sync(0xffffffffu, s1, 1);
        s1 += __shfl_xor_sync(0xffffffffu, s1, 2);
        l0r = l0r*al0 + s0; l1r = l1r*al1 + s1;
        m0r = mn0; m1r = mn1;
        #pragma unroll
        for (int j=0;j<8;j++){
            oa[j][0]*=al0; oa[j][1]*=al0; oa[j][2]*=al1; oa[j][3]*=al1;
        }
        __syncthreads();
        float* Ps = Ks + warp*16*AST;
        #pragma unroll
        for (int j=0;j<8;j++){
            Ps[g4*AST     + 8*j + 2*q4]     = sc[j][0];
            Ps[g4*AST     + 8*j + 2*q4 + 1] = sc[j][1];
            Ps[(g4+8)*AST + 8*j + 2*q4]     = sc[j][2];
            Ps[(g4+8)*AST + 8*j + 2*q4 + 1] = sc[j][3];
        }
        __syncwarp();
        const uint32_t* Pu = (const uint32_t*)Ps;
        #pragma unroll
        for (int ks=0; ks<8; ks++){
            uint32_t a[4];
            a[0] = Pu[g4*AST     + ks*8+q4];
            a[1] = Pu[(g4+8)*AST + ks*8+q4];
            a[2] = Pu[g4*AST     + ks*8+q4+4];
            a[3] = Pu[(g4+8)*AST + ks*8+q4+4];
            #pragma unroll
            for (int j=0;j<8;j++){
                uint32_t bfr[2];
                bfr[0] = Vu[(ks*8+q4)*AST   + 8*j+g4];
                bfr[1] = Vu[(ks*8+q4+4)*AST + 8*j+g4];
                mma_tf32(oa[j], a, bfr);
            }
        }
        __syncthreads();
    }
    float inv0 = 1.0f / l0r, inv1 = 1.0f / l1r;
    int qg0 = q0 + qrow + g4, qg1 = qg0 + 8;
    #pragma unroll
    for (int j=0;j<8;j++){
        int d = h*HD + 8*j + 2*q4;
        if (qg0 < NN){
            float2 v; v.x = oa[j][0]*inv0; v.y = oa[j][1]*inv0;
            *(float2*)(o + (size_t)(b*NN + qg0)*CC + d) = v;
        }
        if (qg1 < NN){
            float2 v; v.x = oa[j][2]*inv1; v.y = oa[j][3]*inv1;
            *(float2*)(o + (size_t)(b*NN + qg1)*CC + d) = v;
        }
    }
}

// ---------------- depthwise 3x3 + BN + residual GELU ----------------
__global__ void dwconv_kernel(const float* __restrict__ y, const float* __restrict__ w2,
                              const float* __restrict__ b2, const float* __restrict__ s2,
                              const float* __restrict__ h2b, float* __restrict__ out)
{
    int pix = blockIdx.x;                 // 0..16383
    int b = pix >> 10, p = pix & 1023;
    int sy = p >> 5, sx = p & 31;
    const float* yb = y + (size_t)(b << 10) * HID;
    for (int c = threadIdx.x; c < HID; c += blockDim.x){
        float acc = 0.f;
        #pragma unroll
        for (int dy=0; dy<3; dy++){
            int iy = sy + dy - 1;
            if ((unsigned)iy >= 32u) continue;
            #pragma unroll
            for (int dx=0; dx<3; dx++){
                int ix = sx + dx - 1;
                if ((unsigned)ix >= 32u) continue;
                acc += yb[(size_t)((iy<<5)+ix)*HID + c] * w2[c*9 + dy*3 + dx];
            }
        }
        float v = (acc + b2[c]) * s2[c] + h2b[c];
        out[(size_t)pix*HID + c] = y[(size_t)pix*HID + c] + gelu_f(v);
    }
}

// ---------------- spatial mean partials ----------------
__global__ void mean_part_kernel(const float* __restrict__ y3, float* __restrict__ part)
{
    int b = blockIdx.x, ch = blockIdx.y, c = threadIdx.x;   // 384 threads
    float s = 0.f;
    int base = (b << 10) + ch*64;
    for (int t=0;t<64;t++) s += y3[(size_t)(base + t)*CC + c];
    part[(b*16 + ch)*CC + c] = s;
}

// ---------------- SE gate ----------------
__global__ void se_kernel(const float* __restrict__ part, const float* __restrict__ cw,
                          const float* __restrict__ cb, const float* __restrict__ ew,
                          const float* __restrict__ eb, float* __restrict__ wout)
{
    __shared__ float m[CC];
    __shared__ float cv[96];
    int b = blockIdx.x, t = threadIdx.x;    // 384 threads
    float s = 0.f;
    for (int i=0;i<16;i++) s += part[(b*16 + i)*CC + t];
    m[t] = s * (1.0f/1024.0f);
    __syncthreads();
    if (t < 96){
        float a = cb[t];
        for (int k=0;k<CC;k++) a += m[k]*cw[t*CC + k];
        cv[t] = gelu_f(a);
    }
    __syncthreads();
    float a = eb[t];
    for (int k=0;k<96;k++) a += cv[k]*ew[t*96 + k];
    wout[b*CC + t] = a;
}

// ---------------- final assemble: out = x1 + concat(cls*w, y3) ----------------
__global__ void final_kernel(const float* __restrict__ x1, const float* __restrict__ h2,
                             const float* __restrict__ y3, const float* __restrict__ w,
                             float* __restrict__ out)
{
    size_t i = (size_t)blockIdx.x*256 + threadIdx.x;
    if (i >= (size_t)MTOT*CC) return;
    int c = (int)(i % CC);
    int row = (int)(i / CC);
    int b = row / NN, n = row % NN;
    float add;
    if (n == 0) add = h2[i] * w[b*CC + c];
    else        add = y3[(size_t)((b<<10) + (n-1))*CC + c];
    out[i] = x1[i] + add;
}

// ---------------- launcher ----------------
extern "C" void kernel_launch(void* const* d_in, const int* in_sizes, int n_in,
                              void* d_out, int out_size)
{
    const float* x       = (const float*)d_in[0];
    const float* ln1_g   = (const float*)d_in[1];
    const float* ln1_b   = (const float*)d_in[2];
    const float* qkv_w   = (const float*)d_in[3];
    const float* proj_w  = (const float*)d_in[4];
    const float* proj_b  = (const float*)d_in[5];
    const float* ln2_g   = (const float*)d_in[6];
    const float* ln2_b   = (const float*)d_in[7];
    const float* conv1_w = (const float*)d_in[8];
    const float* conv1_b = (const float*)d_in[9];
    const float* conv2_w = (const float*)d_in[10];
    const float* conv2_b = (const float*)d_in[11];
    const float* conv3_w = (const float*)d_in[12];
    const float* conv3_b = (const float*)d_in[13];
    const float* bn1_s   = (const float*)d_in[14];
    const float* bn1_b   = (const float*)d_in[15];
    const float* bn2_s   = (const float*)d_in[16];
    const float* bn2_b   = (const float*)d_in[17];
    const float* bn3_s   = (const float*)d_in[18];
    const float* bn3_b   = (const float*)d_in[19];
    const float* comp_w  = (const float*)d_in[20];
    const float* comp_b  = (const float*)d_in[21];
    const float* exc_w   = (const float*)d_in[22];
    const float* exc_b   = (const float*)d_in[23];
    float* out = (float*)d_out;

    static bool init = false;
    static float *p_h, *p_qkv, *p_o, *p_x1, *p_h2, *p_y, *p_y2, *p_y3, *p_part, *p_w;
    if (!init){
        cudaGetSymbolAddress((void**)&p_h,    g_h);
        cudaGetSymbolAddress((void**)&p_qkv,  g_qkv);
        cudaGetSymbolAddress((void**)&p_o,    g_o);
        cudaGetSymbolAddress((void**)&p_x1,   g_x1);
        cudaGetSymbolAddress((void**)&p_h2,   g_h2);
        cudaGetSymbolAddress((void**)&p_y,    g_y);
        cudaGetSymbolAddress((void**)&p_y2,   g_y2);
        cudaGetSymbolAddress((void**)&p_y3,   g_y3);
        cudaGetSymbolAddress((void**)&p_part, g_part);
        cudaGetSymbolAddress((void**)&p_w,    g_w);
        cudaFuncSetAttribute(gemm_tc<0,false>, cudaFuncAttributeMaxDynamicSharedMemorySize, GEMM_SMEM);
        cudaFuncSetAttribute(gemm_tc<1,false>, cudaFuncAttributeMaxDynamicSharedMemorySize, GEMM_SMEM);
        cudaFuncSetAttribute(gemm_tc<2,true>,  cudaFuncAttributeMaxDynamicSharedMemorySize, GEMM_SMEM);
        cudaFuncSetAttribute(gemm_tc<3,false>, cudaFuncAttributeMaxDynamicSharedMemorySize, GEMM_SMEM);
        cudaFuncSetAttribute(attn_tc, cudaFuncAttributeMaxDynamicSharedMemorySize, ATTN_SMEM);
        init = true;
    }

    // 1. LN1
    ln_kernel<<<MTOT, 128>>>(x, ln1_g, ln1_b, p_h);
    // 2. QKV = h @ qkv_w^T
    gemm_tc<0,false><<<dim3(9,129), 256, GEMM_SMEM>>>(p_h, qkv_w, p_qkv, MTOT, 3*CC, CC,
                                                      nullptr, nullptr, nullptr, nullptr);
    // 3. attention -> o
    attn_tc<<<BB*HH*17, 128, ATTN_SMEM>>>(p_qkv, p_o);
    // 4. x1 = x + o @ proj_w^T + proj_b
    gemm_tc<1,false><<<dim3(3,129), 256, GEMM_SMEM>>>(p_o, proj_w, p_x1, MTOT, CC, CC,
                                                      proj_b, nullptr, nullptr, x);
    // 5. LN2
    ln_kernel<<<MTOT, 128>>>(p_x1, ln2_g, ln2_b, p_h2);
    // 6. conv1 (1x1) + BN1 + GELU on tokens only (skip cls row)
    gemm_tc<2,true><<<dim3(12,128), 256, GEMM_SMEM>>>(p_h2, conv1_w, p_y, MTOK, HID, CC,
                                                      conv1_b, bn1_s, bn1_b, nullptr);
    // 7. depthwise 3x3 + BN2, y2 = y + gelu(.)
    dwconv_kernel<<<MTOK, 256>>>(p_y, conv2_w, conv2_b, bn2_s, bn2_b, p_y2);
    // 8. conv3 (1x1) + BN3
    gemm_tc<3,false><<<dim3(3,128), 256, GEMM_SMEM>>>(p_y2, conv3_w, p_y3, MTOK, CC, HID,
                                                      conv3_b, bn3_s, bn3_b, nullptr);
    // 9. spatial mean partials
    mean_part_kernel<<<dim3(16,16), CC>>>(p_y3, p_part);
    // 10. SE gate
    se_kernel<<<BB, CC>>>(p_part, comp_w, comp_b, exc_w, exc_b, p_w);
    // 11. assemble
    final_kernel<<<(MTOT*CC + 255)/256, 256>>>(p_x1, p_h2, p_y3, p_w, out);
}

// round 8
// speedup vs baseline: 2.7658x; 1.0185x over previous
#include <cuda_runtime.h>
#include <cstdint>

// ---------------- problem constants ----------------
#define BB   16
#define NN   1025
#define CC   384
#define HH   6
#define HD   64
#define HID  1536
#define MTOT (BB*NN)      // 16400
#define MTOK (BB*1024)    // 16384

// ---------------- scratch (device globals, no alloc) ----------------
__device__ float g_h    [MTOT*CC];
__device__ float g_qkv  [MTOT*3*CC];
__device__ float g_o    [MTOT*CC];
__device__ float g_x1   [MTOT*CC];
__device__ float g_h2   [MTOT*CC];
__device__ float g_y    [MTOK*HID];
__device__ float g_y2   [MTOK*HID];
__device__ float g_part2[BB*CC];
__device__ float g_w    [BB*CC];

__device__ __forceinline__ float gelu_f(float x){
    return 0.5f * x * (1.0f + erff(x * 0.70710678118654752f));
}

__device__ __forceinline__ void mma_tf32(float* c, const uint32_t* a, const uint32_t* b){
    asm volatile("mma.sync.aligned.m16n8k8.row.col.f32.tf32.tf32.f32 "
        "{%0,%1,%2,%3}, {%4,%5,%6,%7}, {%8,%9}, {%0,%1,%2,%3};"
        : "+f"(c[0]), "+f"(c[1]), "+f"(c[2]), "+f"(c[3])
        : "r"(a[0]), "r"(a[1]), "r"(a[2]), "r"(a[3]), "r"(b[0]), "r"(b[1]));
}

__device__ __forceinline__ uint32_t smem_u32(const void* p){
    return (uint32_t)__cvta_generic_to_shared(p);
}

// 16B async copy; pred==false -> zero-fill
__device__ __forceinline__ void cp16(uint32_t dst, const void* src, bool pred){
    int sz = pred ? 16 : 0;
    asm volatile("cp.async.ca.shared.global [%0], [%1], 16, %2;"
                 :: "r"(dst), "l"(src), "r"(sz));
}
__device__ __forceinline__ void cp_commit(){ asm volatile("cp.async.commit_group;"); }
__device__ __forceinline__ void cp_wait0(){ asm volatile("cp.async.wait_group 0;"); }
__device__ __forceinline__ void cp_wait1(){ asm volatile("cp.async.wait_group 1;"); }

// ---------------- LayerNorm over last dim (C=384) ----------------
__global__ void ln_kernel(const float* __restrict__ x, const float* __restrict__ g,
                          const float* __restrict__ bta, float* __restrict__ out)
{
    __shared__ float red[4];
    __shared__ float bc[2];
    int row = blockIdx.x;
    const float* xr = x + (size_t)row * CC;
    int t = threadIdx.x;                      // 128 threads
    float v0 = xr[t], v1 = xr[t+128], v2 = xr[t+256];
    float s = v0 + v1 + v2;
    #pragma unroll
    for (int o=16;o;o>>=1) s += __shfl_xor_sync(0xffffffffu, s, o);
    if ((t&31)==0) red[t>>5] = s;
    __syncthreads();
    if (t==0) bc[0] = (red[0]+red[1]+red[2]+red[3]) * (1.0f/CC);
    __syncthreads();
    float mu = bc[0];
    float d0=v0-mu, d1=v1-mu, d2=v2-mu;
    float q = d0*d0 + d1*d1 + d2*d2;
    #pragma unroll
    for (int o=16;o;o>>=1) q += __shfl_xor_sync(0xffffffffu, q, o);
    if ((t&31)==0) red[t>>5] = q;
    __syncthreads();
    if (t==0) bc[1] = rsqrtf((red[0]+red[1]+red[2]+red[3]) * (1.0f/CC) + 1e-5f);
    __syncthreads();
    float rs = bc[1];
    float* orow = out + (size_t)row * CC;
    orow[t]     = d0*rs*g[t]     + bta[t];
    orow[t+128] = d1*rs*g[t+128] + bta[t+128];
    orow[t+256] = d2*rs*g[t+256] + bta[t+256];
}

// ---------------- TF32 mma.sync GEMM v3 ----------------
// C[M,N] = A[M,K] @ W[N,K]^T + epilogue.
// 256 threads / 8 warps. CTA tile 128x128, warp tile 64x32, k-block 32.
// EPI: 0 none | 1 residual+bias | 2 bias+BN+GELU | 4 bias+BN + residual into
// remapped output rows + column-sum atomics (conv3 fused tail).
#define SPAD 36
#define BUFW (2*128*SPAD)
#define GEMM_SMEM (3*BUFW*4)

template<int EPI, bool SKIP>
__global__ void __launch_bounds__(256, 2) gemm_tc(
    const float* __restrict__ A, const float* __restrict__ W, float* __restrict__ C,
    int M, int N, int K,
    const float* __restrict__ bias, const float* __restrict__ scale,
    const float* __restrict__ shift, const float* __restrict__ residual,
    float* __restrict__ psum)
{
    extern __shared__ float smg[];
    const int tid  = threadIdx.x;
    const int lane = tid & 31;
    const int warp = tid >> 5;
    const int wm = (warp & 1) * 64;
    const int wn = (warp >> 1) * 32;
    const int m0 = blockIdx.y * 128, n0 = blockIdx.x * 128;
    const int f = tid & 7;
    const int r = tid >> 3;
    const int g4 = lane >> 2;
    const int q4 = lane & 3;
    const int nk = K / 32;

    float c[4][4][4];
    #pragma unroll
    for (int i=0;i<4;i++)
        #pragma unroll
        for (int j=0;j<4;j++)
            #pragma unroll
            for (int e=0;e<4;e++) c[i][j][e] = 0.f;

    auto stage = [&](int kb, int bf){
        float* As = smg + bf*BUFW;
        float* Bs = As + 128*SPAD;
        int k0 = kb * 32;
        #pragma unroll
        for (int i = 0; i < 4; i++){
            int row = r + 32*i;
            int m = m0 + row;
            bool p = (m < M);
            int gr = 0;
            if (p) gr = SKIP ? ((m >> 10)*1025 + (m & 1023) + 1) : m;
            cp16(smem_u32(As + row*SPAD + 4*f), A + (size_t)gr*K + k0 + 4*f, p);
        }
        #pragma unroll
        for (int i = 0; i < 4; i++){
            int row = r + 32*i;
            cp16(smem_u32(Bs + row*SPAD + 4*f), W + (size_t)(n0+row)*K + k0 + 4*f, true);
        }
    };

    stage(0, 0); cp_commit();
    stage(1, 1); cp_commit();

    for (int kb = 0; kb < nk; kb++){
        if (kb + 1 < nk) cp_wait1(); else cp_wait0();
        __syncthreads();
        if (kb + 2 < nk){ stage(kb+2, (kb+2)%3); cp_commit(); }
        const uint32_t* Au = (const uint32_t*)(smg + (kb%3)*BUFW);
        const uint32_t* Bu = Au + 128*SPAD;
        #pragma unroll
        for (int k8 = 0; k8 < 4; k8++){
            const int kbp = k8*8 + q4;
            uint32_t a[4][4], b[4][2];
            #pragma unroll
            for (int i=0;i<4;i++){
                int ar = wm + 16*i + g4;
                a[i][0] = Au[ar*SPAD + kbp];
                a[i][1] = Au[(ar+8)*SPAD + kbp];
                a[i][2] = Au[ar*SPAD + kbp + 4];
                a[i][3] = Au[(ar+8)*SPAD + kbp + 4];
            }
            #pragma unroll
            for (int j=0;j<4;j++){
                int br = wn + 8*j + g4;
                b[j][0] = Bu[br*SPAD + kbp];
                b[j][1] = Bu[br*SPAD + kbp + 4];
            }
            #pragma unroll
            for (int i=0;i<4;i++)
                #pragma unroll
                for (int j=0;j<4;j++)
                    mma_tf32(c[i][j], a[i], b[j]);
        }
    }
    // ---- epilogue ----
    if (EPI == 4){
        // conv3 fused tail: BN + residual into remapped out rows + column sums
        const int bidx = m0 >> 10;
        float colsum[8];
        #pragma unroll
        for (int e=0;e<8;e++) colsum[e] = 0.f;
        #pragma unroll
        for (int i=0;i<4;i++){
            #pragma unroll
            for (int hh=0; hh<2; hh++){
                int m = m0 + wm + 16*i + g4 + 8*hh;
                size_t orow = (size_t)((m >> 10)*1025 + (m & 1023) + 1);
                #pragma unroll
                for (int j=0;j<4;j++){
                    int n = n0 + wn + 8*j + 2*q4;
                    float vx = (c[i][j][hh*2+0] + bias[n])  *scale[n]   + shift[n];
                    float vy = (c[i][j][hh*2+1] + bias[n+1])*scale[n+1] + shift[n+1];
                    colsum[2*j]   += vx;
                    colsum[2*j+1] += vy;
                    float2 rv = *(const float2*)(residual + orow*N + n);
                    float2 ov; ov.x = vx + rv.x; ov.y = vy + rv.y;
                    *(float2*)(C + orow*N + n) = ov;
                }
            }
        }
        #pragma unroll
        for (int e=0;e<8;e++){
            float v = colsum[e];
            v += __shfl_xor_sync(0xffffffffu, v, 4);
            v += __shfl_xor_sync(0xffffffffu, v, 8);
            v += __shfl_xor_sync(0xffffffffu, v, 16);
            if ((lane >> 2) == 0){
                int n = n0 + wn + 8*(e>>1) + 2*(lane&3) + (e&1);
                atomicAdd(&psum[bidx*CC + n], v);
            }
        }
        return;
    }
    #pragma unroll
    for (int i=0;i<4;i++){
        int mrow0 = m0 + wm + 16*i + g4;
        #pragma unroll
        for (int hh=0; hh<2; hh++){
            int m = mrow0 + 8*hh;
            if (m >= M) continue;
            #pragma unroll
            for (int j=0;j<4;j++){
                int n = n0 + wn + 8*j + 2*q4;
                float2 v;
                v.x = c[i][j][hh*2 + 0];
                v.y = c[i][j][hh*2 + 1];
                size_t idx = (size_t)m*N + n;
                if (EPI == 0){
                    *(float2*)(C + idx) = v;
                } else if (EPI == 1){
                    float2 rv = *(const float2*)(residual + idx);
                    v.x += bias[n]   + rv.x;
                    v.y += bias[n+1] + rv.y;
                    *(float2*)(C + idx) = v;
                } else if (EPI == 2){
                    v.x = gelu_f((v.x + bias[n])  *scale[n]   + shift[n]);
                    v.y = gelu_f((v.y + bias[n+1])*scale[n+1] + shift[n+1]);
                    *(float2*)(C + idx) = v;
                }
            }
        }
    }
}

// ---------------- tensor-core flash attention v2 ----------------
// 256 threads / 8 warps; CTA covers 128 q rows sharing each K/V tile.
// grid = (B*H) * 9 pairs. Warp w owns q rows [warp*16, warp*16+16).
#define AST 68
#define ATTN_SMEM ((128+64+64+128)*AST*4)
__global__ void __launch_bounds__(256) attn_tc(const float* __restrict__ qkv,
                                               float* __restrict__ o)
{
    extern __shared__ float sm[];
    float* Qs = sm;                     // [128][AST]
    float* Ks = Qs + 128*AST;           // [64][AST]
    float* Vs = Ks + 64*AST;            // [64][AST]
    float* Pa = Vs + 64*AST;            // [128][AST] P staging (per-warp slices)

    const int tid  = threadIdx.x;
    const int lane = tid & 31;
    const int warp = tid >> 5;
    const int g4 = lane >> 2, q4 = lane & 3;
    const int pair = blockIdx.x % 9;
    const int bh   = blockIdx.x / 9;
    const int h = bh % HH, b = bh / HH;
    const int q0 = pair * 128;
    const int qrow = warp * 16;

    const float* qp = qkv + (size_t)b*NN*(3*CC) + h*HD;
    const float* kp = qp + CC;
    const float* vp = qp + 2*CC;

    const int f  = tid & 15;
    const int rr = tid >> 4;            // 0..15

    // stage Q (128 rows, once)
    #pragma unroll
    for (int i=0;i<8;i++){
        int row = rr + 16*i;
        int q = q0 + row;
        bool p = (q < NN);
        const float* src = qp + (size_t)(p ? q : 0)*(3*CC) + 4*f;
        cp16(smem_u32(Qs + row*AST + 4*f), src, p);
    }
    cp_commit();

    float oa[8][4];
    #pragma unroll
    for (int j=0;j<8;j++){ oa[j][0]=0.f; oa[j][1]=0.f; oa[j][2]=0.f; oa[j][3]=0.f; }
    float m0r = -1e30f, m1r = -1e30f, l0r = 0.f, l1r = 0.f;

    for (int kt = 0; kt < 17; kt++){
        // stage K and V tiles (64 rows)
        #pragma unroll
        for (int i=0;i<4;i++){
            int row = rr + 16*i;
            int kk = kt*64 + row;
            bool p = (kk < NN);
            size_t off = (size_t)(p ? kk : 0)*(3*CC) + 4*f;
            cp16(smem_u32(Ks + row*AST + 4*f), kp + off, p);
            cp16(smem_u32(Vs + row*AST + 4*f), vp + off, p);
        }
        cp_commit();
        cp_wait0();
        __syncthreads();

        const uint32_t* Qu = (const uint32_t*)Qs;
        const uint32_t* Ku = (const uint32_t*)Ks;
        const uint32_t* Vu = (const uint32_t*)Vs;

        // ---- S = Q K^T ----
        float sc[8][4];
        #pragma unroll
        for (int j=0;j<8;j++){ sc[j][0]=0.f; sc[j][1]=0.f; sc[j][2]=0.f; sc[j][3]=0.f; }
        #pragma unroll
        for (int ks=0; ks<8; ks++){
            uint32_t a[4];
            a[0] = Qu[(qrow+g4)*AST   + ks*8+q4];
            a[1] = Qu[(qrow+g4+8)*AST + ks*8+q4];
            a[2] = Qu[(qrow+g4)*AST   + ks*8+q4+4];
            a[3] = Qu[(qrow+g4+8)*AST + ks*8+q4+4];
            #pragma unroll
            for (int j=0;j<8;j++){
                uint32_t bfr[2];
                bfr[0] = Ku[(8*j+g4)*AST + ks*8+q4];
                bfr[1] = Ku[(8*j+g4)*AST + ks*8+q4+4];
                mma_tf32(sc[j], a, bfr);
            }
        }
        #pragma unroll
        for (int j=0;j<8;j++){
            sc[j][0]*=0.125f; sc[j][1]*=0.125f; sc[j][2]*=0.125f; sc[j][3]*=0.125f;
        }
        if (kt == 16){
            #pragma unroll
            for (int j=0;j<8;j++){
                int c0 = kt*64 + 8*j + 2*q4;
                if (c0   >= NN){ sc[j][0] = -1e30f; sc[j][2] = -1e30f; }
                if (c0+1 >= NN){ sc[j][1] = -1e30f; sc[j][3] = -1e30f; }
            }
        }
        // ---- online softmax ----
        float mx0 = -1e30f, mx1 = -1e30f;
        #pragma unroll
        for (int j=0;j<8;j++){
            mx0 = fmaxf(mx0, fmaxf(sc[j][0], sc[j][1]));
            mx1 = fmaxf(mx1, fmaxf(sc[j][2], sc[j][3]));
        }
        mx0 = fmaxf(mx0, __shfl_xor_sync(0xffffffffu, mx0, 1));
        mx0 = fmaxf(mx0, __shfl_xor_sync(0xffffffffu, mx0, 2));
        mx1 = fmaxf(mx1, __shfl_xor_sync(0xffffffffu, mx1, 1));
        mx1 = fmaxf(mx1, __shfl_xor_sync(0xffffffffu, mx1, 2));
        float mn0 = fmaxf(m0r, mx0), mn1 = fmaxf(m1r, mx1);
        float al0 = __expf(m0r - mn0), al1 = __expf(m1r - mn1);
        float s0 = 0.f, s1 = 0.f;
        #pragma unroll
        for (int j=0;j<8;j++){
            float p00 = __expf(sc[j][0]-mn0), p01 = __expf(sc[j][1]-mn0);
            float p10 = __expf(sc[j][2]-mn1), p11 = __expf(sc[j][3]-mn1);
            sc[j][0]=p00; sc[j][1]=p01; sc[j][2]=p10; sc[j][3]=p11;
            s0 += p00 + p01; s1 += p10 + p11;
        }
        s0 += __shfl_xor_sync(0xffffffffu, s0, 1);
        s0 += __shfl_xor_sync(0xffffffffu, s0, 2);
        s1 += __shfl_xor_sync(0xffffffffu, s1, 1);
        s1 += __shfl_xor_sync(0xffffffffu, s1, 2);
        l0r = l0r*al0 + s0; l1r = l1r*al1 + s1;
        m0r = mn0; m1r = mn1;
        #pragma unroll
        for (int j=0;j<8;j++){
            oa[j][0]*=al0; oa[j][1]*=al0; oa[j][2]*=al1; oa[j][3]*=al1;
        }
        // ---- stage P (per-warp slice) ----
        float* Ps = Pa + warp*16*AST;
        #pragma unroll
        for (int j=0;j<8;j++){
            Ps[g4*AST     + 8*j + 2*q4]     = sc[j][0];
            Ps[g4*AST     + 8*j + 2*q4 + 1] = sc[j][1];
            Ps[(g4+8)*AST + 8*j + 2*q4]     = sc[j][2];
            Ps[(g4+8)*AST + 8*j + 2*q4 + 1] = sc[j][3];
        }
        __syncwarp();
        const uint32_t* Pu = (const uint32_t*)Ps;
        // ---- O += P V ----
        #pragma unroll
        for (int ks=0; ks<8; ks++){
            uint32_t a[4];
            a[0] = Pu[g4*AST     + ks*8+q4];
            a[1] = Pu[(g4+8)*AST + ks*8+q4];
            a[2] = Pu[g4*AST     + ks*8+q4+4];
            a[3] = Pu[(g4+8)*AST + ks*8+q4+4];
            #pragma unroll
            for (int j=0;j<8;j++){
                uint32_t bfr[2];
                bfr[0] = Vu[(ks*8+q4)*AST   + 8*j+g4];
                bfr[1] = Vu[(ks*8+q4+4)*AST + 8*j+g4];
                mma_tf32(oa[j], a, bfr);
            }
        }
        __syncthreads();
    }
    float inv0 = 1.0f / l0r, inv1 = 1.0f / l1r;
    int qg0 = q0 + qrow + g4, qg1 = qg0 + 8;
    #pragma unroll
    for (int j=0;j<8;j++){
        int d = h*HD + 8*j + 2*q4;
        if (qg0 < NN){
            float2 v; v.x = oa[j][0]*inv0; v.y = oa[j][1]*inv0;
            *(float2*)(o + (size_t)(b*NN + qg0)*CC + d) = v;
        }
        if (qg1 < NN){
            float2 v; v.x = oa[j][2]*inv1; v.y = oa[j][3]*inv1;
            *(float2*)(o + (size_t)(b*NN + qg1)*CC + d) = v;
        }
    }
}

// ---------------- depthwise 3x3 + BN + residual GELU ----------------
__global__ void dwconv_kernel(const float* __restrict__ y, const float* __restrict__ w2,
                              const float* __restrict__ b2, const float* __restrict__ s2,
                              const float* __restrict__ h2b, float* __restrict__ out)
{
    int pix = blockIdx.x;                 // 0..16383
    int b = pix >> 10, p = pix & 1023;
    int sy = p >> 5, sx = p & 31;
    const float* yb = y + (size_t)(b << 10) * HID;
    for (int c = threadIdx.x; c < HID; c += blockDim.x){
        float acc = 0.f;
        #pragma unroll
        for (int dy=0; dy<3; dy++){
            int iy = sy + dy - 1;
            if ((unsigned)iy >= 32u) continue;
            #pragma unroll
            for (int dx=0; dx<3; dx++){
                int ix = sx + dx - 1;
                if ((unsigned)ix >= 32u) continue;
                acc += yb[(size_t)((iy<<5)+ix)*HID + c] * w2[c*9 + dy*3 + dx];
            }
        }
        float v = (acc + b2[c]) * s2[c] + h2b[c];
        out[(size_t)pix*HID + c] = y[(size_t)pix*HID + c] + gelu_f(v);
    }
}

// ---------------- zero the column-sum buffer ----------------
__global__ void zero_part_kernel(float* __restrict__ p){
    int i = blockIdx.x*256 + threadIdx.x;
    if (i < BB*CC) p[i] = 0.f;
}

// ---------------- SE gate (reads fused column sums) ----------------
__global__ void se_kernel(const float* __restrict__ part, const float* __restrict__ cw,
                          const float* __restrict__ cb, const float* __restrict__ ew,
                          const float* __restrict__ eb, float* __restrict__ wout)
{
    __shared__ float m[CC];
    __shared__ float cv[96];
    int b = blockIdx.x, t = threadIdx.x;    // 384 threads
    m[t] = part[b*CC + t] * (1.0f/1024.0f);
    __syncthreads();
    if (t < 96){
        float a = cb[t];
        for (int k=0;k<CC;k++) a += m[k]*cw[t*CC + k];
        cv[t] = gelu_f(a);
    }
    __syncthreads();
    float a = eb[t];
    for (int k=0;k<96;k++) a += cv[k]*ew[t*96 + k];
    wout[b*CC + t] = a;
}

// ---------------- cls rows: out[b,0,:] = x1 + h2*w ----------------
__global__ void final_cls_kernel(const float* __restrict__ x1, const float* __restrict__ h2,
                                 const float* __restrict__ w, float* __restrict__ out)
{
    int b = blockIdx.x, t = threadIdx.x;    // 384 threads
    size_t i = (size_t)b*NN*CC + t;
    out[i] = x1[i] + h2[i] * w[b*CC + t];
}

// ---------------- launcher ----------------
extern "C" void kernel_launch(void* const* d_in, const int* in_sizes, int n_in,
                              void* d_out, int out_size)
{
    const float* x       = (const float*)d_in[0];
    const float* ln1_g   = (const float*)d_in[1];
    const float* ln1_b   = (const float*)d_in[2];
    const float* qkv_w   = (const float*)d_in[3];
    const float* proj_w  = (const float*)d_in[4];
    const float* proj_b  = (const float*)d_in[5];
    const float* ln2_g   = (const float*)d_in[6];
    const float* ln2_b   = (const float*)d_in[7];
    const float* conv1_w = (const float*)d_in[8];
    const float* conv1_b = (const float*)d_in[9];
    const float* conv2_w = (const float*)d_in[10];
    const float* conv2_b = (const float*)d_in[11];
    const float* conv3_w = (const float*)d_in[12];
    const float* conv3_b = (const float*)d_in[13];
    const float* bn1_s   = (const float*)d_in[14];
    const float* bn1_b   = (const float*)d_in[15];
    const float* bn2_s   = (const float*)d_in[16];
    const float* bn2_b   = (const float*)d_in[17];
    const float* bn3_s   = (const float*)d_in[18];
    const float* bn3_b   = (const float*)d_in[19];
    const float* comp_w  = (const float*)d_in[20];
    const float* comp_b  = (const float*)d_in[21];
    const float* exc_w   = (const float*)d_in[22];
    const float* exc_b   = (const float*)d_in[23];
    float* out = (float*)d_out;

    static bool init = false;
    static float *p_h, *p_qkv, *p_o, *p_x1, *p_h2, *p_y, *p_y2, *p_part2, *p_w;
    if (!init){
        cudaGetSymbolAddress((void**)&p_h,     g_h);
        cudaGetSymbolAddress((void**)&p_qkv,   g_qkv);
        cudaGetSymbolAddress((void**)&p_o,     g_o);
        cudaGetSymbolAddress((void**)&p_x1,    g_x1);
        cudaGetSymbolAddress((void**)&p_h2,    g_h2);
        cudaGetSymbolAddress((void**)&p_y,     g_y);
        cudaGetSymbolAddress((void**)&p_y2,    g_y2);
        cudaGetSymbolAddress((void**)&p_part2, g_part2);
        cudaGetSymbolAddress((void**)&p_w,     g_w);
        cudaFuncSetAttribute(gemm_tc<0,false>, cudaFuncAttributeMaxDynamicSharedMemorySize, GEMM_SMEM);
        cudaFuncSetAttribute(gemm_tc<1,false>, cudaFuncAttributeMaxDynamicSharedMemorySize, GEMM_SMEM);
        cudaFuncSetAttribute(gemm_tc<2,true>,  cudaFuncAttributeMaxDynamicSharedMemorySize, GEMM_SMEM);
        cudaFuncSetAttribute(gemm_tc<4,false>, cudaFuncAttributeMaxDynamicSharedMemorySize, GEMM_SMEM);
        cudaFuncSetAttribute(attn_tc, cudaFuncAttributeMaxDynamicSharedMemorySize, ATTN_SMEM);
        init = true;
    }

    // 1. LN1
    ln_kernel<<<MTOT, 128>>>(x, ln1_g, ln1_b, p_h);
    // 2. QKV = h @ qkv_w^T
    gemm_tc<0,false><<<dim3(9,129), 256, GEMM_SMEM>>>(p_h, qkv_w, p_qkv, MTOT, 3*CC, CC,
                                                      nullptr, nullptr, nullptr, nullptr, nullptr);
    // 3. attention -> o (paired q-tiles)
    attn_tc<<<BB*HH*9, 256, ATTN_SMEM>>>(p_qkv, p_o);
    // 4. x1 = x + o @ proj_w^T + proj_b
    gemm_tc<1,false><<<dim3(3,129), 256, GEMM_SMEM>>>(p_o, proj_w, p_x1, MTOT, CC, CC,
                                                      proj_b, nullptr, nullptr, x, nullptr);
    // 5. LN2
    ln_kernel<<<MTOT, 128>>>(p_x1, ln2_g, ln2_b, p_h2);
    // 6. conv1 (1x1) + BN1 + GELU on tokens only (skip cls row)
    gemm_tc<2,true><<<dim3(12,128), 256, GEMM_SMEM>>>(p_h2, conv1_w, p_y, MTOK, HID, CC,
                                                      conv1_b, bn1_s, bn1_b, nullptr, nullptr);
    // 7. depthwise 3x3 + BN2, y2 = y + gelu(.)
    dwconv_kernel<<<MTOK, 256>>>(p_y, conv2_w, conv2_b, bn2_s, bn2_b, p_y2);
    // 7.5 zero column sums
    zero_part_kernel<<<(BB*CC + 255)/256, 256>>>(p_part2);
    // 8. conv3 (1x1) + BN3 fused: writes token rows of OUT (+x1 residual) and column sums
    gemm_tc<4,false><<<dim3(3,128), 256, GEMM_SMEM>>>(p_y2, conv3_w, out, MTOK, CC, HID,
                                                      conv3_b, bn3_s, bn3_b, p_x1, p_part2);
    // 9. SE gate
    se_kernel<<<BB, CC>>>(p_part2, comp_w, comp_b, exc_w, exc_b, p_w);
    // 10. cls rows
    final_cls_kernel<<<BB, CC>>>(p_x1, p_h2, p_w, out);
}

// round 9
// speedup vs baseline: 3.8761x; 1.4014x over previous
#include <cuda_runtime.h>
#include <cuda_fp16.h>
#include <cstdint>

// ---------------- problem constants ----------------
#define BB   16
#define NN   1025
#define CC   384
#define HH   6
#define HD   64
#define HID  1536
#define MTOT (BB*NN)      // 16400
#define MTOK (BB*1024)    // 16384

// ---------------- scratch (device globals, no alloc) ----------------
__device__ __half g_hh  [MTOT*CC];
__device__ __half g_qkvh[MTOT*3*CC];
__device__ __half g_oh  [MTOT*CC];
__device__ float  g_x1  [MTOT*CC];
__device__ __half g_h2h [MTOT*CC];
__device__ __half g_yh  [(size_t)MTOK*HID];
__device__ __half g_y2h [(size_t)MTOK*HID];
__device__ float  g_part2[BB*CC];
__device__ float  g_w   [BB*CC];
__device__ __half g_wq  [3*CC*CC];
__device__ __half g_wp  [CC*CC];
__device__ __half g_w1  [HID*CC];
__device__ __half g_w3  [CC*HID];

__device__ __forceinline__ float gelu_f(float x){
    return 0.5f * x * (1.0f + erff(x * 0.70710678118654752f));
}

__device__ __forceinline__ void mma_f16(float* c, const uint32_t* a, const uint32_t* b){
    asm volatile("mma.sync.aligned.m16n8k16.row.col.f32.f16.f16.f32 "
        "{%0,%1,%2,%3}, {%4,%5,%6,%7}, {%8,%9}, {%0,%1,%2,%3};"
        : "+f"(c[0]), "+f"(c[1]), "+f"(c[2]), "+f"(c[3])
        : "r"(a[0]), "r"(a[1]), "r"(a[2]), "r"(a[3]), "r"(b[0]), "r"(b[1]));
}

__device__ __forceinline__ uint32_t smem_u32(const void* p){
    return (uint32_t)__cvta_generic_to_shared(p);
}
__device__ __forceinline__ void cp16(uint32_t dst, const void* src, bool pred){
    int sz = pred ? 16 : 0;
    asm volatile("cp.async.ca.shared.global [%0], [%1], 16, %2;"
                 :: "r"(dst), "l"(src), "r"(sz));
}
__device__ __forceinline__ void cp_commit(){ asm volatile("cp.async.commit_group;"); }
__device__ __forceinline__ void cp_wait0(){ asm volatile("cp.async.wait_group 0;"); }
__device__ __forceinline__ void cp_wait1(){ asm volatile("cp.async.wait_group 1;"); }

__device__ __forceinline__ uint32_t pack_h2(float x, float y){
    __half2 h = __floats2half2_rn(x, y);
    return *reinterpret_cast<uint32_t*>(&h);
}

// ---------------- fp32 -> fp16 convert ----------------
__global__ void f2h_kernel(const float* __restrict__ s, __half* __restrict__ d, int n){
    int i = blockIdx.x*256 + threadIdx.x;
    int stride = gridDim.x*256;
    for (; i < n; i += stride) d[i] = __float2half(s[i]);
}

// ---------------- LayerNorm over last dim (C=384), fp16 out ----------------
__global__ void ln_kernel(const float* __restrict__ x, const float* __restrict__ g,
                          const float* __restrict__ bta, __half* __restrict__ out)
{
    __shared__ float red[4];
    __shared__ float bc[2];
    int row = blockIdx.x;
    const float* xr = x + (size_t)row * CC;
    int t = threadIdx.x;                      // 128 threads
    float v0 = xr[t], v1 = xr[t+128], v2 = xr[t+256];
    float s = v0 + v1 + v2;
    #pragma unroll
    for (int o=16;o;o>>=1) s += __shfl_xor_sync(0xffffffffu, s, o);
    if ((t&31)==0) red[t>>5] = s;
    __syncthreads();
    if (t==0) bc[0] = (red[0]+red[1]+red[2]+red[3]) * (1.0f/CC);
    __syncthreads();
    float mu = bc[0];
    float d0=v0-mu, d1=v1-mu, d2=v2-mu;
    float q = d0*d0 + d1*d1 + d2*d2;
    #pragma unroll
    for (int o=16;o;o>>=1) q += __shfl_xor_sync(0xffffffffu, q, o);
    if ((t&31)==0) red[t>>5] = q;
    __syncthreads();
    if (t==0) bc[1] = rsqrtf((red[0]+red[1]+red[2]+red[3]) * (1.0f/CC) + 1e-5f);
    __syncthreads();
    float rs = bc[1];
    __half* orow = out + (size_t)row * CC;
    orow[t]     = __float2half(d0*rs*g[t]     + bta[t]);
    orow[t+128] = __float2half(d1*rs*g[t+128] + bta[t+128]);
    orow[t+256] = __float2half(d2*rs*g[t+256] + bta[t+256]);
}

// ---------------- fp16 mma.sync GEMM ----------------
// C[M,N] = A[M,K] @ W[N,K]^T + epilogue. A, W fp16.
// 256 threads / 8 warps. CTA tile 128x128, warp tile 64x32, k-block 64.
// EPI: 0 -> fp16 out | 1 -> fp32 resid+bias | 2 -> fp16 bias+BN+GELU |
//      4 -> fp32 bias+BN + resid into remapped out rows + column-sum atomics.
#define SPAD 36                     // u32 per row (64 halfs + pad)
#define BUFW (2*128*SPAD)
#define GEMM_SMEM (3*BUFW*4)

template<int EPI, bool SKIP>
__global__ void __launch_bounds__(256, 2) gemm_h(
    const __half* __restrict__ A, const __half* __restrict__ W, void* __restrict__ Cv,
    int M, int N, int K,
    const float* __restrict__ bias, const float* __restrict__ scale,
    const float* __restrict__ shift, const float* __restrict__ residual,
    float* __restrict__ psum)
{
    extern __shared__ uint32_t smg[];
    const int tid  = threadIdx.x;
    const int lane = tid & 31;
    const int warp = tid >> 5;
    const int wm = (warp & 1) * 64;
    const int wn = (warp >> 1) * 32;
    const int m0 = blockIdx.y * 128, n0 = blockIdx.x * 128;
    const int f = tid & 7;
    const int r = tid >> 3;
    const int g4 = lane >> 2;
    const int q4 = lane & 3;
    const int nk = K / 64;

    float c[4][4][4];
    #pragma unroll
    for (int i=0;i<4;i++)
        #pragma unroll
        for (int j=0;j<4;j++)
            #pragma unroll
            for (int e=0;e<4;e++) c[i][j][e] = 0.f;

    auto stage = [&](int kb, int bf){
        uint32_t* As = smg + bf*BUFW;
        uint32_t* Bs = As + 128*SPAD;
        int k0 = kb * 64 + f * 8;       // in halfs
        #pragma unroll
        for (int i = 0; i < 4; i++){
            int row = r + 32*i;
            int m = m0 + row;
            bool p = (m < M);
            int gr = 0;
            if (p) gr = SKIP ? ((m >> 10)*1025 + (m & 1023) + 1) : m;
            cp16(smem_u32(As + row*SPAD + 4*f), A + (size_t)gr*K + k0, p);
        }
        #pragma unroll
        for (int i = 0; i < 4; i++){
            int row = r + 32*i;
            cp16(smem_u32(Bs + row*SPAD + 4*f), W + (size_t)(n0+row)*K + k0, true);
        }
    };

    stage(0, 0); cp_commit();
    if (nk > 1){ stage(1, 1); cp_commit(); }

    for (int kb = 0; kb < nk; kb++){
        if (kb + 1 < nk) cp_wait1(); else cp_wait0();
        __syncthreads();
        if (kb + 2 < nk){ stage(kb+2, (kb+2)%3); cp_commit(); }
        const uint32_t* Au = smg + (kb%3)*BUFW;
        const uint32_t* Bu = Au + 128*SPAD;
        #pragma unroll
        for (int ks = 0; ks < 4; ks++){
            const int kbp = ks*8 + q4;
            uint32_t a[4][4], b[4][2];
            #pragma unroll
            for (int i=0;i<4;i++){
                int ar = wm + 16*i + g4;
                a[i][0] = Au[ar*SPAD + kbp];
                a[i][1] = Au[(ar+8)*SPAD + kbp];
                a[i][2] = Au[ar*SPAD + kbp + 4];
                a[i][3] = Au[(ar+8)*SPAD + kbp + 4];
            }
            #pragma unroll
            for (int j=0;j<4;j++){
                int br = wn + 8*j + g4;
                b[j][0] = Bu[br*SPAD + kbp];
                b[j][1] = Bu[br*SPAD + kbp + 4];
            }
            #pragma unroll
            for (int i=0;i<4;i++)
                #pragma unroll
                for (int j=0;j<4;j++)
                    mma_f16(c[i][j], a[i], b[j]);
        }
        __syncthreads();
    }
    // ---- epilogue ----
    if (EPI == 4){
        float* C = (float*)Cv;
        const int bidx = m0 >> 10;
        float colsum[8];
        #pragma unroll
        for (int e=0;e<8;e++) colsum[e] = 0.f;
        #pragma unroll
        for (int i=0;i<4;i++){
            #pragma unroll
            for (int hh=0; hh<2; hh++){
                int m = m0 + wm + 16*i + g4 + 8*hh;
                size_t orow = (size_t)((m >> 10)*1025 + (m & 1023) + 1);
                #pragma unroll
                for (int j=0;j<4;j++){
                    int n = n0 + wn + 8*j + 2*q4;
                    float vx = (c[i][j][hh*2+0] + bias[n])  *scale[n]   + shift[n];
                    float vy = (c[i][j][hh*2+1] + bias[n+1])*scale[n+1] + shift[n+1];
                    colsum[2*j]   += vx;
                    colsum[2*j+1] += vy;
                    float2 rv = *(const float2*)(residual + orow*N + n);
                    float2 ov; ov.x = vx + rv.x; ov.y = vy + rv.y;
                    *(float2*)(C + orow*N + n) = ov;
                }
            }
        }
        #pragma unroll
        for (int e=0;e<8;e++){
            float v = colsum[e];
            v += __shfl_xor_sync(0xffffffffu, v, 4);
            v += __shfl_xor_sync(0xffffffffu, v, 8);
            v += __shfl_xor_sync(0xffffffffu, v, 16);
            if ((lane >> 2) == 0){
                int n = n0 + wn + 8*(e>>1) + 2*(lane&3) + (e&1);
                atomicAdd(&psum[bidx*CC + n], v);
            }
        }
        return;
    }
    #pragma unroll
    for (int i=0;i<4;i++){
        int mrow0 = m0 + wm + 16*i + g4;
        #pragma unroll
        for (int hh=0; hh<2; hh++){
            int m = mrow0 + 8*hh;
            if (m >= M) continue;
            #pragma unroll
            for (int j=0;j<4;j++){
                int n = n0 + wn + 8*j + 2*q4;
                float vx = c[i][j][hh*2 + 0];
                float vy = c[i][j][hh*2 + 1];
                size_t idx = (size_t)m*N + n;
                if (EPI == 0){
                    *(uint32_t*)((__half*)Cv + idx) = pack_h2(vx, vy);
                } else if (EPI == 1){
                    float* C = (float*)Cv;
                    float2 rv = *(const float2*)(residual + idx);
                    float2 ov; ov.x = vx + bias[n] + rv.x; ov.y = vy + bias[n+1] + rv.y;
                    *(float2*)(C + idx) = ov;
                } else if (EPI == 2){
                    vx = gelu_f((vx + bias[n])  *scale[n]   + shift[n]);
                    vy = gelu_f((vy + bias[n+1])*scale[n+1] + shift[n+1]);
                    *(uint32_t*)((__half*)Cv + idx) = pack_h2(vx, vy);
                }
            }
        }
    }
}

// ---------------- fp16 tensor-core flash attention ----------------
// 256 threads / 8 warps; 128 q rows per CTA share each 64-key K/V tile.
#define ATTN_SMEM ((128*36 + 64*36 + 64*36 + 128*36)*4)
__global__ void __launch_bounds__(256) attn_h(const __half* __restrict__ qkv,
                                              __half* __restrict__ o)
{
    extern __shared__ uint32_t sm[];
    uint32_t* Qu = sm;                  // [128][36]
    uint32_t* Ku = Qu + 128*36;         // [64][36]
    uint32_t* Vt = Ku + 64*36;          // [64 d][36], kk-pair swizzled
    uint32_t* Pu = Vt + 64*36;          // [128][36]

    const int tid  = threadIdx.x;
    const int lane = tid & 31;
    const int warp = tid >> 5;
    const int g4 = lane >> 2, q4 = lane & 3;
    const int pair = blockIdx.x % 9;
    const int bh   = blockIdx.x / 9;
    const int h = bh % HH, b = bh / HH;
    const int q0 = pair * 128;
    const int qrow = warp * 16;

    const __half* qp = qkv + (size_t)b*NN*(3*CC) + h*HD;
    const __half* kp = qp + CC;
    const __half* vp = qp + 2*CC;

    const int f  = tid & 7;
    const int rg = tid >> 3;            // 0..31

    // stage Q (128 rows)
    #pragma unroll
    for (int i=0;i<4;i++){
        int row = rg + 32*i;
        int q = q0 + row;
        bool p = (q < NN);
        cp16(smem_u32(Qu + row*36 + 4*f), qp + (size_t)(p ? q : 0)*(3*CC) + 8*f, p);
    }
    cp_commit();

    float oa[8][4];
    #pragma unroll
    for (int j=0;j<8;j++){ oa[j][0]=0.f; oa[j][1]=0.f; oa[j][2]=0.f; oa[j][3]=0.f; }
    float m0r = -1e30f, m1r = -1e30f, l0r = 0.f, l1r = 0.f;

    for (int kt = 0; kt < 17; kt++){
        // K tile via cp.async
        #pragma unroll
        for (int i=0;i<2;i++){
            int row = rg + 32*i;
            int kk = kt*64 + row;
            bool p = (kk < NN);
            cp16(smem_u32(Ku + row*36 + 4*f), kp + (size_t)(p ? kk : 0)*(3*CC) + 8*f, p);
        }
        cp_commit();
        // V tile transposed: Vt[d][kk-pair ^ 4*(d>>3)]
        {
            int kk0 = kt*64 + 2*rg;
            uint4 va = make_uint4(0,0,0,0), vb = make_uint4(0,0,0,0);
            if (kk0   < NN) va = *(const uint4*)(vp + (size_t)kk0*(3*CC) + 8*f);
            if (kk0+1 < NN) vb = *(const uint4*)(vp + (size_t)(kk0+1)*(3*CC) + 8*f);
            uint32_t sw = (uint32_t)rg ^ (uint32_t)(4*f);
            uint32_t ua[4] = {va.x, va.y, va.z, va.w};
            uint32_t ub[4] = {vb.x, vb.y, vb.z, vb.w};
            #pragma unroll
            for (int t4=0;t4<4;t4++){
                int d0 = 8*f + 2*t4;
                Vt[d0*36 + sw]     = (ua[t4] & 0xFFFFu)  | (ub[t4] << 16);
                Vt[(d0+1)*36 + sw] = (ua[t4] >> 16)      | (ub[t4] & 0xFFFF0000u);
            }
        }
        cp_wait0();
        __syncthreads();

        // ---- S = Q K^T (fp16 k16) ----
        float sc[8][4];
        #pragma unroll
        for (int j=0;j<8;j++){ sc[j][0]=0.f; sc[j][1]=0.f; sc[j][2]=0.f; sc[j][3]=0.f; }
        #pragma unroll
        for (int ks=0; ks<4; ks++){
            uint32_t a[4];
            a[0] = Qu[(qrow+g4)*36   + ks*8+q4];
            a[1] = Qu[(qrow+g4+8)*36 + ks*8+q4];
            a[2] = Qu[(qrow+g4)*36   + ks*8+q4+4];
            a[3] = Qu[(qrow+g4+8)*36 + ks*8+q4+4];
            #pragma unroll
            for (int j=0;j<8;j++){
                uint32_t bfr[2];
                bfr[0] = Ku[(8*j+g4)*36 + ks*8+q4];
                bfr[1] = Ku[(8*j+g4)*36 + ks*8+q4+4];
                mma_f16(sc[j], a, bfr);
            }
        }
        #pragma unroll
        for (int j=0;j<8;j++){
            sc[j][0]*=0.125f; sc[j][1]*=0.125f; sc[j][2]*=0.125f; sc[j][3]*=0.125f;
        }
        if (kt == 16){
            #pragma unroll
            for (int j=0;j<8;j++){
                int c0 = kt*64 + 8*j + 2*q4;
                if (c0   >= NN){ sc[j][0] = -1e30f; sc[j][2] = -1e30f; }
                if (c0+1 >= NN){ sc[j][1] = -1e30f; sc[j][3] = -1e30f; }
            }
        }
        // ---- online softmax ----
        float mx0 = -1e30f, mx1 = -1e30f;
        #pragma unroll
        for (int j=0;j<8;j++){
            mx0 = fmaxf(mx0, fmaxf(sc[j][0], sc[j][1]));
            mx1 = fmaxf(mx1, fmaxf(sc[j][2], sc[j][3]));
        }
        mx0 = fmaxf(mx0, __shfl_xor_sync(0xffffffffu, mx0, 1));
        mx0 = fmaxf(mx0, __shfl_xor_sync(0xffffffffu, mx0, 2));
        mx1 = fmaxf(mx1, __shfl_xor_sync(0xffffffffu, mx1, 1));
        mx1 = fmaxf(mx1, __shfl_xor_sync(0xffffffffu, mx1, 2));
        float mn0 = fmaxf(m0r, mx0), mn1 = fmaxf(m1r, mx1);
        float al0 = __expf(m0r - mn0), al1 = __expf(m1r - mn1);
        float s0 = 0.f, s1 = 0.f;
        #pragma unroll
        for (int j=0;j<8;j++){
            float p00 = __expf(sc[j][0]-mn0), p01 = __expf(sc[j][1]-mn0);
            float p10 = __expf(sc[j][2]-mn1), p11 = __expf(sc[j][3]-mn1);
            sc[j][0]=p00; sc[j][1]=p01; sc[j][2]=p10; sc[j][3]=p11;
            s0 += p00 + p01; s1 += p10 + p11;
        }
        s0 += __shfl_xor_sync(0xffffffffu, s0, 1);
        s0 += __shfl_xor_sync(0xffffffffu, s0, 2);
        s1 += __shfl_xor_sync(0xffffffffu, s1, 1);
        s1 += __shfl_xor_sync(0xffffffffu, s1, 2);
        l0r = l0r*al0 + s0; l1r = l1r*al1 + s1;
        m0r = mn0; m1r = mn1;
        #pragma unroll
        for (int j=0;j<8;j++){
            oa[j][0]*=al0; oa[j][1]*=al0; oa[j][2]*=al1; oa[j][3]*=al1;
        }
        // ---- stage P (fp16, per-warp rows) ----
        #pragma unroll
        for (int j=0;j<8;j++){
            Pu[(qrow+g4)*36   + 4*j+q4] = pack_h2(sc[j][0], sc[j][1]);
            Pu[(qrow+g4+8)*36 + 4*j+q4] = pack_h2(sc[j][2], sc[j][3]);
        }
        __syncwarp();
        // ---- O += P V ----
        #pragma unroll
        for (int ks=0; ks<4; ks++){
            uint32_t a[4];
            a[0] = Pu[(qrow+g4)*36   + ks*8+q4];
            a[1] = Pu[(qrow+g4+8)*36 + ks*8+q4];
            a[2] = Pu[(qrow+g4)*36   + ks*8+q4+4];
            a[3] = Pu[(qrow+g4+8)*36 + ks*8+q4+4];
            #pragma unroll
            for (int j=0;j<8;j++){
                uint32_t bfr[2];
                int sw0 = (ks*8+q4)   ^ (4*j);
                int sw1 = (ks*8+q4+4) ^ (4*j);
                bfr[0] = Vt[(8*j+g4)*36 + sw0];
                bfr[1] = Vt[(8*j+g4)*36 + sw1];
                mma_f16(oa[j], a, bfr);
            }
        }
        __syncthreads();
    }
    float inv0 = 1.0f / l0r, inv1 = 1.0f / l1r;
    int qg0 = q0 + qrow + g4, qg1 = qg0 + 8;
    #pragma unroll
    for (int j=0;j<8;j++){
        int d = h*HD + 8*j + 2*q4;
        if (qg0 < NN)
            *(uint32_t*)(o + (size_t)(b*NN + qg0)*CC + d) = pack_h2(oa[j][0]*inv0, oa[j][1]*inv0);
        if (qg1 < NN)
            *(uint32_t*)(o + (size_t)(b*NN + qg1)*CC + d) = pack_h2(oa[j][2]*inv1, oa[j][3]*inv1);
    }
}

// ---------------- depthwise 3x3 + BN + residual GELU (fp16 in/out) ----------------
__global__ void dwconv_kernel(const __half2* __restrict__ y, const float* __restrict__ w2,
                              const float* __restrict__ b2, const float* __restrict__ s2,
                              const float* __restrict__ h2b, __half2* __restrict__ out)
{
    int pix = blockIdx.x;                 // 0..16383
    int b = pix >> 10, p = pix & 1023;
    int sy = p >> 5, sx = p & 31;
    const __half2* yb = y + (size_t)(b << 10) * 768;
    for (int c2 = threadIdx.x; c2 < 768; c2 += blockDim.x){
        int c = 2*c2;
        float ax = 0.f, ay = 0.f;
        #pragma unroll
        for (int dy=0; dy<3; dy++){
            int iy = sy + dy - 1;
            if ((unsigned)iy >= 32u) continue;
            #pragma unroll
            for (int dx=0; dx<3; dx++){
                int ix = sx + dx - 1;
                if ((unsigned)ix >= 32u) continue;
                float2 fv = __half22float2(yb[(size_t)((iy<<5)+ix)*768 + c2]);
                ax += fv.x * w2[c*9 + dy*3 + dx];
                ay += fv.y * w2[(c+1)*9 + dy*3 + dx];
            }
        }
        float vx = (ax + b2[c])  *s2[c]   + h2b[c];
        float vy = (ay + b2[c+1])*s2[c+1] + h2b[c+1];
        float2 cf = __half22float2(y[(size_t)pix*768 + c2]);
        out[(size_t)pix*768 + c2] = __floats2half2_rn(cf.x + gelu_f(vx), cf.y + gelu_f(vy));
    }
}

// ---------------- zero the column-sum buffer ----------------
__global__ void zero_part_kernel(float* __restrict__ p){
    int i = blockIdx.x*256 + threadIdx.x;
    if (i < BB*CC) p[i] = 0.f;
}

// ---------------- SE gate ----------------
__global__ void se_kernel(const float* __restrict__ part, const float* __restrict__ cw,
                          const float* __restrict__ cb, const float* __restrict__ ew,
                          const float* __restrict__ eb, float* __restrict__ wout)
{
    __shared__ float m[CC];
    __shared__ float cv[96];
    int b = blockIdx.x, t = threadIdx.x;    // 384 threads
    m[t] = part[b*CC + t] * (1.0f/1024.0f);
    __syncthreads();
    if (t < 96){
        float a = cb[t];
        for (int k=0;k<CC;k++) a += m[k]*cw[t*CC + k];
        cv[t] = gelu_f(a);
    }
    __syncthreads();
    float a = eb[t];
    for (int k=0;k<96;k++) a += cv[k]*ew[t*96 + k];
    wout[b*CC + t] = a;
}

// ---------------- cls rows: out[b,0,:] = x1 + h2*w ----------------
__global__ void final_cls_kernel(const float* __restrict__ x1, const __half* __restrict__ h2,
                                 const float* __restrict__ w, float* __restrict__ out)
{
    int b = blockIdx.x, t = threadIdx.x;    // 384 threads
    size_t i = (size_t)b*NN*CC + t;
    out[i] = x1[i] + __half2float(h2[i]) * w[b*CC + t];
}

// ---------------- launcher ----------------
extern "C" void kernel_launch(void* const* d_in, const int* in_sizes, int n_in,
                              void* d_out, int out_size)
{
    const float* x       = (const float*)d_in[0];
    const float* ln1_g   = (const float*)d_in[1];
    const float* ln1_b   = (const float*)d_in[2];
    const float* qkv_w   = (const float*)d_in[3];
    const float* proj_w  = (const float*)d_in[4];
    const float* proj_b  = (const float*)d_in[5];
    const float* ln2_g   = (const float*)d_in[6];
    const float* ln2_b   = (const float*)d_in[7];
    const float* conv1_w = (const float*)d_in[8];
    const float* conv1_b = (const float*)d_in[9];
    const float* conv2_w = (const float*)d_in[10];
    const float* conv2_b = (const float*)d_in[11];
    const float* conv3_w = (const float*)d_in[12];
    const float* conv3_b = (const float*)d_in[13];
    const float* bn1_s   = (const float*)d_in[14];
    const float* bn1_b   = (const float*)d_in[15];
    const float* bn2_s   = (const float*)d_in[16];
    const float* bn2_b   = (const float*)d_in[17];
    const float* bn3_s   = (const float*)d_in[18];
    const float* bn3_b   = (const float*)d_in[19];
    const float* comp_w  = (const float*)d_in[20];
    const float* comp_b  = (const float*)d_in[21];
    const float* exc_w   = (const float*)d_in[22];
    const float* exc_b   = (const float*)d_in[23];
    float* out = (float*)d_out;

    static bool init = false;
    static __half *p_hh, *p_qkvh, *p_oh, *p_h2h, *p_yh, *p_y2h, *p_wq, *p_wp, *p_w1, *p_w3;
    static float *p_x1, *p_part2, *p_w;
    if (!init){
        cudaGetSymbolAddress((void**)&p_hh,    g_hh);
        cudaGetSymbolAddress((void**)&p_qkvh,  g_qkvh);
        cudaGetSymbolAddress((void**)&p_oh,    g_oh);
        cudaGetSymbolAddress((void**)&p_x1,    g_x1);
        cudaGetSymbolAddress((void**)&p_h2h,   g_h2h);
        cudaGetSymbolAddress((void**)&p_yh,    g_yh);
        cudaGetSymbolAddress((void**)&p_y2h,   g_y2h);
        cudaGetSymbolAddress((void**)&p_part2, g_part2);
        cudaGetSymbolAddress((void**)&p_w,     g_w);
        cudaGetSymbolAddress((void**)&p_wq,    g_wq);
        cudaGetSymbolAddress((void**)&p_wp,    g_wp);
        cudaGetSymbolAddress((void**)&p_w1,    g_w1);
        cudaGetSymbolAddress((void**)&p_w3,    g_w3);
        cudaFuncSetAttribute(gemm_h<0,false>, cudaFuncAttributeMaxDynamicSharedMemorySize, GEMM_SMEM);
        cudaFuncSetAttribute(gemm_h<1,false>, cudaFuncAttributeMaxDynamicSharedMemorySize, GEMM_SMEM);
        cudaFuncSetAttribute(gemm_h<2,true>,  cudaFuncAttributeMaxDynamicSharedMemorySize, GEMM_SMEM);
        cudaFuncSetAttribute(gemm_h<4,false>, cudaFuncAttributeMaxDynamicSharedMemorySize, GEMM_SMEM);
        cudaFuncSetAttribute(attn_h, cudaFuncAttributeMaxDynamicSharedMemorySize, ATTN_SMEM);
        init = true;
    }

    // 0. weight conversions
    f2h_kernel<<<512, 256>>>(qkv_w,   p_wq, 3*CC*CC);
    f2h_kernel<<<512, 256>>>(proj_w,  p_wp, CC*CC);
    f2h_kernel<<<512, 256>>>(conv1_w, p_w1, HID*CC);
    f2h_kernel<<<512, 256>>>(conv3_w, p_w3, CC*HID);
    // 1. LN1 -> fp16 h
    ln_kernel<<<MTOT, 128>>>(x, ln1_g, ln1_b, p_hh);
    // 2. QKV = h @ qkv_w^T -> fp16
    gemm_h<0,false><<<dim3(9,129), 256, GEMM_SMEM>>>(p_hh, p_wq, p_qkvh, MTOT, 3*CC, CC,
                                                     nullptr, nullptr, nullptr, nullptr, nullptr);
    // 3. attention -> fp16 o
    attn_h<<<BB*HH*9, 256, ATTN_SMEM>>>(p_qkvh, p_oh);
    // 4. x1 = x + o @ proj_w^T + proj_b (fp32)
    gemm_h<1,false><<<dim3(3,129), 256, GEMM_SMEM>>>(p_oh, p_wp, p_x1, MTOT, CC, CC,
                                                     proj_b, nullptr, nullptr, x, nullptr);
    // 5. LN2 -> fp16 h2
    ln_kernel<<<MTOT, 128>>>(p_x1, ln2_g, ln2_b, p_h2h);
    // 6. conv1 + BN1 + GELU -> fp16 y (tokens only)
    gemm_h<2,true><<<dim3(12,128), 256, GEMM_SMEM>>>(p_h2h, p_w1, p_yh, MTOK, HID, CC,
                                                     conv1_b, bn1_s, bn1_b, nullptr, nullptr);
    // 7. depthwise 3x3 + BN2 -> fp16 y2
    dwconv_kernel<<<MTOK, 256>>>((const __half2*)p_yh, conv2_w, conv2_b, bn2_s, bn2_b,
                                 (__half2*)p_y2h);
    // 7.5 zero column sums
    zero_part_kernel<<<(BB*CC + 255)/256, 256>>>(p_part2);
    // 8. conv3 + BN3 fused tail (writes token rows of out + column sums)
    gemm_h<4,false><<<dim3(3,128), 256, GEMM_SMEM>>>(p_y2h, p_w3, out, MTOK, CC, HID,
                                                     conv3_b, bn3_s, bn3_b, p_x1, p_part2);
    // 9. SE gate
    se_kernel<<<BB, CC>>>(p_part2, comp_w, comp_b, exc_w, exc_b, p_w);
    // 10. cls rows
    final_cls_kernel<<<BB, CC>>>(p_x1, p_h2h, p_w, out);
}

// round 10
// speedup vs baseline: 4.1573x; 1.0725x over previous
#include <cuda_runtime.h>
#include <cuda_fp16.h>
#include <cstdint>

// ---------------- problem constants ----------------
#define BB   16
#define NN   1025
#define CC   384
#define HH   6
#define HD   64
#define HID  1536
#define MTOT (BB*NN)      // 16400
#define MTOK (BB*1024)    // 16384

// ---------------- scratch (device globals, no alloc) ----------------
__device__ __half g_hh  [MTOT*CC];
__device__ __half g_qkvh[MTOT*3*CC];
__device__ __half g_oh  [MTOT*CC];
__device__ float  g_x1  [MTOT*CC];
__device__ __half g_h2h [MTOT*CC];
__device__ __half g_yh  [(size_t)MTOK*HID];
__device__ __half g_y2h [(size_t)MTOK*HID];
__device__ float  g_part2[BB*CC];
__device__ float  g_w   [BB*CC];
__device__ __half g_wq  [3*CC*CC];
__device__ __half g_wp  [CC*CC];
__device__ __half g_w1  [HID*CC];
__device__ __half g_w3  [CC*HID];

__device__ __forceinline__ float gelu_f(float x){
    return 0.5f * x * (1.0f + erff(x * 0.70710678118654752f));
}

__device__ __forceinline__ void mma_f16(float* c, const uint32_t* a, const uint32_t* b){
    asm volatile("mma.sync.aligned.m16n8k16.row.col.f32.f16.f16.f32 "
        "{%0,%1,%2,%3}, {%4,%5,%6,%7}, {%8,%9}, {%0,%1,%2,%3};"
        : "+f"(c[0]), "+f"(c[1]), "+f"(c[2]), "+f"(c[3])
        : "r"(a[0]), "r"(a[1]), "r"(a[2]), "r"(a[3]), "r"(b[0]), "r"(b[1]));
}

__device__ __forceinline__ void ldsm4(uint32_t* r, uint32_t addr){
    asm volatile("ldmatrix.sync.aligned.m8n8.x4.shared.b16 {%0,%1,%2,%3}, [%4];"
        : "=r"(r[0]), "=r"(r[1]), "=r"(r[2]), "=r"(r[3]) : "r"(addr));
}

__device__ __forceinline__ uint32_t smem_u32(const void* p){
    return (uint32_t)__cvta_generic_to_shared(p);
}
__device__ __forceinline__ void cp16(uint32_t dst, const void* src, bool pred){
    int sz = pred ? 16 : 0;
    asm volatile("cp.async.ca.shared.global [%0], [%1], 16, %2;"
                 :: "r"(dst), "l"(src), "r"(sz));
}
__device__ __forceinline__ void cp_commit(){ asm volatile("cp.async.commit_group;"); }
__device__ __forceinline__ void cp_wait0(){ asm volatile("cp.async.wait_group 0;"); }
__device__ __forceinline__ void cp_wait1(){ asm volatile("cp.async.wait_group 1;"); }

__device__ __forceinline__ uint32_t pack_h2(float x, float y){
    __half2 h = __floats2half2_rn(x, y);
    return *reinterpret_cast<uint32_t*>(&h);
}

// ---------------- fused fp32 -> fp16 weight convert (one launch) ----------------
#define NW0 (3*CC*CC)
#define NW1 (CC*CC)
#define NW2 (HID*CC)
#define NW3 (CC*HID)
__global__ void f2h_all(const float* __restrict__ s0, __half* __restrict__ d0,
                        const float* __restrict__ s1, __half* __restrict__ d1,
                        const float* __restrict__ s2, __half* __restrict__ d2,
                        const float* __restrict__ s3, __half* __restrict__ d3)
{
    int i2 = blockIdx.x*256 + threadIdx.x;       // index in float2 units
    int stride = gridDim.x*256;
    const int t0 = NW0/2, t1 = t0 + NW1/2, t2 = t1 + NW2/2, t3 = t2 + NW3/2;
    for (; i2 < t3; i2 += stride){
        const float2* s; __half2* d; int off;
        if (i2 < t0){ s = (const float2*)s0; d = (__half2*)d0; off = i2; }
        else if (i2 < t1){ s = (const float2*)s1; d = (__half2*)d1; off = i2 - t0; }
        else if (i2 < t2){ s = (const float2*)s2; d = (__half2*)d2; off = i2 - t1; }
        else { s = (const float2*)s3; d = (__half2*)d3; off = i2 - t2; }
        float2 v = s[off];
        d[off] = __floats2half2_rn(v.x, v.y);
    }
}

// ---------------- LayerNorm over last dim (C=384), fp16 out ----------------
__global__ void ln_kernel(const float* __restrict__ x, const float* __restrict__ g,
                          const float* __restrict__ bta, __half* __restrict__ out)
{
    __shared__ float red[4];
    __shared__ float bc[2];
    int row = blockIdx.x;
    const float* xr = x + (size_t)row * CC;
    int t = threadIdx.x;                      // 128 threads
    float v0 = xr[t], v1 = xr[t+128], v2 = xr[t+256];
    float s = v0 + v1 + v2;
    #pragma unroll
    for (int o=16;o;o>>=1) s += __shfl_xor_sync(0xffffffffu, s, o);
    if ((t&31)==0) red[t>>5] = s;
    __syncthreads();
    if (t==0) bc[0] = (red[0]+red[1]+red[2]+red[3]) * (1.0f/CC);
    __syncthreads();
    float mu = bc[0];
    float d0=v0-mu, d1=v1-mu, d2=v2-mu;
    float q = d0*d0 + d1*d1 + d2*d2;
    #pragma unroll
    for (int o=16;o;o>>=1) q += __shfl_xor_sync(0xffffffffu, q, o);
    if ((t&31)==0) red[t>>5] = q;
    __syncthreads();
    if (t==0) bc[1] = rsqrtf((red[0]+red[1]+red[2]+red[3]) * (1.0f/CC) + 1e-5f);
    __syncthreads();
    float rs = bc[1];
    __half* orow = out + (size_t)row * CC;
    orow[t]     = __float2half(d0*rs*g[t]     + bta[t]);
    orow[t+128] = __float2half(d1*rs*g[t+128] + bta[t+128]);
    orow[t+256] = __float2half(d2*rs*g[t+256] + bta[t+256]);
}

// ---------------- fp16 mma.sync GEMM with ldmatrix ----------------
// C[M,N] = A[M,K] @ W[N,K]^T + epilogue. A, W fp16.
// 256 threads / 8 warps. CTA tile 128x128, warp tile 64x32, k-block 64.
// EPI: 0 -> fp16 out | 1 -> fp32 resid+bias | 2 -> fp16 bias+BN+GELU |
//      4 -> fp32 bias+BN + resid into remapped out rows + column-sum atomics.
#define SPAD 36                     // u32 per row (64 halfs + pad)
#define BUFW (2*128*SPAD)
#define GEMM_SMEM (3*BUFW*4)

template<int EPI, bool SKIP>
__global__ void __launch_bounds__(256, 2) gemm_h(
    const __half* __restrict__ A, const __half* __restrict__ W, void* __restrict__ Cv,
    int M, int N, int K,
    const float* __restrict__ bias, const float* __restrict__ scale,
    const float* __restrict__ shift, const float* __restrict__ residual,
    float* __restrict__ psum)
{
    extern __shared__ uint32_t smg[];
    const int tid  = threadIdx.x;
    const int lane = tid & 31;
    const int warp = tid >> 5;
    const int wm = (warp & 1) * 64;
    const int wn = (warp >> 1) * 32;
    const int m0 = blockIdx.y * 128, n0 = blockIdx.x * 128;
    const int f = tid & 7;
    const int r = tid >> 3;
    const int g4 = lane >> 2;
    const int q4 = lane & 3;
    const int nk = K / 64;
    // ldmatrix per-thread address components
    const int arow = lane & 15;                 // row within 16-row A tile
    const int acol = 4*(lane >> 4);             // 16B half-select
    const int brow = (lane & 7) + ((lane >> 4) & 1)*8;   // row within 16-row B pair
    const int bcol = 4*((lane >> 3) & 1);

    float c[4][4][4];
    #pragma unroll
    for (int i=0;i<4;i++)
        #pragma unroll
        for (int j=0;j<4;j++)
            #pragma unroll
            for (int e=0;e<4;e++) c[i][j][e] = 0.f;

    auto stage = [&](int kb, int bf){
        uint32_t* As = smg + bf*BUFW;
        uint32_t* Bs = As + 128*SPAD;
        int k0 = kb * 64 + f * 8;       // in halfs
        #pragma unroll
        for (int i = 0; i < 4; i++){
            int row = r + 32*i;
            int m = m0 + row;
            bool p = (m < M);
            int gr = 0;
            if (p) gr = SKIP ? ((m >> 10)*1025 + (m & 1023) + 1) : m;
            cp16(smem_u32(As + row*SPAD + 4*f), A + (size_t)gr*K + k0, p);
        }
        #pragma unroll
        for (int i = 0; i < 4; i++){
            int row = r + 32*i;
            cp16(smem_u32(Bs + row*SPAD + 4*f), W + (size_t)(n0+row)*K + k0, true);
        }
    };

    stage(0, 0); cp_commit();
    if (nk > 1){ stage(1, 1); cp_commit(); }

    for (int kb = 0; kb < nk; kb++){
        if (kb + 1 < nk) cp_wait1(); else cp_wait0();
        __syncthreads();
        if (kb + 2 < nk){ stage(kb+2, (kb+2)%3); cp_commit(); }
        const uint32_t* Au = smg + (kb%3)*BUFW;
        const uint32_t* Bu = Au + 128*SPAD;
        #pragma unroll
        for (int ks = 0; ks < 4; ks++){
            uint32_t a[4][4], bt[2][4];
            #pragma unroll
            for (int i=0;i<4;i++)
                ldsm4(a[i], smem_u32(Au + (wm + 16*i + arow)*SPAD + ks*8 + acol));
            ldsm4(bt[0], smem_u32(Bu + (wn +      brow)*SPAD + ks*8 + bcol));
            ldsm4(bt[1], smem_u32(Bu + (wn + 16 + brow)*SPAD + ks*8 + bcol));
            #pragma unroll
            for (int i=0;i<4;i++){
                mma_f16(c[i][0], a[i], &bt[0][0]);
                mma_f16(c[i][1], a[i], &bt[0][2]);
                mma_f16(c[i][2], a[i], &bt[1][0]);
                mma_f16(c[i][3], a[i], &bt[1][2]);
            }
        }
        __syncthreads();
    }
    // ---- epilogue ----
    if (EPI == 4){
        float* C = (float*)Cv;
        const int bidx = m0 >> 10;
        float colsum[8];
        #pragma unroll
        for (int e=0;e<8;e++) colsum[e] = 0.f;
        #pragma unroll
        for (int i=0;i<4;i++){
            #pragma unroll
            for (int hh=0; hh<2; hh++){
                int m = m0 + wm + 16*i + g4 + 8*hh;
                size_t orow = (size_t)((m >> 10)*1025 + (m & 1023) + 1);
                #pragma unroll
                for (int j=0;j<4;j++){
                    int n = n0 + wn + 8*j + 2*q4;
                    float vx = (c[i][j][hh*2+0] + bias[n])  *scale[n]   + shift[n];
                    float vy = (c[i][j][hh*2+1] + bias[n+1])*scale[n+1] + shift[n+1];
                    colsum[2*j]   += vx;
                    colsum[2*j+1] += vy;
                    float2 rv = *(const float2*)(residual + orow*N + n);
                    float2 ov; ov.x = vx + rv.x; ov.y = vy + rv.y;
                    *(float2*)(C + orow*N + n) = ov;
                }
            }
        }
        #pragma unroll
        for (int e=0;e<8;e++){
            float v = colsum[e];
            v += __shfl_xor_sync(0xffffffffu, v, 4);
            v += __shfl_xor_sync(0xffffffffu, v, 8);
            v += __shfl_xor_sync(0xffffffffu, v, 16);
            if ((lane >> 2) == 0){
                int n = n0 + wn + 8*(e>>1) + 2*(lane&3) + (e&1);
                atomicAdd(&psum[bidx*CC + n], v);
            }
        }
        return;
    }
    #pragma unroll
    for (int i=0;i<4;i++){
        int mrow0 = m0 + wm + 16*i + g4;
        #pragma unroll
        for (int hh=0; hh<2; hh++){
            int m = mrow0 + 8*hh;
            if (m >= M) continue;
            #pragma unroll
            for (int j=0;j<4;j++){
                int n = n0 + wn + 8*j + 2*q4;
                float vx = c[i][j][hh*2 + 0];
                float vy = c[i][j][hh*2 + 1];
                size_t idx = (size_t)m*N + n;
                if (EPI == 0){
                    *(uint32_t*)((__half*)Cv + idx) = pack_h2(vx, vy);
                } else if (EPI == 1){
                    float* C = (float*)Cv;
                    float2 rv = *(const float2*)(residual + idx);
                    float2 ov; ov.x = vx + bias[n] + rv.x; ov.y = vy + bias[n+1] + rv.y;
                    *(float2*)(C + idx) = ov;
                } else if (EPI == 2){
                    vx = gelu_f((vx + bias[n])  *scale[n]   + shift[n]);
                    vy = gelu_f((vy + bias[n+1])*scale[n+1] + shift[n+1]);
                    *(uint32_t*)((__half*)Cv + idx) = pack_h2(vx, vy);
                }
            }
        }
    }
}

// ---------------- fp16 tensor-core flash attention (ldmatrix) ----------------
// 256 threads / 8 warps; 128 q rows per CTA share each 64-key K/V tile.
#define ATTN_SMEM ((128*36 + 64*36 + 64*36 + 128*36)*4)
__global__ void __launch_bounds__(256) attn_h(const __half* __restrict__ qkv,
                                              __half* __restrict__ o)
{
    extern __shared__ uint32_t sm[];
    uint32_t* Qu = sm;                  // [128][36]
    uint32_t* Ku = Qu + 128*36;         // [64][36]
    uint32_t* Vt = Ku + 64*36;          // [64 d][36], kk-pair swizzled
    uint32_t* Pu = Vt + 64*36;          // [128][36]

    const int tid  = threadIdx.x;
    const int lane = tid & 31;
    const int warp = tid >> 5;
    const int g4 = lane >> 2, q4 = lane & 3;
    const int pair = blockIdx.x % 9;
    const int bh   = blockIdx.x / 9;
    const int h = bh % HH, b = bh / HH;
    const int q0 = pair * 128;
    const int qrow = warp * 16;
    const int arow = lane & 15;
    const int acol = 4*(lane >> 4);
    const int brow = (lane & 7) + ((lane >> 4) & 1)*8;
    const int bcol = 4*((lane >> 3) & 1);

    const __half* qp = qkv + (size_t)b*NN*(3*CC) + h*HD;
    const __half* kp = qp + CC;
    const __half* vp = qp + 2*CC;

    const int f  = tid & 7;
    const int rg = tid >> 3;            // 0..31

    // stage Q (128 rows)
    #pragma unroll
    for (int i=0;i<4;i++){
        int row = rg + 32*i;
        int q = q0 + row;
        bool p = (q < NN);
        cp16(smem_u32(Qu + row*36 + 4*f), qp + (size_t)(p ? q : 0)*(3*CC) + 8*f, p);
    }
    cp_commit();

    float oa[8][4];
    #pragma unroll
    for (int j=0;j<8;j++){ oa[j][0]=0.f; oa[j][1]=0.f; oa[j][2]=0.f; oa[j][3]=0.f; }
    float m0r = -1e30f, m1r = -1e30f, l0r = 0.f, l1r = 0.f;

    for (int kt = 0; kt < 17; kt++){
        // K tile via cp.async
        #pragma unroll
        for (int i=0;i<2;i++){
            int row = rg + 32*i;
            int kk = kt*64 + row;
            bool p = (kk < NN);
            cp16(smem_u32(Ku + row*36 + 4*f), kp + (size_t)(p ? kk : 0)*(3*CC) + 8*f, p);
        }
        cp_commit();
        // V tile transposed: Vt[d][kk-pair ^ 4*(d>>3)]
        {
            int kk0 = kt*64 + 2*rg;
            uint4 va = make_uint4(0,0,0,0), vb = make_uint4(0,0,0,0);
            if (kk0   < NN) va = *(const uint4*)(vp + (size_t)kk0*(3*CC) + 8*f);
            if (kk0+1 < NN) vb = *(const uint4*)(vp + (size_t)(kk0+1)*(3*CC) + 8*f);
            uint32_t sw = (uint32_t)rg ^ (uint32_t)(4*f);
            uint32_t ua[4] = {va.x, va.y, va.z, va.w};
            uint32_t ub[4] = {vb.x, vb.y, vb.z, vb.w};
            #pragma unroll
            for (int t4=0;t4<4;t4++){
                int d0 = 8*f + 2*t4;
                Vt[d0*36 + sw]     = (ua[t4] & 0xFFFFu)  | (ub[t4] << 16);
                Vt[(d0+1)*36 + sw] = (ua[t4] >> 16)      | (ub[t4] & 0xFFFF0000u);
            }
        }
        cp_wait0();
        __syncthreads();

        // ---- S = Q K^T (fp16 k16, ldmatrix) ----
        float sc[8][4];
        #pragma unroll
        for (int j=0;j<8;j++){ sc[j][0]=0.f; sc[j][1]=0.f; sc[j][2]=0.f; sc[j][3]=0.f; }
        #pragma unroll
        for (int ks=0; ks<4; ks++){
            uint32_t a[4];
            ldsm4(a, smem_u32(Qu + (qrow + arow)*36 + ks*8 + acol));
            #pragma unroll
            for (int j2=0; j2<4; j2++){
                uint32_t bt[4];
                ldsm4(bt, smem_u32(Ku + (16*j2 + brow)*36 + ks*8 + bcol));
                mma_f16(sc[2*j2],   a, &bt[0]);
                mma_f16(sc[2*j2+1], a, &bt[2]);
            }
        }
        #pragma unroll
        for (int j=0;j<8;j++){
            sc[j][0]*=0.125f; sc[j][1]*=0.125f; sc[j][2]*=0.125f; sc[j][3]*=0.125f;
        }
        if (kt == 16){
            #pragma unroll
            for (int j=0;j<8;j++){
                int c0 = kt*64 + 8*j + 2*q4;
                if (c0   >= NN){ sc[j][0] = -1e30f; sc[j][2] = -1e30f; }
                if (c0+1 >= NN){ sc[j][1] = -1e30f; sc[j][3] = -1e30f; }
            }
        }
        // ---- online softmax ----
        float mx0 = -1e30f, mx1 = -1e30f;
        #pragma unroll
        for (int j=0;j<8;j++){
            mx0 = fmaxf(mx0, fmaxf(sc[j][0], sc[j][1]));
            mx1 = fmaxf(mx1, fmaxf(sc[j][2], sc[j][3]));
        }
        mx0 = fmaxf(mx0, __shfl_xor_sync(0xffffffffu, mx0, 1));
        mx0 = fmaxf(mx0, __shfl_xor_sync(0xffffffffu, mx0, 2));
        mx1 = fmaxf(mx1, __shfl_xor_sync(0xffffffffu, mx1, 1));
        mx1 = fmaxf(mx1, __shfl_xor_sync(0xffffffffu, mx1, 2));
        float mn0 = fmaxf(m0r, mx0), mn1 = fmaxf(m1r, mx1);
        float al0 = __expf(m0r - mn0), al1 = __expf(m1r - mn1);
        float s0 = 0.f, s1 = 0.f;
        #pragma unroll
        for (int j=0;j<8;j++){
            float p00 = __expf(sc[j][0]-mn0), p01 = __expf(sc[j][1]-mn0);
            float p10 = __expf(sc[j][2]-mn1), p11 = __expf(sc[j][3]-mn1);
            sc[j][0]=p00; sc[j][1]=p01; sc[j][2]=p10; sc[j][3]=p11;
            s0 += p00 + p01; s1 += p10 + p11;
        }
        s0 += __shfl_xor_sync(0xffffffffu, s0, 1);
        s0 += __shfl_xor_sync(0xffffffffu, s0, 2);
        s1 += __shfl_xor_sync(0xffffffffu, s1, 1);
        s1 += __shfl_xor_sync(0xffffffffu, s1, 2);
        l0r = l0r*al0 + s0; l1r = l1r*al1 + s1;
        m0r = mn0; m1r = mn1;
        #pragma unroll
        for (int j=0;j<8;j++){
            oa[j][0]*=al0; oa[j][1]*=al0; oa[j][2]*=al1; oa[j][3]*=al1;
        }
        // ---- stage P (fp16, per-warp rows) ----
        #pragma unroll
        for (int j=0;j<8;j++){
            Pu[(qrow+g4)*36   + 4*j+q4] = pack_h2(sc[j][0], sc[j][1]);
            Pu[(qrow+g4+8)*36 + 4*j+q4] = pack_h2(sc[j][2], sc[j][3]);
        }
        __syncwarp();
        // ---- O += P V ----
        #pragma unroll
        for (int ks=0; ks<4; ks++){
            uint32_t a[4];
            ldsm4(a, smem_u32(Pu + (qrow + arow)*36 + ks*8 + acol));
            #pragma unroll
            for (int j=0;j<8;j++){
                uint32_t bfr[2];
                int sw0 = (ks*8+q4)   ^ (4*j);
                int sw1 = (ks*8+q4+4) ^ (4*j);
                bfr[0] = Vt[(8*j+g4)*36 + sw0];
                bfr[1] = Vt[(8*j+g4)*36 + sw1];
                mma_f16(oa[j], a, bfr);
            }
        }
        __syncthreads();
    }
    float inv0 = 1.0f / l0r, inv1 = 1.0f / l1r;
    int qg0 = q0 + qrow + g4, qg1 = qg0 + 8;
    #pragma unroll
    for (int j=0;j<8;j++){
        int d = h*HD + 8*j + 2*q4;
        if (qg0 < NN)
            *(uint32_t*)(o + (size_t)(b*NN + qg0)*CC + d) = pack_h2(oa[j][0]*inv0, oa[j][1]*inv0);
        if (qg1 < NN)
            *(uint32_t*)(o + (size_t)(b*NN + qg1)*CC + d) = pack_h2(oa[j][2]*inv1, oa[j][3]*inv1);
    }
}

// ---------------- depthwise 3x3 + BN + residual GELU (fp16 in/out) ----------------
__global__ void dwconv_kernel(const __half2* __restrict__ y, const float* __restrict__ w2,
                              const float* __restrict__ b2, const float* __restrict__ s2,
                              const float* __restrict__ h2b, __half2* __restrict__ out)
{
    int pix = blockIdx.x;                 // 0..16383
    int b = pix >> 10, p = pix & 1023;
    int sy = p >> 5, sx = p & 31;
    const __half2* yb = y + (size_t)(b << 10) * 768;
    for (int c2 = threadIdx.x; c2 < 768; c2 += blockDim.x){
        int c = 2*c2;
        float ax = 0.f, ay = 0.f;
        #pragma unroll
        for (int dy=0; dy<3; dy++){
            int iy = sy + dy - 1;
            if ((unsigned)iy >= 32u) continue;
            #pragma unroll
            for (int dx=0; dx<3; dx++){
                int ix = sx + dx - 1;
                if ((unsigned)ix >= 32u) continue;
                float2 fv = __half22float2(yb[(size_t)((iy<<5)+ix)*768 + c2]);
                ax += fv.x * w2[c*9 + dy*3 + dx];
                ay += fv.y * w2[(c+1)*9 + dy*3 + dx];
            }
        }
        float vx = (ax + b2[c])  *s2[c]   + h2b[c];
        float vy = (ay + b2[c+1])*s2[c+1] + h2b[c+1];
        float2 cf = __half22float2(y[(size_t)pix*768 + c2]);
        out[(size_t)pix*768 + c2] = __floats2half2_rn(cf.x + gelu_f(vx), cf.y + gelu_f(vy));
    }
}

// ---------------- zero the column-sum buffer ----------------
__global__ void zero_part_kernel(float* __restrict__ p){
    int i = blockIdx.x*256 + threadIdx.x;
    if (i < BB*CC) p[i] = 0.f;
}

// ---------------- SE gate ----------------
__global__ void se_kernel(const float* __restrict__ part, const float* __restrict__ cw,
                          const float* __restrict__ cb, const float* __restrict__ ew,
                          const float* __restrict__ eb, float* __restrict__ wout)
{
    __shared__ float m[CC];
    __shared__ float cv[96];
    int b = blockIdx.x, t = threadIdx.x;    // 384 threads
    m[t] = part[b*CC + t] * (1.0f/1024.0f);
    __syncthreads();
    if (t < 96){
        float a = cb[t];
        for (int k=0;k<CC;k++) a += m[k]*cw[t*CC + k];
        cv[t] = gelu_f(a);
    }
    __syncthreads();
    float a = eb[t];
    for (int k=0;k<96;k++) a += cv[k]*ew[t*96 + k];
    wout[b*CC + t] = a;
}

// ---------------- cls rows: out[b,0,:] = x1 + h2*w ----------------
__global__ void final_cls_kernel(const float* __restrict__ x1, const __half* __restrict__ h2,
                                 const float* __restrict__ w, float* __restrict__ out)
{
    int b = blockIdx.x, t = threadIdx.x;    // 384 threads
    size_t i = (size_t)b*NN*CC + t;
    out[i] = x1[i] + __half2float(h2[i]) * w[b*CC + t];
}

// ---------------- launcher ----------------
extern "C" void kernel_launch(void* const* d_in, const int* in_sizes, int n_in,
                              void* d_out, int out_size)
{
    const float* x       = (const float*)d_in[0];
    const float* ln1_g   = (const float*)d_in[1];
    const float* ln1_b   = (const float*)d_in[2];
    const float* qkv_w   = (const float*)d_in[3];
    const float* proj_w  = (const float*)d_in[4];
    const float* proj_b  = (const float*)d_in[5];
    const float* ln2_g   = (const float*)d_in[6];
    const float* ln2_b   = (const float*)d_in[7];
    const float* conv1_w = (const float*)d_in[8];
    const float* conv1_b = (const float*)d_in[9];
    const float* conv2_w = (const float*)d_in[10];
    const float* conv2_b = (const float*)d_in[11];
    const float* conv3_w = (const float*)d_in[12];
    const float* conv3_b = (const float*)d_in[13];
    const float* bn1_s   = (const float*)d_in[14];
    const float* bn1_b   = (const float*)d_in[15];
    const float* bn2_s   = (const float*)d_in[16];
    const float* bn2_b   = (const float*)d_in[17];
    const float* bn3_s   = (const float*)d_in[18];
    const float* bn3_b   = (const float*)d_in[19];
    const float* comp_w  = (const float*)d_in[20];
    const float* comp_b  = (const float*)d_in[21];
    const float* exc_w   = (const float*)d_in[22];
    const float* exc_b   = (const float*)d_in[23];
    float* out = (float*)d_out;

    static bool init = false;
    static __half *p_hh, *p_qkvh, *p_oh, *p_h2h, *p_yh, *p_y2h, *p_wq, *p_wp, *p_w1, *p_w3;
    static float *p_x1, *p_part2, *p_w;
    if (!init){
        cudaGetSymbolAddress((void**)&p_hh,    g_hh);
        cudaGetSymbolAddress((void**)&p_qkvh,  g_qkvh);
        cudaGetSymbolAddress((void**)&p_oh,    g_oh);
        cudaGetSymbolAddress((void**)&p_x1,    g_x1);
        cudaGetSymbolAddress((void**)&p_h2h,   g_h2h);
        cudaGetSymbolAddress((void**)&p_yh,    g_yh);
        cudaGetSymbolAddress((void**)&p_y2h,   g_y2h);
        cudaGetSymbolAddress((void**)&p_part2, g_part2);
        cudaGetSymbolAddress((void**)&p_w,     g_w);
        cudaGetSymbolAddress((void**)&p_wq,    g_wq);
        cudaGetSymbolAddress((void**)&p_wp,    g_wp);
        cudaGetSymbolAddress((void**)&p_w1,    g_w1);
        cudaGetSymbolAddress((void**)&p_w3,    g_w3);
        cudaFuncSetAttribute(gemm_h<0,false>, cudaFuncAttributeMaxDynamicSharedMemorySize, GEMM_SMEM);
        cudaFuncSetAttribute(gemm_h<1,false>, cudaFuncAttributeMaxDynamicSharedMemorySize, GEMM_SMEM);
        cudaFuncSetAttribute(gemm_h<2,true>,  cudaFuncAttributeMaxDynamicSharedMemorySize, GEMM_SMEM);
        cudaFuncSetAttribute(gemm_h<4,false>, cudaFuncAttributeMaxDynamicSharedMemorySize, GEMM_SMEM);
        cudaFuncSetAttribute(attn_h, cudaFuncAttributeMaxDynamicSharedMemorySize, ATTN_SMEM);
        init = true;
    }

    // 0. weight conversions (single launch)
    f2h_all<<<512, 256>>>(qkv_w, p_wq, proj_w, p_wp, conv1_w, p_w1, conv3_w, p_w3);
    // 1. LN1 -> fp16 h
    ln_kernel<<<MTOT, 128>>>(x, ln1_g, ln1_b, p_hh);
    // 2. QKV = h @ qkv_w^T -> fp16
    gemm_h<0,false><<<dim3(9,129), 256, GEMM_SMEM>>>(p_hh, p_wq, p_qkvh, MTOT, 3*CC, CC,
                                                     nullptr, nullptr, nullptr, nullptr, nullptr);
    // 3. attention -> fp16 o
    attn_h<<<BB*HH*9, 256, ATTN_SMEM>>>(p_qkvh, p_oh);
    // 4. x1 = x + o @ proj_w^T + proj_b (fp32)
    gemm_h<1,false><<<dim3(3,129), 256, GEMM_SMEM>>>(p_oh, p_wp, p_x1, MTOT, CC, CC,
                                                     proj_b, nullptr, nullptr, x, nullptr);
    // 5. LN2 -> fp16 h2
    ln_kernel<<<MTOT, 128>>>(p_x1, ln2_g, ln2_b, p_h2h);
    // 6. conv1 + BN1 + GELU -> fp16 y (tokens only)
    gemm_h<2,true><<<dim3(12,128), 256, GEMM_SMEM>>>(p_h2h, p_w1, p_yh, MTOK, HID, CC,
                                                     conv1_b, bn1_s, bn1_b, nullptr, nullptr);
    // 7. depthwise 3x3 + BN2 -> fp16 y2
    dwconv_kernel<<<MTOK, 256>>>((const __half2*)p_yh, conv2_w, conv2_b, bn2_s, bn2_b,
                                 (__half2*)p_y2h);
    // 7.5 zero column sums
    zero_part_kernel<<<(BB*CC + 255)/256, 256>>>(p_part2);
    // 8. conv3 + BN3 fused tail (writes token rows of out + column sums)
    gemm_h<4,false><<<dim3(3,128), 256, GEMM_SMEM>>>(p_y2h, p_w3, out, MTOK, CC, HID,
                                                     conv3_b, bn3_s, bn3_b, p_x1, p_part2);
    // 9. SE gate
    se_kernel<<<BB, CC>>>(p_part2, comp_w, comp_b, exc_w, exc_b, p_w);
    // 10. cls rows
    final_cls_kernel<<<BB, CC>>>(p_x1, p_h2h, p_w, out);
}

// round 11
// speedup vs baseline: 4.5809x; 1.1019x over previous
#include <cuda_runtime.h>
#include <cuda_fp16.h>
#include <cstdint>

// ---------------- problem constants ----------------
#define BB   16
#define NN   1025
#define CC   384
#define HH   6
#define HD   64
#define HID  1536
#define MTOT (BB*NN)      // 16400
#define MTOK (BB*1024)    // 16384

// ---------------- scratch (device globals, no alloc) ----------------
__device__ __half g_hh  [MTOT*CC];
__device__ __half g_qkvh[MTOT*3*CC];
__device__ __half g_oh  [MTOT*CC];
__device__ float  g_x1  [MTOT*CC];
__device__ __half g_h2h [MTOT*CC];
__device__ __half g_yh  [(size_t)MTOK*HID];
__device__ __half g_y2h [(size_t)MTOK*HID];
__device__ float  g_part2[BB*CC];
__device__ float  g_w   [BB*CC];
__device__ __half g_wq  [3*CC*CC];
__device__ __half g_wp  [CC*CC];
__device__ __half g_w1  [HID*CC];
__device__ __half g_w3  [CC*HID];

__device__ __forceinline__ float gelu_f(float x){
    return 0.5f * x * (1.0f + erff(x * 0.70710678118654752f));
}

__device__ __forceinline__ void mma_f16(float* c, const uint32_t* a, const uint32_t* b){
    asm volatile("mma.sync.aligned.m16n8k16.row.col.f32.f16.f16.f32 "
        "{%0,%1,%2,%3}, {%4,%5,%6,%7}, {%8,%9}, {%0,%1,%2,%3};"
        : "+f"(c[0]), "+f"(c[1]), "+f"(c[2]), "+f"(c[3])
        : "r"(a[0]), "r"(a[1]), "r"(a[2]), "r"(a[3]), "r"(b[0]), "r"(b[1]));
}

__device__ __forceinline__ void ldsm4(uint32_t* r, uint32_t addr){
    asm volatile("ldmatrix.sync.aligned.m8n8.x4.shared.b16 {%0,%1,%2,%3}, [%4];"
        : "=r"(r[0]), "=r"(r[1]), "=r"(r[2]), "=r"(r[3]) : "r"(addr));
}
__device__ __forceinline__ void ldsm4t(uint32_t* r, uint32_t addr){
    asm volatile("ldmatrix.sync.aligned.m8n8.x4.trans.shared.b16 {%0,%1,%2,%3}, [%4];"
        : "=r"(r[0]), "=r"(r[1]), "=r"(r[2]), "=r"(r[3]) : "r"(addr));
}

__device__ __forceinline__ uint32_t smem_u32(const void* p){
    return (uint32_t)__cvta_generic_to_shared(p);
}
__device__ __forceinline__ void cp16(uint32_t dst, const void* src, bool pred){
    int sz = pred ? 16 : 0;
    asm volatile("cp.async.ca.shared.global [%0], [%1], 16, %2;"
                 :: "r"(dst), "l"(src), "r"(sz));
}
__device__ __forceinline__ void cp_commit(){ asm volatile("cp.async.commit_group;"); }
__device__ __forceinline__ void cp_wait0(){ asm volatile("cp.async.wait_group 0;"); }
__device__ __forceinline__ void cp_wait1(){ asm volatile("cp.async.wait_group 1;"); }

__device__ __forceinline__ uint32_t pack_h2(float x, float y){
    __half2 h = __floats2half2_rn(x, y);
    return *reinterpret_cast<uint32_t*>(&h);
}

// ---------------- fused fp32 -> fp16 weight convert (one launch) ----------------
#define NW0 (3*CC*CC)
#define NW1 (CC*CC)
#define NW2 (HID*CC)
#define NW3 (CC*HID)
__global__ void f2h_all(const float* __restrict__ s0, __half* __restrict__ d0,
                        const float* __restrict__ s1, __half* __restrict__ d1,
                        const float* __restrict__ s2, __half* __restrict__ d2,
                        const float* __restrict__ s3, __half* __restrict__ d3)
{
    int i2 = blockIdx.x*256 + threadIdx.x;       // index in float2 units
    int stride = gridDim.x*256;
    const int t0 = NW0/2, t1 = t0 + NW1/2, t2 = t1 + NW2/2, t3 = t2 + NW3/2;
    for (; i2 < t3; i2 += stride){
        const float2* s; __half2* d; int off;
        if (i2 < t0){ s = (const float2*)s0; d = (__half2*)d0; off = i2; }
        else if (i2 < t1){ s = (const float2*)s1; d = (__half2*)d1; off = i2 - t0; }
        else if (i2 < t2){ s = (const float2*)s2; d = (__half2*)d2; off = i2 - t1; }
        else { s = (const float2*)s3; d = (__half2*)d3; off = i2 - t2; }
        float2 v = s[off];
        d[off] = __floats2half2_rn(v.x, v.y);
    }
}

// ---------------- LayerNorm over last dim (C=384), fp16 out ----------------
__global__ void ln_kernel(const float* __restrict__ x, const float* __restrict__ g,
                          const float* __restrict__ bta, __half* __restrict__ out)
{
    __shared__ float red[4];
    __shared__ float bc[2];
    int row = blockIdx.x;
    const float* xr = x + (size_t)row * CC;
    int t = threadIdx.x;                      // 128 threads
    float v0 = xr[t], v1 = xr[t+128], v2 = xr[t+256];
    float s = v0 + v1 + v2;
    #pragma unroll
    for (int o=16;o;o>>=1) s += __shfl_xor_sync(0xffffffffu, s, o);
    if ((t&31)==0) red[t>>5] = s;
    __syncthreads();
    if (t==0) bc[0] = (red[0]+red[1]+red[2]+red[3]) * (1.0f/CC);
    __syncthreads();
    float mu = bc[0];
    float d0=v0-mu, d1=v1-mu, d2=v2-mu;
    float q = d0*d0 + d1*d1 + d2*d2;
    #pragma unroll
    for (int o=16;o;o>>=1) q += __shfl_xor_sync(0xffffffffu, q, o);
    if ((t&31)==0) red[t>>5] = q;
    __syncthreads();
    if (t==0) bc[1] = rsqrtf((red[0]+red[1]+red[2]+red[3]) * (1.0f/CC) + 1e-5f);
    __syncthreads();
    float rs = bc[1];
    __half* orow = out + (size_t)row * CC;
    orow[t]     = __float2half(d0*rs*g[t]     + bta[t]);
    orow[t+128] = __float2half(d1*rs*g[t+128] + bta[t+128]);
    orow[t+256] = __float2half(d2*rs*g[t+256] + bta[t+256]);
}

// ---------------- fp16 mma.sync GEMM with ldmatrix ----------------
#define SPAD 36
#define BUFW (2*128*SPAD)
#define GEMM_SMEM (3*BUFW*4)

template<int EPI, bool SKIP>
__global__ void __launch_bounds__(256, 2) gemm_h(
    const __half* __restrict__ A, const __half* __restrict__ W, void* __restrict__ Cv,
    int M, int N, int K,
    const float* __restrict__ bias, const float* __restrict__ scale,
    const float* __restrict__ shift, const float* __restrict__ residual,
    float* __restrict__ psum)
{
    extern __shared__ uint32_t smg[];
    const int tid  = threadIdx.x;
    const int lane = tid & 31;
    const int warp = tid >> 5;
    const int wm = (warp & 1) * 64;
    const int wn = (warp >> 1) * 32;
    const int m0 = blockIdx.y * 128, n0 = blockIdx.x * 128;
    const int f = tid & 7;
    const int r = tid >> 3;
    const int g4 = lane >> 2;
    const int q4 = lane & 3;
    const int nk = K / 64;
    const int arow = lane & 15;
    const int acol = 4*(lane >> 4);
    const int brow = (lane & 7) + ((lane >> 4) & 1)*8;
    const int bcol = 4*((lane >> 3) & 1);

    float c[4][4][4];
    #pragma unroll
    for (int i=0;i<4;i++)
        #pragma unroll
        for (int j=0;j<4;j++)
            #pragma unroll
            for (int e=0;e<4;e++) c[i][j][e] = 0.f;

    auto stage = [&](int kb, int bf){
        uint32_t* As = smg + bf*BUFW;
        uint32_t* Bs = As + 128*SPAD;
        int k0 = kb * 64 + f * 8;
        #pragma unroll
        for (int i = 0; i < 4; i++){
            int row = r + 32*i;
            int m = m0 + row;
            bool p = (m < M);
            int gr = 0;
            if (p) gr = SKIP ? ((m >> 10)*1025 + (m & 1023) + 1) : m;
            cp16(smem_u32(As + row*SPAD + 4*f), A + (size_t)gr*K + k0, p);
        }
        #pragma unroll
        for (int i = 0; i < 4; i++){
            int row = r + 32*i;
            cp16(smem_u32(Bs + row*SPAD + 4*f), W + (size_t)(n0+row)*K + k0, true);
        }
    };

    stage(0, 0); cp_commit();
    if (nk > 1){ stage(1, 1); cp_commit(); }

    for (int kb = 0; kb < nk; kb++){
        if (kb + 1 < nk) cp_wait1(); else cp_wait0();
        __syncthreads();
        if (kb + 2 < nk){ stage(kb+2, (kb+2)%3); cp_commit(); }
        const uint32_t* Au = smg + (kb%3)*BUFW;
        const uint32_t* Bu = Au + 128*SPAD;
        #pragma unroll
        for (int ks = 0; ks < 4; ks++){
            uint32_t a[4][4], bt[2][4];
            #pragma unroll
            for (int i=0;i<4;i++)
                ldsm4(a[i], smem_u32(Au + (wm + 16*i + arow)*SPAD + ks*8 + acol));
            ldsm4(bt[0], smem_u32(Bu + (wn +      brow)*SPAD + ks*8 + bcol));
            ldsm4(bt[1], smem_u32(Bu + (wn + 16 + brow)*SPAD + ks*8 + bcol));
            #pragma unroll
            for (int i=0;i<4;i++){
                mma_f16(c[i][0], a[i], &bt[0][0]);
                mma_f16(c[i][1], a[i], &bt[0][2]);
                mma_f16(c[i][2], a[i], &bt[1][0]);
                mma_f16(c[i][3], a[i], &bt[1][2]);
            }
        }
        __syncthreads();
    }
    // ---- epilogue ----
    if (EPI == 4){
        float* C = (float*)Cv;
        const int bidx = m0 >> 10;
        float colsum[8];
        #pragma unroll
        for (int e=0;e<8;e++) colsum[e] = 0.f;
        #pragma unroll
        for (int i=0;i<4;i++){
            #pragma unroll
            for (int hh=0; hh<2; hh++){
                int m = m0 + wm + 16*i + g4 + 8*hh;
                size_t orow = (size_t)((m >> 10)*1025 + (m & 1023) + 1);
                #pragma unroll
                for (int j=0;j<4;j++){
                    int n = n0 + wn + 8*j + 2*q4;
                    float vx = (c[i][j][hh*2+0] + bias[n])  *scale[n]   + shift[n];
                    float vy = (c[i][j][hh*2+1] + bias[n+1])*scale[n+1] + shift[n+1];
                    colsum[2*j]   += vx;
                    colsum[2*j+1] += vy;
                    float2 rv = *(const float2*)(residual + orow*N + n);
                    float2 ov; ov.x = vx + rv.x; ov.y = vy + rv.y;
                    *(float2*)(C + orow*N + n) = ov;
                }
            }
        }
        #pragma unroll
        for (int e=0;e<8;e++){
            float v = colsum[e];
            v += __shfl_xor_sync(0xffffffffu, v, 4);
            v += __shfl_xor_sync(0xffffffffu, v, 8);
            v += __shfl_xor_sync(0xffffffffu, v, 16);
            if ((lane >> 2) == 0){
                int n = n0 + wn + 8*(e>>1) + 2*(lane&3) + (e&1);
                atomicAdd(&psum[bidx*CC + n], v);
            }
        }
        return;
    }
    #pragma unroll
    for (int i=0;i<4;i++){
        int mrow0 = m0 + wm + 16*i + g4;
        #pragma unroll
        for (int hh=0; hh<2; hh++){
            int m = mrow0 + 8*hh;
            if (m >= M) continue;
            #pragma unroll
            for (int j=0;j<4;j++){
                int n = n0 + wn + 8*j + 2*q4;
                float vx = c[i][j][hh*2 + 0];
                float vy = c[i][j][hh*2 + 1];
                size_t idx = (size_t)m*N + n;
                if (EPI == 0){
                    *(uint32_t*)((__half*)Cv + idx) = pack_h2(vx, vy);
                } else if (EPI == 1){
                    float* C = (float*)Cv;
                    float2 rv = *(const float2*)(residual + idx);
                    float2 ov; ov.x = vx + bias[n] + rv.x; ov.y = vy + bias[n+1] + rv.y;
                    *(float2*)(C + idx) = ov;
                } else if (EPI == 2){
                    vx = gelu_f((vx + bias[n])  *scale[n]   + shift[n]);
                    vy = gelu_f((vy + bias[n+1])*scale[n+1] + shift[n+1]);
                    *(uint32_t*)((__half*)Cv + idx) = pack_h2(vx, vy);
                }
            }
        }
    }
}

// ---------------- fp16 flash attention v3: reg-P, ldmatrix.trans V, dbl-buffer KV ----
// 256 threads / 8 warps; 128 q rows per CTA; K/V tiles of 64 keys, double-buffered.
#define ATTN_SMEM ((128*36 + 2*128*36)*4)      // Q + 2x(K64+V64)
__global__ void __launch_bounds__(256) attn_h(const __half* __restrict__ qkv,
                                              __half* __restrict__ o)
{
    extern __shared__ uint32_t sm[];
    uint32_t* Qu  = sm;                 // [128][36]

    const int tid  = threadIdx.x;
    const int lane = tid & 31;
    const int warp = tid >> 5;
    const int g4 = lane >> 2, q4 = lane & 3;
    const int pair = blockIdx.x % 9;
    const int bh   = blockIdx.x / 9;
    const int h = bh % HH, b = bh / HH;
    const int q0 = pair * 128;
    const int qrow = warp * 16;
    const int arow = lane & 15;
    const int acol = 4*(lane >> 4);
    const int brow = (lane & 7) + ((lane >> 4) & 1)*8;
    const int bcol = 4*((lane >> 3) & 1);
    // trans-ldmatrix lane address parts for V ([k][d] source)
    const int vtile = lane >> 3;                 // 0..3
    const int vrow  = (lane & 7) + (vtile & 1)*8;   // k row within 16
    const int vcol  = (vtile >> 1)*8;               // d offset (halfs) within 16

    const __half* qp = qkv + (size_t)b*NN*(3*CC) + h*HD;
    const __half* kp = qp + CC;
    const __half* vp = qp + 2*CC;

    const int f  = tid & 7;
    const int rg = tid >> 3;            // 0..31

    // stage Q (128 rows)
    #pragma unroll
    for (int i=0;i<4;i++){
        int row = rg + 32*i;
        int q = q0 + row;
        bool p = (q < NN);
        cp16(smem_u32(Qu + row*36 + 4*f), qp + (size_t)(p ? q : 0)*(3*CC) + 8*f, p);
    }

    auto stage_kv = [&](int kt, int bf){
        uint32_t* Ku = sm + 128*36 + bf*128*36;
        uint32_t* Vs = Ku + 64*36;
        #pragma unroll
        for (int i=0;i<2;i++){
            int row = rg + 32*i;
            int kk = kt*64 + row;
            bool p = (kk < NN);
            size_t off = (size_t)(p ? kk : 0)*(3*CC) + 8*f;
            cp16(smem_u32(Ku + row*36 + 4*f), kp + off, p);
            cp16(smem_u32(Vs + row*36 + 4*f), vp + off, p);
        }
    };

    stage_kv(0, 0);
    cp_commit();

    float oa[8][4];
    #pragma unroll
    for (int j=0;j<8;j++){ oa[j][0]=0.f; oa[j][1]=0.f; oa[j][2]=0.f; oa[j][3]=0.f; }
    float m0r = -1e30f, m1r = -1e30f, l0r = 0.f, l1r = 0.f;

    for (int kt = 0; kt < 17; kt++){
        cp_wait0();
        __syncthreads();
        if (kt + 1 < 17){ stage_kv(kt+1, (kt+1)&1); cp_commit(); }
        const uint32_t* Ku = sm + 128*36 + (kt&1)*128*36;
        const uint32_t* Vs = Ku + 64*36;

        // ---- S = Q K^T ----
        float sc[8][4];
        #pragma unroll
        for (int j=0;j<8;j++){ sc[j][0]=0.f; sc[j][1]=0.f; sc[j][2]=0.f; sc[j][3]=0.f; }
        #pragma unroll
        for (int ks=0; ks<4; ks++){
            uint32_t a[4];
            ldsm4(a, smem_u32(Qu + (qrow + arow)*36 + ks*8 + acol));
            #pragma unroll
            for (int j2=0; j2<4; j2++){
                uint32_t bt[4];
                ldsm4(bt, smem_u32(Ku + (16*j2 + brow)*36 + ks*8 + bcol));
                mma_f16(sc[2*j2],   a, &bt[0]);
                mma_f16(sc[2*j2+1], a, &bt[2]);
            }
        }
        #pragma unroll
        for (int j=0;j<8;j++){
            sc[j][0]*=0.125f; sc[j][1]*=0.125f; sc[j][2]*=0.125f; sc[j][3]*=0.125f;
        }
        if (kt == 16){
            #pragma unroll
            for (int j=0;j<8;j++){
                int c0 = kt*64 + 8*j + 2*q4;
                if (c0   >= NN){ sc[j][0] = -1e30f; sc[j][2] = -1e30f; }
                if (c0+1 >= NN){ sc[j][1] = -1e30f; sc[j][3] = -1e30f; }
            }
        }
        // ---- online softmax ----
        float mx0 = -1e30f, mx1 = -1e30f;
        #pragma unroll
        for (int j=0;j<8;j++){
            mx0 = fmaxf(mx0, fmaxf(sc[j][0], sc[j][1]));
            mx1 = fmaxf(mx1, fmaxf(sc[j][2], sc[j][3]));
        }
        mx0 = fmaxf(mx0, __shfl_xor_sync(0xffffffffu, mx0, 1));
        mx0 = fmaxf(mx0, __shfl_xor_sync(0xffffffffu, mx0, 2));
        mx1 = fmaxf(mx1, __shfl_xor_sync(0xffffffffu, mx1, 1));
        mx1 = fmaxf(mx1, __shfl_xor_sync(0xffffffffu, mx1, 2));
        float mn0 = fmaxf(m0r, mx0), mn1 = fmaxf(m1r, mx1);
        float al0 = __expf(m0r - mn0), al1 = __expf(m1r - mn1);
        float s0 = 0.f, s1 = 0.f;
        #pragma unroll
        for (int j=0;j<8;j++){
            float p00 = __expf(sc[j][0]-mn0), p01 = __expf(sc[j][1]-mn0);
            float p10 = __expf(sc[j][2]-mn1), p11 = __expf(sc[j][3]-mn1);
            sc[j][0]=p00; sc[j][1]=p01; sc[j][2]=p10; sc[j][3]=p11;
            s0 += p00 + p01; s1 += p10 + p11;
        }
        s0 += __shfl_xor_sync(0xffffffffu, s0, 1);
        s0 += __shfl_xor_sync(0xffffffffu, s0, 2);
        s1 += __shfl_xor_sync(0xffffffffu, s1, 1);
        s1 += __shfl_xor_sync(0xffffffffu, s1, 2);
        l0r = l0r*al0 + s0; l1r = l1r*al1 + s1;
        m0r = mn0; m1r = mn1;
        #pragma unroll
        for (int j=0;j<8;j++){
            oa[j][0]*=al0; oa[j][1]*=al0; oa[j][2]*=al1; oa[j][3]*=al1;
        }
        // ---- O += P V : P direct from registers, V via ldmatrix.trans ----
        #pragma unroll
        for (int ks=0; ks<4; ks++){
            uint32_t a[4];
            a[0] = pack_h2(sc[2*ks][0],   sc[2*ks][1]);
            a[1] = pack_h2(sc[2*ks][2],   sc[2*ks][3]);
            a[2] = pack_h2(sc[2*ks+1][0], sc[2*ks+1][1]);
            a[3] = pack_h2(sc[2*ks+1][2], sc[2*ks+1][3]);
            #pragma unroll
            for (int j=0;j<4;j++){
                uint32_t bt[4];
                ldsm4t(bt, smem_u32(Vs + (16*ks + vrow)*36 + (16*j + vcol)/2));
                mma_f16(oa[2*j],   a, &bt[0]);
                mma_f16(oa[2*j+1], a, &bt[2]);
            }
        }
        __syncthreads();           // all warps done with buf kt before it's restaged
    }
    float inv0 = 1.0f / l0r, inv1 = 1.0f / l1r;
    int qg0 = q0 + qrow + g4, qg1 = qg0 + 8;
    #pragma unroll
    for (int j=0;j<8;j++){
        int d = h*HD + 8*j + 2*q4;
        if (qg0 < NN)
            *(uint32_t*)(o + (size_t)(b*NN + qg0)*CC + d) = pack_h2(oa[j][0]*inv0, oa[j][1]*inv0);
        if (qg1 < NN)
            *(uint32_t*)(o + (size_t)(b*NN + qg1)*CC + d) = pack_h2(oa[j][2]*inv1, oa[j][3]*inv1);
    }
}

// ---------------- depthwise 3x3 + BN + residual GELU (fp16 in/out) ----------------
__global__ void dwconv_kernel(const __half2* __restrict__ y, const float* __restrict__ w2,
                              const float* __restrict__ b2, const float* __restrict__ s2,
                              const float* __restrict__ h2b, __half2* __restrict__ out)
{
    int pix = blockIdx.x;                 // 0..16383
    int b = pix >> 10, p = pix & 1023;
    int sy = p >> 5, sx = p & 31;
    const __half2* yb = y + (size_t)(b << 10) * 768;
    for (int c2 = threadIdx.x; c2 < 768; c2 += blockDim.x){
        int c = 2*c2;
        float ax = 0.f, ay = 0.f;
        #pragma unroll
        for (int dy=0; dy<3; dy++){
            int iy = sy + dy - 1;
            if ((unsigned)iy >= 32u) continue;
            #pragma unroll
            for (int dx=0; dx<3; dx++){
                int ix = sx + dx - 1;
                if ((unsigned)ix >= 32u) continue;
                float2 fv = __half22float2(yb[(size_t)((iy<<5)+ix)*768 + c2]);
                ax += fv.x * w2[c*9 + dy*3 + dx];
                ay += fv.y * w2[(c+1)*9 + dy*3 + dx];
            }
        }
        float vx = (ax + b2[c])  *s2[c]   + h2b[c];
        float vy = (ay + b2[c+1])*s2[c+1] + h2b[c+1];
        float2 cf = __half22float2(y[(size_t)pix*768 + c2]);
        out[(size_t)pix*768 + c2] = __floats2half2_rn(cf.x + gelu_f(vx), cf.y + gelu_f(vy));
    }
}

// ---------------- zero the column-sum buffer ----------------
__global__ void zero_part_kernel(float* __restrict__ p){
    int i = blockIdx.x*256 + threadIdx.x;
    if (i < BB*CC) p[i] = 0.f;
}

// ---------------- SE gate ----------------
__global__ void se_kernel(const float* __restrict__ part, const float* __restrict__ cw,
                          const float* __restrict__ cb, const float* __restrict__ ew,
                          const float* __restrict__ eb, float* __restrict__ wout)
{
    __shared__ float m[CC];
    __shared__ float cv[96];
    int b = blockIdx.x, t = threadIdx.x;    // 384 threads
    m[t] = part[b*CC + t] * (1.0f/1024.0f);
    __syncthreads();
    if (t < 96){
        float a = cb[t];
        for (int k=0;k<CC;k++) a += m[k]*cw[t*CC + k];
        cv[t] = gelu_f(a);
    }
    __syncthreads();
    float a = eb[t];
    for (int k=0;k<96;k++) a += cv[k]*ew[t*96 + k];
    wout[b*CC + t] = a;
}

// ---------------- cls rows: out[b,0,:] = x1 + h2*w ----------------
__global__ void final_cls_kernel(const float* __restrict__ x1, const __half* __restrict__ h2,
                                 const float* __restrict__ w, float* __restrict__ out)
{
    int b = blockIdx.x, t = threadIdx.x;    // 384 threads
    size_t i = (size_t)b*NN*CC + t;
    out[i] = x1[i] + __half2float(h2[i]) * w[b*CC + t];
}

// ---------------- launcher ----------------
extern "C" void kernel_launch(void* const* d_in, const int* in_sizes, int n_in,
                              void* d_out, int out_size)
{
    const float* x       = (const float*)d_in[0];
    const float* ln1_g   = (const float*)d_in[1];
    const float* ln1_b   = (const float*)d_in[2];
    const float* qkv_w   = (const float*)d_in[3];
    const float* proj_w  = (const float*)d_in[4];
    const float* proj_b  = (const float*)d_in[5];
    const float* ln2_g   = (const float*)d_in[6];
    const float* ln2_b   = (const float*)d_in[7];
    const float* conv1_w = (const float*)d_in[8];
    const float* conv1_b = (const float*)d_in[9];
    const float* conv2_w = (const float*)d_in[10];
    const float* conv2_b = (const float*)d_in[11];
    const float* conv3_w = (const float*)d_in[12];
    const float* conv3_b = (const float*)d_in[13];
    const float* bn1_s   = (const float*)d_in[14];
    const float* bn1_b   = (const float*)d_in[15];
    const float* bn2_s   = (const float*)d_in[16];
    const float* bn2_b   = (const float*)d_in[17];
    const float* bn3_s   = (const float*)d_in[18];
    const float* bn3_b   = (const float*)d_in[19];
    const float* comp_w  = (const float*)d_in[20];
    const float* comp_b  = (const float*)d_in[21];
    const float* exc_w   = (const float*)d_in[22];
    const float* exc_b   = (const float*)d_in[23];
    float* out = (float*)d_out;

    static bool init = false;
    static __half *p_hh, *p_qkvh, *p_oh, *p_h2h, *p_yh, *p_y2h, *p_wq, *p_wp, *p_w1, *p_w3;
    static float *p_x1, *p_part2, *p_w;
    if (!init){
        cudaGetSymbolAddress((void**)&p_hh,    g_hh);
        cudaGetSymbolAddress((void**)&p_qkvh,  g_qkvh);
        cudaGetSymbolAddress((void**)&p_oh,    g_oh);
        cudaGetSymbolAddress((void**)&p_x1,    g_x1);
        cudaGetSymbolAddress((void**)&p_h2h,   g_h2h);
        cudaGetSymbolAddress((void**)&p_yh,    g_yh);
        cudaGetSymbolAddress((void**)&p_y2h,   g_y2h);
        cudaGetSymbolAddress((void**)&p_part2, g_part2);
        cudaGetSymbolAddress((void**)&p_w,     g_w);
        cudaGetSymbolAddress((void**)&p_wq,    g_wq);
        cudaGetSymbolAddress((void**)&p_wp,    g_wp);
        cudaGetSymbolAddress((void**)&p_w1,    g_w1);
        cudaGetSymbolAddress((void**)&p_w3,    g_w3);
        cudaFuncSetAttribute(gemm_h<0,false>, cudaFuncAttributeMaxDynamicSharedMemorySize, GEMM_SMEM);
        cudaFuncSetAttribute(gemm_h<1,false>, cudaFuncAttributeMaxDynamicSharedMemorySize, GEMM_SMEM);
        cudaFuncSetAttribute(gemm_h<2,true>,  cudaFuncAttributeMaxDynamicSharedMemorySize, GEMM_SMEM);
        cudaFuncSetAttribute(gemm_h<4,false>, cudaFuncAttributeMaxDynamicSharedMemorySize, GEMM_SMEM);
        cudaFuncSetAttribute(attn_h, cudaFuncAttributeMaxDynamicSharedMemorySize, ATTN_SMEM);
        init = true;
    }

    // 0. weight conversions (single launch)
    f2h_all<<<512, 256>>>(qkv_w, p_wq, proj_w, p_wp, conv1_w, p_w1, conv3_w, p_w3);
    // 1. LN1 -> fp16 h
    ln_kernel<<<MTOT, 128>>>(x, ln1_g, ln1_b, p_hh);
    // 2. QKV = h @ qkv_w^T -> fp16
    gemm_h<0,false><<<dim3(9,129), 256, GEMM_SMEM>>>(p_hh, p_wq, p_qkvh, MTOT, 3*CC, CC,
                                                     nullptr, nullptr, nullptr, nullptr, nullptr);
    // 3. attention -> fp16 o
    attn_h<<<BB*HH*9, 256, ATTN_SMEM>>>(p_qkvh, p_oh);
    // 4. x1 = x + o @ proj_w^T + proj_b (fp32)
    gemm_h<1,false><<<dim3(3,129), 256, GEMM_SMEM>>>(p_oh, p_wp, p_x1, MTOT, CC, CC,
                                                     proj_b, nullptr, nullptr, x, nullptr);
    // 5. LN2 -> fp16 h2
    ln_kernel<<<MTOT, 128>>>(p_x1, ln2_g, ln2_b, p_h2h);
    // 6. conv1 + BN1 + GELU -> fp16 y (tokens only)
    gemm_h<2,true><<<dim3(12,128), 256, GEMM_SMEM>>>(p_h2h, p_w1, p_yh, MTOK, HID, CC,
                                                     conv1_b, bn1_s, bn1_b, nullptr, nullptr);
    // 7. depthwise 3x3 + BN2 -> fp16 y2
    dwconv_kernel<<<MTOK, 256>>>((const __half2*)p_yh, conv2_w, conv2_b, bn2_s, bn2_b,
                                 (__half2*)p_y2h);
    // 7.5 zero column sums
    zero_part_kernel<<<(BB*CC + 255)/256, 256>>>(p_part2);
    // 8. conv3 + BN3 fused tail (writes token rows of out + column sums)
    gemm_h<4,false><<<dim3(3,128), 256, GEMM_SMEM>>>(p_y2h, p_w3, out, MTOK, CC, HID,
                                                     conv3_b, bn3_s, bn3_b, p_x1, p_part2);
    // 9. SE gate
    se_kernel<<<BB, CC>>>(p_part2, comp_w, comp_b, exc_w, exc_b, p_w);
    // 10. cls rows
    final_cls_kernel<<<BB, CC>>>(p_x1, p_h2h, p_w, out);
}